// round 1
// baseline (speedup 1.0000x reference)
#include <cuda_runtime.h>
#include <math.h>

#define N_NODES 50000
#define N_EDGES 800000
#define FEAT    128
#define CLS     10
#define NG      64
#define KDIM    1024   // 128 inputs * 8 expanded (silu + 7 spline bases)

// ---------------- scratch (static device globals; no allocation) ----------------
__device__ float g_W[3][FEAT * KDIM];   // combined weights per layer: [o][i*8+j]
__device__ float g_Wr[CLS * KDIM];      // readout combined weights
__device__ float g_deg[N_NODES];
__device__ float g_dinv[N_NODES];
__device__ float g_Y[N_NODES * FEAT];   // KAN linear output
__device__ float g_Z[N_NODES * FEAT];   // aggregation accumulator
__device__ float g_H[N_NODES * FEAT];   // layer output (post-silu)
__device__ float g_pool[NG * FEAT];
__device__ float g_cnt[NG];

// ---------------- helpers ----------------
__device__ __forceinline__ void red_add_v4(float* addr, float4 v) {
    asm volatile("red.global.add.v4.f32 [%0], {%1, %2, %3, %4};"
                 :: "l"(addr), "f"(v.x), "f"(v.y), "f"(v.z), "f"(v.w) : "memory");
}

// expand one scalar into [silu(x), B0..B6] (Cox–de Boor, grid [-2.5..2.5], h=0.5, order 3)
__device__ __forceinline__ void expand8(float x, float* e) {
    e[0] = x / (1.0f + __expf(-x));
    float b[10];
#pragma unroll
    for (int j = 0; j < 10; ++j) {
        float gj = -2.5f + 0.5f * (float)j;
        b[j] = (x >= gj && x < gj + 0.5f) ? 1.0f : 0.0f;
    }
#pragma unroll
    for (int k = 1; k <= 3; ++k) {
        float inv = 1.0f / (0.5f * (float)k);
#pragma unroll
        for (int j = 0; j < 10; ++j) {
            if (j < 10 - k) {
                float gj = -2.5f + 0.5f * (float)j;
                float left  = (x - gj) * inv;
                float right = ((gj + 0.5f * (float)(k + 1)) - x) * inv;
                b[j] = left * b[j] + right * b[j + 1];
            }
        }
    }
#pragma unroll
    for (int j = 0; j < 7; ++j) e[1 + j] = b[j];
}

// ---------------- setup kernels ----------------
__global__ void k_zeros() {
    int t = blockIdx.x * 256 + threadIdx.x;
    if (t < N_NODES)   g_deg[t]  = 0.0f;
    if (t < NG * FEAT) g_pool[t] = 0.0f;
    if (t < NG)        g_cnt[t]  = 0.0f;
}

__global__ void k_deg(const int* __restrict__ dst) {
    int e = blockIdx.x * 256 + threadIdx.x;
    if (e < N_EDGES) atomicAdd(&g_deg[dst[e]], 1.0f);
}

__global__ void k_dinv() {
    int n = blockIdx.x * 256 + threadIdx.x;
    if (n < N_NODES) g_dinv[n] = rsqrtf(g_deg[n] + 1.0f);  // +1 self-loop; always > 0
}

// build combined weights: Wc[o*1024 + i*8 + 0] = bw[o,i]; +1+k = sw[o,i,k]*ss[o,i]
__global__ void k_wc(const float* __restrict__ bw, const float* __restrict__ sw,
                     const float* __restrict__ ss, int which, int total) {
    int t = blockIdx.x * 256 + threadIdx.x;
    if (t >= total) return;
    float* Wc = (which < 3) ? g_W[which] : g_Wr;
    float* dstp = Wc + t * 8;
    dstp[0] = bw[t];
    float s = ss[t];
#pragma unroll
    for (int k = 0; k < 7; ++k) dstp[1 + k] = sw[t * 7 + k] * s;
}

// ---------------- fused KAN-linear GEMM ----------------
// Y[n,o] = sum_{i,j} expand8(H[n,i])[j] * Wc[o, i*8+j]
// Tile: 128 nodes x 128 outputs, K=1024 in steps of 16 (2 input dims/step).
#define GEMM_SMEM_BYTES ((128*129 + 16*128 + 16*128) * 4)

__global__ __launch_bounds__(256, 2) void k_kan_gemm(const float* __restrict__ x, int layer) {
    extern __shared__ float sm[];
    float (*Hs)[129] = (float(*)[129])sm;                       // transposed input tile [i][n]
    float (*As)[128] = (float(*)[128])(sm + 128 * 129);         // expanded A tile [kk][n]
    float (*Bs)[128] = (float(*)[128])(sm + 128 * 129 + 16 * 128); // weight tile [kk][o]

    const float* Hin = (layer == 0) ? x : g_H;
    const float* Wc  = g_W[layer];

    int row0 = blockIdx.x * 128;
    int tid  = threadIdx.x;
    int lane = tid & 31, wid = tid >> 5;

    // load input tile transposed (coalesced global, row-per-warp)
    for (int r = wid; r < 128; r += 8) {
        int n = row0 + r;
        float4 v = make_float4(0.f, 0.f, 0.f, 0.f);
        if (n < N_NODES) v = *(const float4*)&Hin[n * FEAT + lane * 4];
        Hs[lane * 4 + 0][r] = v.x;
        Hs[lane * 4 + 1][r] = v.y;
        Hs[lane * 4 + 2][r] = v.z;
        Hs[lane * 4 + 3][r] = v.w;
    }
    __syncthreads();

    float acc[8][8];
#pragma unroll
    for (int i = 0; i < 8; ++i)
#pragma unroll
        for (int j = 0; j < 8; ++j) acc[i][j] = 0.0f;

    int tx = tid & 15, ty = tid >> 4;
    int n_l = tid & 127, i_l = tid >> 7;

    for (int it = 0; it < 64; ++it) {
        // expansion: 2 input dims -> 16 expanded rows of As
        {
            float xv = Hs[it * 2 + i_l][n_l];
            float e[8];
            expand8(xv, e);
#pragma unroll
            for (int j = 0; j < 8; ++j) As[i_l * 8 + j][n_l] = e[j];
        }
        // weight tile: 128 outputs x 16 k
#pragma unroll
        for (int q = 0; q < 2; ++q) {
            int idx = q * 256 + tid;       // float4 index 0..511
            int o = idx >> 2, kq = idx & 3;
            float4 w = *(const float4*)&Wc[o * KDIM + it * 16 + kq * 4];
            Bs[kq * 4 + 0][o] = w.x;
            Bs[kq * 4 + 1][o] = w.y;
            Bs[kq * 4 + 2][o] = w.z;
            Bs[kq * 4 + 3][o] = w.w;
        }
        __syncthreads();

#pragma unroll
        for (int kk = 0; kk < 16; ++kk) {
            float a[8], b[8];
            *(float4*)&a[0] = *(const float4*)&As[kk][ty * 8];
            *(float4*)&a[4] = *(const float4*)&As[kk][ty * 8 + 4];
            *(float4*)&b[0] = *(const float4*)&Bs[kk][tx * 8];
            *(float4*)&b[4] = *(const float4*)&Bs[kk][tx * 8 + 4];
#pragma unroll
            for (int i = 0; i < 8; ++i)
#pragma unroll
                for (int j = 0; j < 8; ++j)
                    acc[i][j] = fmaf(a[i], b[j], acc[i][j]);
        }
        __syncthreads();
    }

#pragma unroll
    for (int i = 0; i < 8; ++i) {
        int n = row0 + ty * 8 + i;
        if (n < N_NODES) {
            *(float4*)&g_Y[n * FEAT + tx * 8]     = *(float4*)&acc[i][0];
            *(float4*)&g_Y[n * FEAT + tx * 8 + 4] = *(float4*)&acc[i][4];
        }
    }
}

// ---------------- aggregation ----------------
__global__ void k_zinit() {
    int t = blockIdx.x * 256 + threadIdx.x;
    if (t >= N_NODES * FEAT) return;
    int n = t >> 7;
    float di = g_dinv[n];
    g_Z[t] = g_Y[t] * di * di;   // self-loop contribution
}

__global__ void k_scatter(const int* __restrict__ ei) {
    int w = (blockIdx.x * 256 + threadIdx.x) >> 5;
    int lane = threadIdx.x & 31;
    if (w >= N_EDGES) return;
    int s = ei[w], d = ei[N_EDGES + w];
    float nm = g_dinv[s] * g_dinv[d];
    float4 v = *(const float4*)&g_Y[s * FEAT + lane * 4];
    v.x *= nm; v.y *= nm; v.z *= nm; v.w *= nm;
    red_add_v4(&g_Z[d * FEAT + lane * 4], v);
}

__global__ void k_post(const float* __restrict__ bias) {
    int t = blockIdx.x * 256 + threadIdx.x;
    if (t >= N_NODES * FEAT) return;
    float z = g_Z[t] + bias[t & 127];
    g_H[t] = z / (1.0f + __expf(-z));
}

// ---------------- pooling + readout ----------------
__global__ void k_pool(const int* __restrict__ batch) {
    int w = (blockIdx.x * 256 + threadIdx.x) >> 5;
    int lane = threadIdx.x & 31;
    if (w >= N_NODES) return;
    int g = batch[w];
    float4 v = *(const float4*)&g_H[w * FEAT + lane * 4];
    red_add_v4(&g_pool[g * FEAT + lane * 4], v);
    if (lane == 0) atomicAdd(&g_cnt[g], 1.0f);
}

__global__ void k_readout(float* __restrict__ out) {
    int g = blockIdx.x;
    int t = threadIdx.x;   // 128 threads
    __shared__ float red[CLS][4];
    __shared__ float logits[CLS];

    float inv = 1.0f / fmaxf(g_cnt[g], 1.0f);
    float p = g_pool[g * FEAT + t] * inv;
    float e[8];
    expand8(p, e);

    float part[CLS];
#pragma unroll
    for (int c = 0; c < CLS; ++c) {
        const float* w = &g_Wr[c * KDIM + t * 8];
        float s = 0.0f;
#pragma unroll
        for (int j = 0; j < 8; ++j) s = fmaf(e[j], w[j], s);
        part[c] = s;
    }
    int lane = t & 31, wid = t >> 5;
#pragma unroll
    for (int c = 0; c < CLS; ++c) {
        float v = part[c];
#pragma unroll
        for (int o = 16; o > 0; o >>= 1) v += __shfl_down_sync(0xffffffffu, v, o);
        if (lane == 0) red[c][wid] = v;
    }
    __syncthreads();
    if (t < CLS) logits[t] = red[t][0] + red[t][1] + red[t][2] + red[t][3];
    __syncthreads();
    if (t == 0) {
        float m = -1e30f;
        for (int c = 0; c < CLS; ++c) m = fmaxf(m, logits[c]);
        float s = 0.0f;
        for (int c = 0; c < CLS; ++c) s += expf(logits[c] - m);
        float lse = m + logf(s);
        for (int c = 0; c < CLS; ++c) out[g * CLS + c] = logits[c] - lse;
    }
}

// ---------------- launch ----------------
extern "C" void kernel_launch(void* const* d_in, const int* in_sizes, int n_in,
                              void* d_out, int out_size) {
    const float* x     = (const float*)d_in[0];
    const int*   ei    = (const int*)d_in[1];
    const int*   batch = (const int*)d_in[2];
    const float* bw[3] = {(const float*)d_in[3], (const float*)d_in[7],  (const float*)d_in[11]};
    const float* sw[3] = {(const float*)d_in[4], (const float*)d_in[8],  (const float*)d_in[12]};
    const float* ss[3] = {(const float*)d_in[5], (const float*)d_in[9],  (const float*)d_in[13]};
    const float* bb[3] = {(const float*)d_in[6], (const float*)d_in[10], (const float*)d_in[14]};
    const float* bwr = (const float*)d_in[15];
    const float* swr = (const float*)d_in[16];
    const float* ssr = (const float*)d_in[17];
    float* out = (float*)d_out;

    cudaFuncSetAttribute(k_kan_gemm, cudaFuncAttributeMaxDynamicSharedMemorySize, GEMM_SMEM_BYTES);

    k_zeros<<<(N_NODES + 255) / 256, 256>>>();
    k_deg<<<(N_EDGES + 255) / 256, 256>>>(ei + N_EDGES);
    k_dinv<<<(N_NODES + 255) / 256, 256>>>();

    k_wc<<<(FEAT * FEAT + 255) / 256, 256>>>(bw[0], sw[0], ss[0], 0, FEAT * FEAT);
    k_wc<<<(FEAT * FEAT + 255) / 256, 256>>>(bw[1], sw[1], ss[1], 1, FEAT * FEAT);
    k_wc<<<(FEAT * FEAT + 255) / 256, 256>>>(bw[2], sw[2], ss[2], 2, FEAT * FEAT);
    k_wc<<<(CLS * FEAT + 255) / 256, 256>>>(bwr, swr, ssr, 3, CLS * FEAT);

    int gemm_blocks = (N_NODES + 127) / 128;  // 391
    int nf_blocks   = (N_NODES * FEAT + 255) / 256;
    for (int l = 0; l < 3; ++l) {
        k_kan_gemm<<<gemm_blocks, 256, GEMM_SMEM_BYTES>>>(x, l);
        k_zinit<<<nf_blocks, 256>>>();
        k_scatter<<<(N_EDGES * 32 + 255) / 256, 256>>>(ei);
        k_post<<<nf_blocks, 256>>>(bb[l]);
    }

    k_pool<<<(N_NODES * 32 + 255) / 256, 256>>>(batch);
    k_readout<<<NG, 128>>>(out);
}

// round 3
// speedup vs baseline: 1.4761x; 1.4761x over previous
#include <cuda_runtime.h>
#include <cuda_bf16.h>
#include <math.h>
#include <stdint.h>

#define N_NODES 50000
#define N_EDGES 800000
#define FEAT    128
#define CLS     10
#define NG      64
#define KDIM    1024   // 128 inputs * 8 expanded (silu + 7 spline bases)

// ---------------- scratch (static device globals; no allocation) ----------------
__device__ __align__(16) __nv_bfloat16 g_Wh[3][FEAT * KDIM];  // combined weights, bf16 hi
__device__ __align__(16) __nv_bfloat16 g_Wl[3][FEAT * KDIM];  // combined weights, bf16 lo
__device__ __align__(16) float g_Wr[CLS * KDIM];              // readout combined weights
__device__ float g_deg[N_NODES];
__device__ float g_dinv[N_NODES];
__device__ __align__(16) float g_Y[N_NODES * FEAT];   // KAN linear output
__device__ __align__(16) float g_Z[N_NODES * FEAT];   // aggregation accumulator
__device__ __align__(16) float g_H[N_NODES * FEAT];   // layer output (post-silu)
__device__ float g_pool[NG * FEAT];
__device__ float g_cnt[NG];

// ---------------- helpers ----------------
__device__ __forceinline__ uint32_t smem_u32(const void* p) {
    uint32_t a;
    asm("{ .reg .u64 t; cvta.to.shared.u64 t, %1; cvt.u32.u64 %0, t; }" : "=r"(a) : "l"(p));
    return a;
}
__device__ __forceinline__ void red_add_v4(float* addr, float4 v) {
    asm volatile("red.global.add.v4.f32 [%0], {%1, %2, %3, %4};"
                 :: "l"(addr), "f"(v.x), "f"(v.y), "f"(v.z), "f"(v.w) : "memory");
}
__device__ __forceinline__ void ldm_x4(uint32_t* r, uint32_t addr) {
    asm volatile("ldmatrix.sync.aligned.m8n8.x4.shared.b16 {%0,%1,%2,%3}, [%4];"
                 : "=r"(r[0]), "=r"(r[1]), "=r"(r[2]), "=r"(r[3]) : "r"(addr));
}
__device__ __forceinline__ void mma16816(float* c, const uint32_t* a, uint32_t b0, uint32_t b1) {
    asm volatile("mma.sync.aligned.m16n8k16.row.col.f32.bf16.bf16.f32 "
                 "{%0,%1,%2,%3}, {%4,%5,%6,%7}, {%8,%9}, {%0,%1,%2,%3};"
                 : "+f"(c[0]), "+f"(c[1]), "+f"(c[2]), "+f"(c[3])
                 : "r"(a[0]), "r"(a[1]), "r"(a[2]), "r"(a[3]), "r"(b0), "r"(b1));
}

// expand one scalar into [silu(x), B0..B6] (Cox–de Boor, grid [-2.5..2.5], h=0.5, order 3)
__device__ __forceinline__ void expand8(float x, float* e) {
    e[0] = x / (1.0f + __expf(-x));
    float b[10];
#pragma unroll
    for (int j = 0; j < 10; ++j) {
        float gj = -2.5f + 0.5f * (float)j;
        b[j] = (x >= gj && x < gj + 0.5f) ? 1.0f : 0.0f;
    }
#pragma unroll
    for (int k = 1; k <= 3; ++k) {
        float inv = 1.0f / (0.5f * (float)k);
#pragma unroll
        for (int j = 0; j < 10; ++j) {
            if (j < 10 - k) {
                float gj = -2.5f + 0.5f * (float)j;
                float left  = (x - gj) * inv;
                float right = ((gj + 0.5f * (float)(k + 1)) - x) * inv;
                b[j] = left * b[j] + right * b[j + 1];
            }
        }
    }
#pragma unroll
    for (int j = 0; j < 7; ++j) e[1 + j] = b[j];
}

__device__ __forceinline__ uint32_t pack_bf16x2(float a, float b) {
    __nv_bfloat162 t = __floats2bfloat162_rn(a, b);
    return *(uint32_t*)&t;
}

// ---------------- setup kernels ----------------
__global__ void k_zeros() {
    int t = blockIdx.x * 256 + threadIdx.x;
    if (t < N_NODES)   g_deg[t]  = 0.0f;
    if (t < NG * FEAT) g_pool[t] = 0.0f;
    if (t < NG)        g_cnt[t]  = 0.0f;
}
__global__ void k_deg(const int* __restrict__ dst) {
    int e = blockIdx.x * 256 + threadIdx.x;
    if (e < N_EDGES) atomicAdd(&g_deg[dst[e]], 1.0f);
}
__global__ void k_dinv() {
    int n = blockIdx.x * 256 + threadIdx.x;
    if (n < N_NODES) g_dinv[n] = rsqrtf(g_deg[n] + 1.0f);  // +1 self-loop
}
// combined weights: Wc[o*1024 + i*8 + 0] = bw[o,i]; +1+k = sw[o,i,k]*ss[o,i]
__global__ void k_wc(const float* __restrict__ bw, const float* __restrict__ sw,
                     const float* __restrict__ ss, int which, int total) {
    int t = blockIdx.x * 256 + threadIdx.x;
    if (t >= total) return;
    float v[8];
    v[0] = bw[t];
    float s = ss[t];
#pragma unroll
    for (int k = 0; k < 7; ++k) v[1 + k] = sw[t * 7 + k] * s;
    if (which < 3) {
        __nv_bfloat16* wh = &g_Wh[which][t * 8];
        __nv_bfloat16* wl = &g_Wl[which][t * 8];
#pragma unroll
        for (int j = 0; j < 8; ++j) {
            __nv_bfloat16 hi = __float2bfloat16(v[j]);
            wh[j] = hi;
            wl[j] = __float2bfloat16(v[j] - __bfloat162float(hi));
        }
    } else {
        float* d = g_Wr + t * 8;
#pragma unroll
        for (int j = 0; j < 8; ++j) d[j] = v[j];
    }
}

// ---------------- HMMA fused KAN-linear GEMM ----------------
// D[n,o] = sum_k expand(H)[n,k]*W[o,k]; fp32 via bf16 3-term split (AhBh+AhBl+AlBh).
// CTA: 128x128 tile, 8 warps of M32xN64. K=1024 in 16 chunks of 64.
// smem offsets (bytes):
#define OFF_AH 0
#define OFF_AL 16384
#define OFF_BH 32768
#define OFF_BL 49152
#define OFF_HS 65536
#define SMEM_NEED (OFF_HS + 128 * 129 * 4)

__global__ __launch_bounds__(256) void k_gemm_mma(const float* __restrict__ x, int layer) {
    extern __shared__ __align__(16) char sm[];
    uint32_t sb = smem_u32(sm);
    float (*Hs)[129] = (float(*)[129])(sm + OFF_HS);

    const float* Hin = (layer == 0) ? x : g_H;
    const __nv_bfloat16* Wh = g_Wh[layer];
    const __nv_bfloat16* Wl = g_Wl[layer];

    const int tid = threadIdx.x, lane = tid & 31, wid = tid >> 5;
    const int row0 = blockIdx.x * 128;
    const int m0w = (wid >> 1) * 32;     // warp M offset
    const int n0w = (wid & 1) * 64;      // warp N offset

    // stage input tile transposed: Hs[i][n]  (coalesced global read)
    for (int r = wid; r < 128; r += 8) {
        int n = row0 + r;
        float4 v = make_float4(0.f, 0.f, 0.f, 0.f);
        if (n < N_NODES) v = *(const float4*)&Hin[n * FEAT + lane * 4];
        Hs[lane * 4 + 0][r] = v.x;
        Hs[lane * 4 + 1][r] = v.y;
        Hs[lane * 4 + 2][r] = v.z;
        Hs[lane * 4 + 3][r] = v.w;
    }
    __syncthreads();

    float acc[2][8][4];
#pragma unroll
    for (int i = 0; i < 2; ++i)
#pragma unroll
        for (int j = 0; j < 8; ++j)
#pragma unroll
            for (int k = 0; k < 4; ++k) acc[i][j][k] = 0.0f;

    for (int c = 0; c < 16; ++c) {
        // ---- produce A tiles: expand 8 input dims -> 64 k cols, bf16 hi/lo ----
#pragma unroll
        for (int q = 0; q < 4; ++q) {
            int id = q * 256 + tid;
            int n = id & 127, ii = id >> 7;          // ii in 0..7
            float xv = Hs[c * 8 + ii][n];
            float e[8];
            expand8(xv, e);
            uint32_t h[4], l[4];
#pragma unroll
            for (int j = 0; j < 4; ++j) {
                float a = e[2 * j], b = e[2 * j + 1];
                __nv_bfloat16 ah = __float2bfloat16(a), bh = __float2bfloat16(b);
                h[j] = pack_bf16x2(a, b);
                l[j] = pack_bf16x2(a - __bfloat162float(ah), b - __bfloat162float(bh));
            }
            uint32_t off = (uint32_t)n * 128 + (uint32_t)((ii ^ (n & 7)) * 16);
            *(uint4*)(sm + OFF_AH + off) = make_uint4(h[0], h[1], h[2], h[3]);
            *(uint4*)(sm + OFF_AL + off) = make_uint4(l[0], l[1], l[2], l[3]);
        }
        // ---- load B tiles (bf16 hi/lo) ----
#pragma unroll
        for (int q = 0; q < 4; ++q) {
            int idx = q * 256 + tid;                 // 0..1023
            int o = idx >> 3, s = idx & 7;
            uint32_t off = (uint32_t)o * 128 + (uint32_t)(((s ^ (o & 7))) * 16);
            *(uint4*)(sm + OFF_BH + off) = *(const uint4*)(Wh + o * KDIM + c * 64 + s * 8);
            *(uint4*)(sm + OFF_BL + off) = *(const uint4*)(Wl + o * KDIM + c * 64 + s * 8);
        }
        __syncthreads();

        // ---- consume: 4 k16 steps ----
#pragma unroll
        for (int kk = 0; kk < 4; ++kk) {
            uint32_t ah[2][4], al[2][4];
#pragma unroll
            for (int mt = 0; mt < 2; ++mt) {
                int m = m0w + mt * 16 + (lane & 15);
                uint32_t chunk = (uint32_t)((kk * 2 + (lane >> 4)) ^ (m & 7));
                uint32_t off = (uint32_t)m * 128 + chunk * 16;
                ldm_x4(ah[mt], sb + OFF_AH + off);
                ldm_x4(al[mt], sb + OFF_AL + off);
            }
            uint32_t bh[4][4], bl[4][4];
#pragma unroll
            for (int ng = 0; ng < 4; ++ng) {
                int n = n0w + ng * 16 + ((lane >> 4) << 3) + (lane & 7);
                uint32_t chunk = (uint32_t)((kk * 2 + ((lane >> 3) & 1)) ^ (n & 7));
                uint32_t off = (uint32_t)n * 128 + chunk * 16;
                ldm_x4(bh[ng], sb + OFF_BH + off);
                ldm_x4(bl[ng], sb + OFF_BL + off);
            }
#pragma unroll
            for (int mt = 0; mt < 2; ++mt)
#pragma unroll
                for (int ng = 0; ng < 4; ++ng)
#pragma unroll
                    for (int hf = 0; hf < 2; ++hf) {
                        float* cc = acc[mt][ng * 2 + hf];
                        mma16816(cc, ah[mt], bh[ng][hf * 2], bh[ng][hf * 2 + 1]);
                        mma16816(cc, ah[mt], bl[ng][hf * 2], bl[ng][hf * 2 + 1]);
                        mma16816(cc, al[mt], bh[ng][hf * 2], bh[ng][hf * 2 + 1]);
                    }
        }
        __syncthreads();
    }

    // ---- epilogue: write Y and self-loop Z = Y*dinv^2 ----
#pragma unroll
    for (int mt = 0; mt < 2; ++mt) {
        int r1 = row0 + m0w + mt * 16 + (lane >> 2);
        int r2 = r1 + 8;
        bool ok1 = r1 < N_NODES, ok2 = r2 < N_NODES;
        float d1 = ok1 ? g_dinv[r1] : 0.0f; d1 *= d1;
        float d2 = ok2 ? g_dinv[r2] : 0.0f; d2 *= d2;
        int cb = n0w + (lane & 3) * 2;
#pragma unroll
        for (int nt = 0; nt < 8; ++nt) {
            int col = cb + nt * 8;
            float* a = acc[mt][nt];
            if (ok1) {
                *(float2*)&g_Y[r1 * FEAT + col] = make_float2(a[0], a[1]);
                *(float2*)&g_Z[r1 * FEAT + col] = make_float2(a[0] * d1, a[1] * d1);
            }
            if (ok2) {
                *(float2*)&g_Y[r2 * FEAT + col] = make_float2(a[2], a[3]);
                *(float2*)&g_Z[r2 * FEAT + col] = make_float2(a[2] * d2, a[3] * d2);
            }
        }
    }
}

// ---------------- aggregation ----------------
__global__ void k_scatter(const int* __restrict__ ei) {
    int w = (blockIdx.x * 256 + threadIdx.x) >> 5;
    int lane = threadIdx.x & 31;
    if (w >= N_EDGES) return;
    int s = ei[w], d = ei[N_EDGES + w];
    float nm = g_dinv[s] * g_dinv[d];
    float4 v = *(const float4*)&g_Y[s * FEAT + lane * 4];
    v.x *= nm; v.y *= nm; v.z *= nm; v.w *= nm;
    red_add_v4(&g_Z[d * FEAT + lane * 4], v);
}

__global__ void k_post(const float* __restrict__ bias) {
    int t = blockIdx.x * 256 + threadIdx.x;
    if (t >= N_NODES * FEAT) return;
    float z = g_Z[t] + bias[t & 127];
    g_H[t] = z / (1.0f + __expf(-z));
}

// ---------------- pooling + readout ----------------
__global__ void k_pool(const int* __restrict__ batch) {
    int w = (blockIdx.x * 256 + threadIdx.x) >> 5;
    int lane = threadIdx.x & 31;
    if (w >= N_NODES) return;
    int g = batch[w];
    float4 v = *(const float4*)&g_H[w * FEAT + lane * 4];
    red_add_v4(&g_pool[g * FEAT + lane * 4], v);
    if (lane == 0) atomicAdd(&g_cnt[g], 1.0f);
}

__global__ void k_readout(float* __restrict__ out) {
    int g = blockIdx.x;
    int t = threadIdx.x;   // 128 threads
    __shared__ float red[CLS][4];
    __shared__ float logits[CLS];

    float inv = 1.0f / fmaxf(g_cnt[g], 1.0f);
    float p = g_pool[g * FEAT + t] * inv;
    float e[8];
    expand8(p, e);

    float part[CLS];
#pragma unroll
    for (int c = 0; c < CLS; ++c) {
        const float* w = &g_Wr[c * KDIM + t * 8];
        float s = 0.0f;
#pragma unroll
        for (int j = 0; j < 8; ++j) s = fmaf(e[j], w[j], s);
        part[c] = s;
    }
    int lane = t & 31, wid = t >> 5;
#pragma unroll
    for (int c = 0; c < CLS; ++c) {
        float v = part[c];
#pragma unroll
        for (int o = 16; o > 0; o >>= 1) v += __shfl_down_sync(0xffffffffu, v, o);
        if (lane == 0) red[c][wid] = v;
    }
    __syncthreads();
    if (t < CLS) logits[t] = red[t][0] + red[t][1] + red[t][2] + red[t][3];
    __syncthreads();
    if (t == 0) {
        float m = -1e30f;
        for (int c = 0; c < CLS; ++c) m = fmaxf(m, logits[c]);
        float s = 0.0f;
        for (int c = 0; c < CLS; ++c) s += expf(logits[c] - m);
        float lse = m + logf(s);
        for (int c = 0; c < CLS; ++c) out[g * CLS + c] = logits[c] - lse;
    }
}

// ---------------- launch ----------------
extern "C" void kernel_launch(void* const* d_in, const int* in_sizes, int n_in,
                              void* d_out, int out_size) {
    const float* x     = (const float*)d_in[0];
    const int*   ei    = (const int*)d_in[1];
    const int*   batch = (const int*)d_in[2];
    const float* bw[3] = {(const float*)d_in[3], (const float*)d_in[7],  (const float*)d_in[11]};
    const float* sw[3] = {(const float*)d_in[4], (const float*)d_in[8],  (const float*)d_in[12]};
    const float* ss[3] = {(const float*)d_in[5], (const float*)d_in[9],  (const float*)d_in[13]};
    const float* bb[3] = {(const float*)d_in[6], (const float*)d_in[10], (const float*)d_in[14]};
    const float* bwr = (const float*)d_in[15];
    const float* swr = (const float*)d_in[16];
    const float* ssr = (const float*)d_in[17];
    float* out = (float*)d_out;

    cudaFuncSetAttribute(k_gemm_mma, cudaFuncAttributeMaxDynamicSharedMemorySize, SMEM_NEED);

    k_zeros<<<(N_NODES + 255) / 256, 256>>>();
    k_deg<<<(N_EDGES + 255) / 256, 256>>>(ei + N_EDGES);
    k_dinv<<<(N_NODES + 255) / 256, 256>>>();

    k_wc<<<(FEAT * FEAT + 255) / 256, 256>>>(bw[0], sw[0], ss[0], 0, FEAT * FEAT);
    k_wc<<<(FEAT * FEAT + 255) / 256, 256>>>(bw[1], sw[1], ss[1], 1, FEAT * FEAT);
    k_wc<<<(FEAT * FEAT + 255) / 256, 256>>>(bw[2], sw[2], ss[2], 2, FEAT * FEAT);
    k_wc<<<(CLS * FEAT + 255) / 256, 256>>>(bwr, swr, ssr, 3, CLS * FEAT);

    int gemm_blocks = (N_NODES + 127) / 128;  // 391
    int nf_blocks   = (N_NODES * FEAT + 255) / 256;
    for (int l = 0; l < 3; ++l) {
        k_gemm_mma<<<gemm_blocks, 256, SMEM_NEED>>>(x, l);  // writes g_Y and g_Z(self-loop)
        k_scatter<<<(N_EDGES * 32 + 255) / 256, 256>>>(ei);
        k_post<<<nf_blocks, 256>>>(bb[l]);
    }

    k_pool<<<(N_NODES * 32 + 255) / 256, 256>>>(batch);
    k_readout<<<NG, 128>>>(out);
}

// round 4
// speedup vs baseline: 2.0702x; 1.4024x over previous
#include <cuda_runtime.h>
#include <cuda_bf16.h>
#include <math.h>
#include <stdint.h>

#define N_NODES 50000
#define N_EDGES 800000
#define FEAT    128
#define CLS     10
#define NG      64
#define KDIM    1024

// ---------------- scratch ----------------
__device__ __align__(16) __nv_bfloat16 g_Wh[3][FEAT * KDIM];
__device__ __align__(16) __nv_bfloat16 g_Wl[3][FEAT * KDIM];
__device__ __align__(16) float g_Wr[CLS * KDIM];
__device__ int   g_degi[N_NODES];
__device__ float g_dinv[N_NODES];
__device__ int   g_rowptr[N_NODES + 1];
__device__ int   g_wofs[N_NODES];
__device__ int   g_srcs[N_EDGES];
__device__ int   g_blocksum[256];
__device__ __align__(16) float g_Y[N_NODES * FEAT];
__device__ __align__(16) float g_H[N_NODES * FEAT];
__device__ float g_pool[NG * FEAT];
__device__ float g_cnt[NG];

// ---------------- helpers ----------------
__device__ __forceinline__ uint32_t smem_u32(const void* p) {
    uint32_t a;
    asm("{ .reg .u64 t; cvta.to.shared.u64 t, %1; cvt.u32.u64 %0, t; }" : "=r"(a) : "l"(p));
    return a;
}
__device__ __forceinline__ void red_add_v4(float* addr, float4 v) {
    asm volatile("red.global.add.v4.f32 [%0], {%1, %2, %3, %4};"
                 :: "l"(addr), "f"(v.x), "f"(v.y), "f"(v.z), "f"(v.w) : "memory");
}
__device__ __forceinline__ void ldm_x4(uint32_t* r, uint32_t addr) {
    asm volatile("ldmatrix.sync.aligned.m8n8.x4.shared.b16 {%0,%1,%2,%3}, [%4];"
                 : "=r"(r[0]), "=r"(r[1]), "=r"(r[2]), "=r"(r[3]) : "r"(addr));
}
__device__ __forceinline__ void mma16816(float* c, const uint32_t* a, uint32_t b0, uint32_t b1) {
    asm volatile("mma.sync.aligned.m16n8k16.row.col.f32.bf16.bf16.f32 "
                 "{%0,%1,%2,%3}, {%4,%5,%6,%7}, {%8,%9}, {%0,%1,%2,%3};"
                 : "+f"(c[0]), "+f"(c[1]), "+f"(c[2]), "+f"(c[3])
                 : "r"(a[0]), "r"(a[1]), "r"(a[2]), "r"(a[3]), "r"(b0), "r"(b1));
}
__device__ __forceinline__ void cp_async16(uint32_t smem_dst, const void* gsrc) {
    asm volatile("cp.async.cg.shared.global [%0], [%1], 16;" :: "r"(smem_dst), "l"(gsrc) : "memory");
}
#define CP_COMMIT() asm volatile("cp.async.commit_group;" ::: "memory")
#define CP_WAIT1()  asm volatile("cp.async.wait_group 1;" ::: "memory")

// closed-form expansion: [silu(x), B0..B6], uniform cubic B-spline, knots -2.5..2.5 step 0.5
__device__ __forceinline__ void expand8(float x, float* e) {
    e[0] = x / (1.0f + __expf(-x));
    float u  = (x + 2.5f) * 2.0f;
    float fj = floorf(u);
    int   ji = (int)fj;
    float t  = u - fj;
    float t2 = t * t, t3 = t2 * t;
    float v3 = t3 * (1.0f / 6.0f);
    float v2 = (1.0f / 6.0f) * (-3.0f * t3 + 3.0f * t2 + 3.0f * t + 1.0f);
    float v1 = (1.0f / 6.0f) * (3.0f * t3 - 6.0f * t2 + 4.0f);
    float omt = 1.0f - t;
    float v0 = (1.0f / 6.0f) * omt * omt * omt;
    if (!(u >= 0.0f && u < 10.0f)) { v0 = v1 = v2 = v3 = 0.0f; }
#pragma unroll
    for (int m = 0; m < 7; ++m) {
        int d = ji - m;
        float r = 0.0f;
        r = (d == 3) ? v0 : r;
        r = (d == 2) ? v1 : r;
        r = (d == 1) ? v2 : r;
        r = (d == 0) ? v3 : r;
        e[1 + m] = r;
    }
}
__device__ __forceinline__ uint32_t pack_bf16x2(float a, float b) {
    __nv_bfloat162 t = __floats2bfloat162_rn(a, b);
    return *(uint32_t*)&t;
}

// ---------------- setup ----------------
__global__ void k_zeros() {
    int t = blockIdx.x * 256 + threadIdx.x;
    if (t < N_NODES)   g_degi[t] = 0;
    if (t < NG * FEAT) g_pool[t] = 0.0f;
    if (t < NG)        g_cnt[t]  = 0.0f;
}
__global__ void k_hist(const int* __restrict__ dst) {
    int e = blockIdx.x * 256 + threadIdx.x;
    if (e < N_EDGES) atomicAdd(&g_degi[dst[e]], 1);
}
__global__ void k_dinv() {
    int n = blockIdx.x * 256 + threadIdx.x;
    if (n < N_NODES) g_dinv[n] = rsqrtf((float)g_degi[n] + 1.0f);
}
__global__ void k_scan1() {
    __shared__ int s[256];
    int i = blockIdx.x * 256 + threadIdx.x;
    int v = (i < N_NODES) ? g_degi[i] : 0;
    s[threadIdx.x] = v;
    __syncthreads();
    for (int o = 1; o < 256; o <<= 1) {
        int t = (threadIdx.x >= o) ? s[threadIdx.x - o] : 0;
        __syncthreads();
        s[threadIdx.x] += t;
        __syncthreads();
    }
    if (i < N_NODES) g_rowptr[i] = s[threadIdx.x] - v;   // exclusive within block
    if (threadIdx.x == 255) g_blocksum[blockIdx.x] = s[255];
}
__global__ void k_scan2(int nblocks) {
    __shared__ int s[256];
    int i = threadIdx.x;
    int v = (i < nblocks) ? g_blocksum[i] : 0;
    s[i] = v;
    __syncthreads();
    for (int o = 1; o < 256; o <<= 1) {
        int t = (i >= o) ? s[i - o] : 0;
        __syncthreads();
        s[i] += t;
        __syncthreads();
    }
    if (i < nblocks) g_blocksum[i] = s[i] - v;  // exclusive
}
__global__ void k_scan3() {
    int i = blockIdx.x * 256 + threadIdx.x;
    if (i < N_NODES) {
        int r = g_rowptr[i] + g_blocksum[blockIdx.x];
        g_rowptr[i] = r;
        g_wofs[i]   = r;
    }
    if (i == 0) g_rowptr[N_NODES] = N_EDGES;
}
__global__ void k_fill(const int* __restrict__ ei) {
    int e = blockIdx.x * 256 + threadIdx.x;
    if (e >= N_EDGES) return;
    int d = ei[N_EDGES + e];
    int pos = atomicAdd(&g_wofs[d], 1);
    g_srcs[pos] = ei[e];
}
__global__ void k_wc(const float* __restrict__ bw, const float* __restrict__ sw,
                     const float* __restrict__ ss, int which, int total) {
    int t = blockIdx.x * 256 + threadIdx.x;
    if (t >= total) return;
    float v[8];
    v[0] = bw[t];
    float s = ss[t];
#pragma unroll
    for (int k = 0; k < 7; ++k) v[1 + k] = sw[t * 7 + k] * s;
    if (which < 3) {
        __nv_bfloat16* wh = &g_Wh[which][t * 8];
        __nv_bfloat16* wl = &g_Wl[which][t * 8];
#pragma unroll
        for (int j = 0; j < 8; ++j) {
            __nv_bfloat16 hi = __float2bfloat16(v[j]);
            wh[j] = hi;
            wl[j] = __float2bfloat16(v[j] - __bfloat162float(hi));
        }
    } else {
        float* d = g_Wr + t * 8;
#pragma unroll
        for (int j = 0; j < 8; ++j) d[j] = v[j];
    }
}

// ---------------- HMMA fused KAN-linear GEMM (3-term bf16 split) ----------------
// smem: AH 0..16K, AL 16K..32K, B stage0 32K..64K (BH/BL), B stage1 64K..96K, Hs 96K..
#define OFF_AH 0
#define OFF_AL 16384
#define OFF_B0 32768
#define OFF_HS 98304
#define SMEM_NEED (OFF_HS + 128 * 129 * 4)

__global__ __launch_bounds__(256) void k_gemm_mma(const float* __restrict__ x, int layer) {
    extern __shared__ __align__(16) char sm[];
    uint32_t sb = smem_u32(sm);
    float (*Hs)[129] = (float(*)[129])(sm + OFF_HS);

    const float* Hin = (layer == 0) ? x : g_H;
    const __nv_bfloat16* Wh = g_Wh[layer];
    const __nv_bfloat16* Wl = g_Wl[layer];

    const int tid = threadIdx.x, lane = tid & 31, wid = tid >> 5;
    const int row0 = blockIdx.x * 128;
    const int m0w = (wid >> 1) * 32;
    const int n0w = (wid & 1) * 64;

    // stage input tile transposed
    for (int r = wid; r < 128; r += 8) {
        int n = row0 + r;
        float4 v = make_float4(0.f, 0.f, 0.f, 0.f);
        if (n < N_NODES) v = *(const float4*)&Hin[n * FEAT + lane * 4];
        Hs[lane * 4 + 0][r] = v.x;
        Hs[lane * 4 + 1][r] = v.y;
        Hs[lane * 4 + 2][r] = v.z;
        Hs[lane * 4 + 3][r] = v.w;
    }

    // prefetch B(0) into stage 0
    {
#pragma unroll
        for (int q = 0; q < 4; ++q) {
            int idx = q * 256 + tid;
            int o = idx >> 3, s = idx & 7;
            uint32_t off = (uint32_t)o * 128 + (uint32_t)((s ^ (o & 7)) * 16);
            cp_async16(sb + OFF_B0 + off,         Wh + o * KDIM + s * 8);
            cp_async16(sb + OFF_B0 + 16384 + off, Wl + o * KDIM + s * 8);
        }
        CP_COMMIT();
    }
    __syncthreads();

    float acc[2][8][4];
#pragma unroll
    for (int i = 0; i < 2; ++i)
#pragma unroll
        for (int j = 0; j < 8; ++j)
#pragma unroll
            for (int k = 0; k < 4; ++k) acc[i][j][k] = 0.0f;

    for (int c = 0; c < 16; ++c) {
        const int st = c & 1;
        // produce A(c)
#pragma unroll
        for (int q = 0; q < 4; ++q) {
            int id = q * 256 + tid;
            int n = id & 127, ii = id >> 7;
            float xv = Hs[c * 8 + ii][n];
            float e[8];
            expand8(xv, e);
            uint32_t h[4], l[4];
#pragma unroll
            for (int j = 0; j < 4; ++j) {
                float a = e[2 * j], b = e[2 * j + 1];
                __nv_bfloat16 ah = __float2bfloat16(a), bh = __float2bfloat16(b);
                h[j] = pack_bf16x2(a, b);
                l[j] = pack_bf16x2(a - __bfloat162float(ah), b - __bfloat162float(bh));
            }
            uint32_t off = (uint32_t)n * 128 + (uint32_t)((ii ^ (n & 7)) * 16);
            *(uint4*)(sm + OFF_AH + off) = make_uint4(h[0], h[1], h[2], h[3]);
            *(uint4*)(sm + OFF_AL + off) = make_uint4(l[0], l[1], l[2], l[3]);
        }
        // prefetch B(c+1) into other stage
        if (c + 1 < 16) {
            uint32_t bst = sb + OFF_B0 + (st ^ 1) * 32768;
#pragma unroll
            for (int q = 0; q < 4; ++q) {
                int idx = q * 256 + tid;
                int o = idx >> 3, s = idx & 7;
                uint32_t off = (uint32_t)o * 128 + (uint32_t)((s ^ (o & 7)) * 16);
                cp_async16(bst + off,         Wh + o * KDIM + (c + 1) * 64 + s * 8);
                cp_async16(bst + 16384 + off, Wl + o * KDIM + (c + 1) * 64 + s * 8);
            }
        }
        CP_COMMIT();
        CP_WAIT1();       // B(c) resident
        __syncthreads();

        const uint32_t bbase = sb + OFF_B0 + st * 32768;
#pragma unroll
        for (int kk = 0; kk < 4; ++kk) {
            uint32_t ah[2][4], al[2][4];
#pragma unroll
            for (int mt = 0; mt < 2; ++mt) {
                int m = m0w + mt * 16 + (lane & 15);
                uint32_t chunk = (uint32_t)((kk * 2 + (lane >> 4)) ^ (m & 7));
                uint32_t off = (uint32_t)m * 128 + chunk * 16;
                ldm_x4(ah[mt], sb + OFF_AH + off);
                ldm_x4(al[mt], sb + OFF_AL + off);
            }
            uint32_t bh[4][4], bl[4][4];
#pragma unroll
            for (int ng = 0; ng < 4; ++ng) {
                int n = n0w + ng * 16 + ((lane >> 4) << 3) + (lane & 7);
                uint32_t chunk = (uint32_t)((kk * 2 + ((lane >> 3) & 1)) ^ (n & 7));
                uint32_t off = (uint32_t)n * 128 + chunk * 16;
                ldm_x4(bh[ng], bbase + off);
                ldm_x4(bl[ng], bbase + 16384 + off);
            }
#pragma unroll
            for (int mt = 0; mt < 2; ++mt)
#pragma unroll
                for (int ng = 0; ng < 4; ++ng)
#pragma unroll
                    for (int hf = 0; hf < 2; ++hf) {
                        float* cc = acc[mt][ng * 2 + hf];
                        mma16816(cc, ah[mt], bh[ng][hf * 2], bh[ng][hf * 2 + 1]);
                        mma16816(cc, ah[mt], bl[ng][hf * 2], bl[ng][hf * 2 + 1]);
                        mma16816(cc, al[mt], bh[ng][hf * 2], bh[ng][hf * 2 + 1]);
                    }
        }
        __syncthreads();
    }

    // epilogue: write Y only
#pragma unroll
    for (int mt = 0; mt < 2; ++mt) {
        int r1 = row0 + m0w + mt * 16 + (lane >> 2);
        int r2 = r1 + 8;
        bool ok1 = r1 < N_NODES, ok2 = r2 < N_NODES;
        int cb = n0w + (lane & 3) * 2;
#pragma unroll
        for (int nt = 0; nt < 8; ++nt) {
            int col = cb + nt * 8;
            float* a = acc[mt][nt];
            if (ok1) *(float2*)&g_Y[r1 * FEAT + col] = make_float2(a[0], a[1]);
            if (ok2) *(float2*)&g_Y[r2 * FEAT + col] = make_float2(a[2], a[3]);
        }
    }
}

// ---------------- fused CSR aggregation + bias + silu ----------------
__global__ __launch_bounds__(256) void k_aggr(const float* __restrict__ bias) {
    int w = (blockIdx.x * 256 + threadIdx.x) >> 5;
    int lane = threadIdx.x & 31;
    if (w >= N_NODES) return;
    float dd = g_dinv[w];
    float dd2 = dd * dd;
    float4 a = *(const float4*)&g_Y[w * FEAT + lane * 4];
    a.x *= dd2; a.y *= dd2; a.z *= dd2; a.w *= dd2;

    int e = g_rowptr[w], end = g_rowptr[w + 1];
    for (; e + 2 <= end; e += 2) {
        int s0 = g_srcs[e], s1 = g_srcs[e + 1];
        float nm0 = g_dinv[s0] * dd, nm1 = g_dinv[s1] * dd;
        float4 v0 = *(const float4*)&g_Y[s0 * FEAT + lane * 4];
        float4 v1 = *(const float4*)&g_Y[s1 * FEAT + lane * 4];
        a.x += v0.x * nm0 + v1.x * nm1;
        a.y += v0.y * nm0 + v1.y * nm1;
        a.z += v0.z * nm0 + v1.z * nm1;
        a.w += v0.w * nm0 + v1.w * nm1;
    }
    if (e < end) {
        int s0 = g_srcs[e];
        float nm0 = g_dinv[s0] * dd;
        float4 v0 = *(const float4*)&g_Y[s0 * FEAT + lane * 4];
        a.x += v0.x * nm0; a.y += v0.y * nm0; a.z += v0.z * nm0; a.w += v0.w * nm0;
    }
    float4 bv = *(const float4*)&bias[lane * 4];
    a.x += bv.x; a.y += bv.y; a.z += bv.z; a.w += bv.w;
    a.x = a.x / (1.0f + __expf(-a.x));
    a.y = a.y / (1.0f + __expf(-a.y));
    a.z = a.z / (1.0f + __expf(-a.z));
    a.w = a.w / (1.0f + __expf(-a.w));
    *(float4*)&g_H[w * FEAT + lane * 4] = a;
}

// ---------------- pooling + readout ----------------
__global__ void k_pool(const int* __restrict__ batch) {
    int w = (blockIdx.x * 256 + threadIdx.x) >> 5;
    int lane = threadIdx.x & 31;
    if (w >= N_NODES) return;
    int g = batch[w];
    float4 v = *(const float4*)&g_H[w * FEAT + lane * 4];
    red_add_v4(&g_pool[g * FEAT + lane * 4], v);
    if (lane == 0) atomicAdd(&g_cnt[g], 1.0f);
}

__global__ void k_readout(float* __restrict__ out) {
    int g = blockIdx.x;
    int t = threadIdx.x;   // 128
    __shared__ float red[CLS][4];
    __shared__ float logits[CLS];

    float inv = 1.0f / fmaxf(g_cnt[g], 1.0f);
    float p = g_pool[g * FEAT + t] * inv;
    float e[8];
    expand8(p, e);

    float part[CLS];
#pragma unroll
    for (int c = 0; c < CLS; ++c) {
        const float* w = &g_Wr[c * KDIM + t * 8];
        float s = 0.0f;
#pragma unroll
        for (int j = 0; j < 8; ++j) s = fmaf(e[j], w[j], s);
        part[c] = s;
    }
    int lane = t & 31, wid = t >> 5;
#pragma unroll
    for (int c = 0; c < CLS; ++c) {
        float v = part[c];
#pragma unroll
        for (int o = 16; o > 0; o >>= 1) v += __shfl_down_sync(0xffffffffu, v, o);
        if (lane == 0) red[c][wid] = v;
    }
    __syncthreads();
    if (t < CLS) logits[t] = red[t][0] + red[t][1] + red[t][2] + red[t][3];
    __syncthreads();
    if (t == 0) {
        float m = -1e30f;
        for (int c = 0; c < CLS; ++c) m = fmaxf(m, logits[c]);
        float s = 0.0f;
        for (int c = 0; c < CLS; ++c) s += expf(logits[c] - m);
        float lse = m + logf(s);
        for (int c = 0; c < CLS; ++c) out[g * CLS + c] = logits[c] - lse;
    }
}

// ---------------- launch ----------------
extern "C" void kernel_launch(void* const* d_in, const int* in_sizes, int n_in,
                              void* d_out, int out_size) {
    const float* x     = (const float*)d_in[0];
    const int*   ei    = (const int*)d_in[1];
    const int*   batch = (const int*)d_in[2];
    const float* bw[3] = {(const float*)d_in[3], (const float*)d_in[7],  (const float*)d_in[11]};
    const float* sw[3] = {(const float*)d_in[4], (const float*)d_in[8],  (const float*)d_in[12]};
    const float* ss[3] = {(const float*)d_in[5], (const float*)d_in[9],  (const float*)d_in[13]};
    const float* bb[3] = {(const float*)d_in[6], (const float*)d_in[10], (const float*)d_in[14]};
    const float* bwr = (const float*)d_in[15];
    const float* swr = (const float*)d_in[16];
    const float* ssr = (const float*)d_in[17];
    float* out = (float*)d_out;

    cudaFuncSetAttribute(k_gemm_mma, cudaFuncAttributeMaxDynamicSharedMemorySize, SMEM_NEED);

    const int nscan = (N_NODES + 255) / 256;   // 196
    k_zeros<<<nscan, 256>>>();
    k_hist<<<(N_EDGES + 255) / 256, 256>>>(ei + N_EDGES);
    k_dinv<<<nscan, 256>>>();
    k_scan1<<<nscan, 256>>>();
    k_scan2<<<1, 256>>>(nscan);
    k_scan3<<<nscan, 256>>>();
    k_fill<<<(N_EDGES + 255) / 256, 256>>>(ei);

    k_wc<<<(FEAT * FEAT + 255) / 256, 256>>>(bw[0], sw[0], ss[0], 0, FEAT * FEAT);
    k_wc<<<(FEAT * FEAT + 255) / 256, 256>>>(bw[1], sw[1], ss[1], 1, FEAT * FEAT);
    k_wc<<<(FEAT * FEAT + 255) / 256, 256>>>(bw[2], sw[2], ss[2], 2, FEAT * FEAT);
    k_wc<<<(CLS * FEAT + 255) / 256, 256>>>(bwr, swr, ssr, 3, CLS * FEAT);

    int gemm_blocks = (N_NODES + 127) / 128;   // 391
    int aggr_blocks = (N_NODES * 32 + 255) / 256;
    for (int l = 0; l < 3; ++l) {
        k_gemm_mma<<<gemm_blocks, 256, SMEM_NEED>>>(x, l);
        k_aggr<<<aggr_blocks, 256>>>(bb[l]);
    }

    k_pool<<<(N_NODES * 32 + 255) / 256, 256>>>(batch);
    k_readout<<<NG, 128>>>(out);
}

// round 6
// speedup vs baseline: 2.3147x; 1.1181x over previous
#include <cuda_runtime.h>
#include <cuda_bf16.h>
#include <math.h>
#include <stdint.h>

#define N_NODES 50000
#define N_EDGES 800000
#define FEAT    128
#define CLS     10
#define NG      64
#define KDIM    1024

// ---------------- scratch ----------------
__device__ __align__(16) __nv_bfloat16 g_Wh[3][FEAT * KDIM];
__device__ __align__(16) __nv_bfloat16 g_Wl[3][FEAT * KDIM];
__device__ __align__(16) float g_Wr[CLS * KDIM];
__device__ int   g_degi[N_NODES];
__device__ float g_dinv[N_NODES];
__device__ int   g_rowptr[N_NODES + 1];
__device__ int   g_wofs[N_NODES];
__device__ int   g_srcs[N_EDGES];
__device__ int   g_blocksum[256];
__device__ __align__(16) float g_Y[N_NODES * FEAT];
__device__ __align__(16) float g_H[N_NODES * FEAT];
__device__ float g_pool[NG * FEAT];
__device__ float g_cnt[NG];

// ---------------- helpers ----------------
__device__ __forceinline__ uint32_t smem_u32(const void* p) {
    uint32_t a;
    asm("{ .reg .u64 t; cvta.to.shared.u64 t, %1; cvt.u32.u64 %0, t; }" : "=r"(a) : "l"(p));
    return a;
}
__device__ __forceinline__ void red_add_v4(float* addr, float4 v) {
    asm volatile("red.global.add.v4.f32 [%0], {%1, %2, %3, %4};"
                 :: "l"(addr), "f"(v.x), "f"(v.y), "f"(v.z), "f"(v.w) : "memory");
}
__device__ __forceinline__ void ldm_x4(uint32_t* r, uint32_t addr) {
    asm volatile("ldmatrix.sync.aligned.m8n8.x4.shared.b16 {%0,%1,%2,%3}, [%4];"
                 : "=r"(r[0]), "=r"(r[1]), "=r"(r[2]), "=r"(r[3]) : "r"(addr));
}
__device__ __forceinline__ void mma16816(float* c, const uint32_t* a, uint32_t b0, uint32_t b1) {
    asm volatile("mma.sync.aligned.m16n8k16.row.col.f32.bf16.bf16.f32 "
                 "{%0,%1,%2,%3}, {%4,%5,%6,%7}, {%8,%9}, {%0,%1,%2,%3};"
                 : "+f"(c[0]), "+f"(c[1]), "+f"(c[2]), "+f"(c[3])
                 : "r"(a[0]), "r"(a[1]), "r"(a[2]), "r"(a[3]), "r"(b0), "r"(b1));
}
__device__ __forceinline__ void cp_async16(uint32_t smem_dst, const void* gsrc) {
    asm volatile("cp.async.cg.shared.global [%0], [%1], 16;" :: "r"(smem_dst), "l"(gsrc) : "memory");
}
#define CP_COMMIT() asm volatile("cp.async.commit_group;" ::: "memory")
#define CP_WAIT1()  asm volatile("cp.async.wait_group 1;" ::: "memory")
#define CP_WAIT0()  asm volatile("cp.async.wait_group 0;" ::: "memory")

// closed-form expansion: [silu(x), B0..B6], uniform cubic B-spline, knots -2.5..2.5 step 0.5
__device__ __forceinline__ void expand8(float x, float* e) {
    e[0] = x / (1.0f + __expf(-x));
    float u  = (x + 2.5f) * 2.0f;
    float fj = floorf(u);
    int   ji = (int)fj;
    float t  = u - fj;
    float t2 = t * t, t3 = t2 * t;
    float v3 = t3 * (1.0f / 6.0f);
    float v2 = (1.0f / 6.0f) * (-3.0f * t3 + 3.0f * t2 + 3.0f * t + 1.0f);
    float v1 = (1.0f / 6.0f) * (3.0f * t3 - 6.0f * t2 + 4.0f);
    float omt = 1.0f - t;
    float v0 = (1.0f / 6.0f) * omt * omt * omt;
    if (!(u >= 0.0f && u < 10.0f)) { v0 = v1 = v2 = v3 = 0.0f; }
#pragma unroll
    for (int m = 0; m < 7; ++m) {
        int d = ji - m;
        float r = 0.0f;
        r = (d == 3) ? v0 : r;
        r = (d == 2) ? v1 : r;
        r = (d == 1) ? v2 : r;
        r = (d == 0) ? v3 : r;
        e[1 + m] = r;
    }
}
__device__ __forceinline__ uint32_t pack_bf16x2(float a, float b) {
    __nv_bfloat162 t = __floats2bfloat162_rn(a, b);
    return *(uint32_t*)&t;
}

// ---------------- fused setup: zeros + all combined-weight prep ----------------
__global__ void k_prep(const float* __restrict__ bw0, const float* __restrict__ sw0, const float* __restrict__ ss0,
                       const float* __restrict__ bw1, const float* __restrict__ sw1, const float* __restrict__ ss1,
                       const float* __restrict__ bw2, const float* __restrict__ sw2, const float* __restrict__ ss2,
                       const float* __restrict__ bwr, const float* __restrict__ swr, const float* __restrict__ ssr) {
    int t = blockIdx.x * 256 + threadIdx.x;
    if (t < N_NODES)   g_degi[t] = 0;
    if (t < NG * FEAT) g_pool[t] = 0.0f;
    if (t < NG)        g_cnt[t]  = 0.0f;

    const int NW = FEAT * FEAT;                  // 16384
    if (t < 3 * NW + CLS * FEAT) {
        int which = t / NW;
        int i = t - which * NW;
        const float *bw, *sw, *ss;
        if      (which == 0) { bw = bw0; sw = sw0; ss = ss0; }
        else if (which == 1) { bw = bw1; sw = sw1; ss = ss1; }
        else if (which == 2) { bw = bw2; sw = sw2; ss = ss2; }
        else                 { bw = bwr; sw = swr; ss = ssr; }
        float v[8];
        v[0] = bw[i];
        float s = ss[i];
#pragma unroll
        for (int k = 0; k < 7; ++k) v[1 + k] = sw[i * 7 + k] * s;
        if (which < 3) {
            __nv_bfloat16* wh = &g_Wh[which][i * 8];
            __nv_bfloat16* wl = &g_Wl[which][i * 8];
#pragma unroll
            for (int j = 0; j < 8; ++j) {
                __nv_bfloat16 hi = __float2bfloat16(v[j]);
                wh[j] = hi;
                wl[j] = __float2bfloat16(v[j] - __bfloat162float(hi));
            }
        } else {
            float* d = g_Wr + i * 8;
#pragma unroll
            for (int j = 0; j < 8; ++j) d[j] = v[j];
        }
    }
}
__global__ void k_hist(const int* __restrict__ dst) {
    int e = blockIdx.x * 256 + threadIdx.x;
    if (e < N_EDGES) atomicAdd(&g_degi[dst[e]], 1);
}
__global__ void k_scan1() {
    __shared__ int s[256];
    int i = blockIdx.x * 256 + threadIdx.x;
    int v = (i < N_NODES) ? g_degi[i] : 0;
    if (i < N_NODES) g_dinv[i] = rsqrtf((float)v + 1.0f);
    s[threadIdx.x] = v;
    __syncthreads();
    for (int o = 1; o < 256; o <<= 1) {
        int t = (threadIdx.x >= o) ? s[threadIdx.x - o] : 0;
        __syncthreads();
        s[threadIdx.x] += t;
        __syncthreads();
    }
    if (i < N_NODES) g_rowptr[i] = s[threadIdx.x] - v;
    if (threadIdx.x == 255) g_blocksum[blockIdx.x] = s[255];
}
__global__ void k_scan2(int nblocks) {
    __shared__ int s[256];
    int i = threadIdx.x;
    int v = (i < nblocks) ? g_blocksum[i] : 0;
    s[i] = v;
    __syncthreads();
    for (int o = 1; o < 256; o <<= 1) {
        int t = (i >= o) ? s[i - o] : 0;
        __syncthreads();
        s[i] += t;
        __syncthreads();
    }
    if (i < nblocks) g_blocksum[i] = s[i] - v;
}
__global__ void k_scan3() {
    int i = blockIdx.x * 256 + threadIdx.x;
    if (i < N_NODES) {
        int r = g_rowptr[i] + g_blocksum[blockIdx.x];
        g_rowptr[i] = r;
        g_wofs[i]   = r;
    }
    if (i == 0) g_rowptr[N_NODES] = N_EDGES;
}
__global__ void k_fill(const int* __restrict__ ei) {
    int e = blockIdx.x * 256 + threadIdx.x;
    if (e >= N_EDGES) return;
    int d = ei[N_EDGES + e];
    int pos = atomicAdd(&g_wofs[d], 1);
    g_srcs[pos] = ei[e];
}

// ---------------- pipelined HMMA fused KAN-linear GEMM ----------------
// A triple-buffered (3 x 32KB), B triple-buffered (3 x 32KB) -> one sync/chunk is race-free:
// writer stage (c+1)%3 never aliases the lagging consumer's stage (c-1)%3.
#define OFF_A 0
#define A_STAGE 32768
#define OFF_B 98304
#define B_STAGE 32768
#define SMEM_NEED (OFF_B + 3 * B_STAGE)   // 196608

__global__ __launch_bounds__(256) void k_gemm_mma(const float* __restrict__ x, int layer) {
    extern __shared__ __align__(16) char sm[];
    uint32_t sb = smem_u32(sm);

    const float* Hin = (layer == 0) ? x : g_H;
    const __nv_bfloat16* Wh = g_Wh[layer];
    const __nv_bfloat16* Wl = g_Wl[layer];

    const int tid = threadIdx.x, lane = tid & 31, wid = tid >> 5;
    const int row0 = blockIdx.x * 128;
    const int m0w = (wid >> 1) * 32;
    const int n0w = (wid & 1) * 64;

    // per-thread H coords: id = q*256+tid -> row n=id>>3, dim dd=id&7
    int hrow[4], hdd;
    hdd = tid & 7;
#pragma unroll
    for (int q = 0; q < 4; ++q) hrow[q] = q * 32 + (tid >> 3);
    bool hok[4];
#pragma unroll
    for (int q = 0; q < 4; ++q) hok[q] = (row0 + hrow[q]) < N_NODES;

    float hv[2][4];
#pragma unroll
    for (int q = 0; q < 4; ++q)
        hv[0][q] = hok[q] ? Hin[(row0 + hrow[q]) * FEAT + hdd] : 0.0f;
#pragma unroll
    for (int q = 0; q < 4; ++q)
        hv[1][q] = hok[q] ? Hin[(row0 + hrow[q]) * FEAT + 8 + hdd] : 0.0f;

    // prefetch B(0) into B stage 0
    {
#pragma unroll
        for (int q = 0; q < 4; ++q) {
            int idx = q * 256 + tid;
            int o = idx >> 3, s = idx & 7;
            uint32_t off = (uint32_t)o * 128 + (uint32_t)((s ^ (o & 7)) * 16);
            cp_async16(sb + OFF_B + off,         Wh + o * KDIM + s * 8);
            cp_async16(sb + OFF_B + 16384 + off, Wl + o * KDIM + s * 8);
        }
        CP_COMMIT();
    }

    // produce A(0) into A stage 0
    {
        char* bufA = sm + OFF_A;
#pragma unroll
        for (int q = 0; q < 4; ++q) {
            int id = q * 256 + tid;
            int n = id >> 3, dd = id & 7;
            float e[8];
            expand8(hv[0][q], e);
            uint32_t h[4], l[4];
#pragma unroll
            for (int j = 0; j < 4; ++j) {
                float a = e[2 * j], b = e[2 * j + 1];
                __nv_bfloat16 ah = __float2bfloat16(a), bh = __float2bfloat16(b);
                h[j] = pack_bf16x2(a, b);
                l[j] = pack_bf16x2(a - __bfloat162float(ah), b - __bfloat162float(bh));
            }
            uint32_t off = (uint32_t)n * 128 + (uint32_t)((dd ^ (n & 7)) * 16);
            *(uint4*)(bufA + off)         = make_uint4(h[0], h[1], h[2], h[3]);
            *(uint4*)(bufA + 16384 + off) = make_uint4(l[0], l[1], l[2], l[3]);
        }
    }

    float acc[2][8][4];
#pragma unroll
    for (int i = 0; i < 2; ++i)
#pragma unroll
        for (int j = 0; j < 8; ++j)
#pragma unroll
            for (int k = 0; k < 4; ++k) acc[i][j][k] = 0.0f;

    int stage_next = 1;   // stage of chunk c+1 (cycles mod 3)
    for (int c = 0; c < 16; ++c) {
        // prefetch B(c+1) into stage (c+1)%3
        if (c + 1 < 16) {
            uint32_t bst = sb + OFF_B + stage_next * B_STAGE;
#pragma unroll
            for (int q = 0; q < 4; ++q) {
                int idx = q * 256 + tid;
                int o = idx >> 3, s = idx & 7;
                uint32_t off = (uint32_t)o * 128 + (uint32_t)((s ^ (o & 7)) * 16);
                cp_async16(bst + off,         Wh + o * KDIM + (c + 1) * 64 + s * 8);
                cp_async16(bst + 16384 + off, Wl + o * KDIM + (c + 1) * 64 + s * 8);
            }
            CP_COMMIT();
        }
        // issue H loads for chunk c+2
        if (c + 2 < 16) {
#pragma unroll
            for (int q = 0; q < 4; ++q)
                hv[c & 1][q] = hok[q] ? Hin[(row0 + hrow[q]) * FEAT + (c + 2) * 8 + hdd] : 0.0f;
        }
        // produce A(c+1) into stage (c+1)%3
        if (c + 1 < 16) {
            char* bufA = sm + OFF_A + stage_next * A_STAGE;
            const float* hvc = hv[(c + 1) & 1];
#pragma unroll
            for (int q = 0; q < 4; ++q) {
                int id = q * 256 + tid;
                int n = id >> 3, dd = id & 7;
                float e[8];
                expand8(hvc[q], e);
                uint32_t h[4], l[4];
#pragma unroll
                for (int j = 0; j < 4; ++j) {
                    float a = e[2 * j], b = e[2 * j + 1];
                    __nv_bfloat16 ah = __float2bfloat16(a), bh = __float2bfloat16(b);
                    h[j] = pack_bf16x2(a, b);
                    l[j] = pack_bf16x2(a - __bfloat162float(ah), b - __bfloat162float(bh));
                }
                uint32_t off = (uint32_t)n * 128 + (uint32_t)((dd ^ (n & 7)) * 16);
                *(uint4*)(bufA + off)         = make_uint4(h[0], h[1], h[2], h[3]);
                *(uint4*)(bufA + 16384 + off) = make_uint4(l[0], l[1], l[2], l[3]);
            }
        }
        if (c == 15) { CP_WAIT0(); } else { CP_WAIT1(); }
        __syncthreads();

        // consume A(c), B(c) from stage c%3
        const int ast = (stage_next + 2) % 3;           // = c % 3
        const uint32_t abase = sb + OFF_A + ast * A_STAGE;
        const uint32_t bbase = sb + OFF_B + ast * B_STAGE;
#pragma unroll
        for (int kk = 0; kk < 4; ++kk) {
            uint32_t ah[2][4], al[2][4];
#pragma unroll
            for (int mt = 0; mt < 2; ++mt) {
                int m = m0w + mt * 16 + (lane & 15);
                uint32_t chunk = (uint32_t)((kk * 2 + (lane >> 4)) ^ (m & 7));
                uint32_t off = (uint32_t)m * 128 + chunk * 16;
                ldm_x4(ah[mt], abase + off);
                ldm_x4(al[mt], abase + 16384 + off);
            }
            uint32_t bh[4][4], bl[4][4];
#pragma unroll
            for (int ng = 0; ng < 4; ++ng) {
                int n = n0w + ng * 16 + ((lane >> 4) << 3) + (lane & 7);
                uint32_t chunk = (uint32_t)((kk * 2 + ((lane >> 3) & 1)) ^ (n & 7));
                uint32_t off = (uint32_t)n * 128 + chunk * 16;
                ldm_x4(bh[ng], bbase + off);
                ldm_x4(bl[ng], bbase + 16384 + off);
            }
#pragma unroll
            for (int mt = 0; mt < 2; ++mt)
#pragma unroll
                for (int ng = 0; ng < 4; ++ng)
#pragma unroll
                    for (int hf = 0; hf < 2; ++hf) {
                        float* cc = acc[mt][ng * 2 + hf];
                        mma16816(cc, ah[mt], bh[ng][hf * 2], bh[ng][hf * 2 + 1]);
                        mma16816(cc, ah[mt], bl[ng][hf * 2], bl[ng][hf * 2 + 1]);
                        mma16816(cc, al[mt], bh[ng][hf * 2], bh[ng][hf * 2 + 1]);
                    }
        }
        stage_next = (stage_next + 1) % 3;
    }

    // epilogue
#pragma unroll
    for (int mt = 0; mt < 2; ++mt) {
        int r1 = row0 + m0w + mt * 16 + (lane >> 2);
        int r2 = r1 + 8;
        bool ok1 = r1 < N_NODES, ok2 = r2 < N_NODES;
        int cb = n0w + (lane & 3) * 2;
#pragma unroll
        for (int nt = 0; nt < 8; ++nt) {
            int col = cb + nt * 8;
            float* a = acc[mt][nt];
            if (ok1) *(float2*)&g_Y[r1 * FEAT + col] = make_float2(a[0], a[1]);
            if (ok2) *(float2*)&g_Y[r2 * FEAT + col] = make_float2(a[2], a[3]);
        }
    }
}

// ---------------- fused CSR aggregation + bias + silu ----------------
__global__ __launch_bounds__(256) void k_aggr(const float* __restrict__ bias) {
    int w = (blockIdx.x * 256 + threadIdx.x) >> 5;
    int lane = threadIdx.x & 31;
    if (w >= N_NODES) return;
    float dd = g_dinv[w];
    float dd2 = dd * dd;
    float4 a = *(const float4*)&g_Y[w * FEAT + lane * 4];
    a.x *= dd2; a.y *= dd2; a.z *= dd2; a.w *= dd2;

    int e = g_rowptr[w], end = g_rowptr[w + 1];
    for (; e + 2 <= end; e += 2) {
        int s0 = g_srcs[e], s1 = g_srcs[e + 1];
        float nm0 = g_dinv[s0] * dd, nm1 = g_dinv[s1] * dd;
        float4 v0 = *(const float4*)&g_Y[s0 * FEAT + lane * 4];
        float4 v1 = *(const float4*)&g_Y[s1 * FEAT + lane * 4];
        a.x += v0.x * nm0 + v1.x * nm1;
        a.y += v0.y * nm0 + v1.y * nm1;
        a.z += v0.z * nm0 + v1.z * nm1;
        a.w += v0.w * nm0 + v1.w * nm1;
    }
    if (e < end) {
        int s0 = g_srcs[e];
        float nm0 = g_dinv[s0] * dd;
        float4 v0 = *(const float4*)&g_Y[s0 * FEAT + lane * 4];
        a.x += v0.x * nm0; a.y += v0.y * nm0; a.z += v0.z * nm0; a.w += v0.w * nm0;
    }
    float4 bv = *(const float4*)&bias[lane * 4];
    a.x += bv.x; a.y += bv.y; a.z += bv.z; a.w += bv.w;
    a.x = a.x / (1.0f + __expf(-a.x));
    a.y = a.y / (1.0f + __expf(-a.y));
    a.z = a.z / (1.0f + __expf(-a.z));
    a.w = a.w / (1.0f + __expf(-a.w));
    *(float4*)&g_H[w * FEAT + lane * 4] = a;
}

// ---------------- pooling + readout ----------------
__global__ void k_pool(const int* __restrict__ batch) {
    int w = (blockIdx.x * 256 + threadIdx.x) >> 5;
    int lane = threadIdx.x & 31;
    if (w >= N_NODES) return;
    int g = batch[w];
    float4 v = *(const float4*)&g_H[w * FEAT + lane * 4];
    red_add_v4(&g_pool[g * FEAT + lane * 4], v);
    if (lane == 0) atomicAdd(&g_cnt[g], 1.0f);
}

__global__ void k_readout(float* __restrict__ out) {
    int g = blockIdx.x;
    int t = threadIdx.x;   // 128
    __shared__ float red[CLS][4];
    __shared__ float logits[CLS];

    float inv = 1.0f / fmaxf(g_cnt[g], 1.0f);
    float p = g_pool[g * FEAT + t] * inv;
    float e[8];
    expand8(p, e);

    float part[CLS];
#pragma unroll
    for (int c = 0; c < CLS; ++c) {
        const float* w = &g_Wr[c * KDIM + t * 8];
        float s = 0.0f;
#pragma unroll
        for (int j = 0; j < 8; ++j) s = fmaf(e[j], w[j], s);
        part[c] = s;
    }
    int lane = t & 31, wid = t >> 5;
#pragma unroll
    for (int c = 0; c < CLS; ++c) {
        float v = part[c];
#pragma unroll
        for (int o = 16; o > 0; o >>= 1) v += __shfl_down_sync(0xffffffffu, v, o);
        if (lane == 0) red[c][wid] = v;
    }
    __syncthreads();
    if (t < CLS) logits[t] = red[t][0] + red[t][1] + red[t][2] + red[t][3];
    __syncthreads();
    if (t == 0) {
        float m = -1e30f;
        for (int c = 0; c < CLS; ++c) m = fmaxf(m, logits[c]);
        float s = 0.0f;
        for (int c = 0; c < CLS; ++c) s += expf(logits[c] - m);
        float lse = m + logf(s);
        for (int c = 0; c < CLS; ++c) out[g * CLS + c] = logits[c] - lse;
    }
}

// ---------------- launch ----------------
extern "C" void kernel_launch(void* const* d_in, const int* in_sizes, int n_in,
                              void* d_out, int out_size) {
    const float* x     = (const float*)d_in[0];
    const int*   ei    = (const int*)d_in[1];
    const int*   batch = (const int*)d_in[2];
    float* out = (float*)d_out;

    cudaFuncSetAttribute(k_gemm_mma, cudaFuncAttributeMaxDynamicSharedMemorySize, SMEM_NEED);

    const int nscan = (N_NODES + 255) / 256;   // 196
    const int nprep = (3 * FEAT * FEAT + CLS * FEAT + 255) / 256;  // 198
    k_prep<<<(nprep > nscan ? nprep : nscan), 256>>>(
        (const float*)d_in[3],  (const float*)d_in[4],  (const float*)d_in[5],
        (const float*)d_in[7],  (const float*)d_in[8],  (const float*)d_in[9],
        (const float*)d_in[11], (const float*)d_in[12], (const float*)d_in[13],
        (const float*)d_in[15], (const float*)d_in[16], (const float*)d_in[17]);
    k_hist<<<(N_EDGES + 255) / 256, 256>>>(ei + N_EDGES);
    k_scan1<<<nscan, 256>>>();
    k_scan2<<<1, 256>>>(nscan);
    k_scan3<<<nscan, 256>>>();
    k_fill<<<(N_EDGES + 255) / 256, 256>>>(ei);

    const float* bb[3] = {(const float*)d_in[6], (const float*)d_in[10], (const float*)d_in[14]};
    int gemm_blocks = (N_NODES + 127) / 128;   // 391
    int aggr_blocks = (N_NODES * 32 + 255) / 256;
    for (int l = 0; l < 3; ++l) {
        k_gemm_mma<<<gemm_blocks, 256, SMEM_NEED>>>(x, l);
        k_aggr<<<aggr_blocks, 256>>>(bb[l]);
    }

    k_pool<<<(N_NODES * 32 + 255) / 256, 256>>>(batch);
    k_readout<<<NG, 128>>>(out);
}

// round 8
// speedup vs baseline: 2.4452x; 1.0563x over previous
#include <cuda_runtime.h>
#include <cuda_bf16.h>
#include <math.h>
#include <stdint.h>

#define N_NODES 50000
#define N_EDGES 800000
#define FEAT    128
#define CLS     10
#define NG      64
#define KDIM    1024

// ---------------- scratch ----------------
__device__ __align__(16) __nv_bfloat16 g_Wh[3][FEAT * KDIM];
__device__ __align__(16) __nv_bfloat16 g_Wl[3][FEAT * KDIM];
__device__ __align__(16) float g_Wr[CLS * KDIM];
__device__ int   g_degi[N_NODES];
__device__ float g_dinv[N_NODES];
__device__ int   g_rowptr[N_NODES + 1];
__device__ int   g_wofs[N_NODES];
__device__ int   g_srcs[N_EDGES];
__device__ int   g_blocksum[256];
__device__ __align__(16) float g_Y[N_NODES * FEAT];
__device__ __align__(16) float g_H[N_NODES * FEAT];
__device__ float g_pool[NG * FEAT];
__device__ float g_cnt[NG];

// ---------------- helpers ----------------
__device__ __forceinline__ uint32_t smem_u32(const void* p) {
    uint32_t a;
    asm("{ .reg .u64 t; cvta.to.shared.u64 t, %1; cvt.u32.u64 %0, t; }" : "=r"(a) : "l"(p));
    return a;
}
__device__ __forceinline__ void red_add_v4(float* addr, float4 v) {
    asm volatile("red.global.add.v4.f32 [%0], {%1, %2, %3, %4};"
                 :: "l"(addr), "f"(v.x), "f"(v.y), "f"(v.z), "f"(v.w) : "memory");
}
__device__ __forceinline__ void ldm_x4(uint32_t* r, uint32_t addr) {
    asm volatile("ldmatrix.sync.aligned.m8n8.x4.shared.b16 {%0,%1,%2,%3}, [%4];"
                 : "=r"(r[0]), "=r"(r[1]), "=r"(r[2]), "=r"(r[3]) : "r"(addr));
}
__device__ __forceinline__ void mma16816(float* c, const uint32_t* a, uint32_t b0, uint32_t b1) {
    asm volatile("mma.sync.aligned.m16n8k16.row.col.f32.bf16.bf16.f32 "
                 "{%0,%1,%2,%3}, {%4,%5,%6,%7}, {%8,%9}, {%0,%1,%2,%3};"
                 : "+f"(c[0]), "+f"(c[1]), "+f"(c[2]), "+f"(c[3])
                 : "r"(a[0]), "r"(a[1]), "r"(a[2]), "r"(a[3]), "r"(b0), "r"(b1));
}
__device__ __forceinline__ void cp_async16(uint32_t smem_dst, const void* gsrc) {
    asm volatile("cp.async.cg.shared.global [%0], [%1], 16;" :: "r"(smem_dst), "l"(gsrc) : "memory");
}
#define CP_COMMIT() asm volatile("cp.async.commit_group;" ::: "memory")
#define CP_WAIT1()  asm volatile("cp.async.wait_group 1;" ::: "memory")
#define CP_WAIT0()  asm volatile("cp.async.wait_group 0;" ::: "memory")

// closed-form expansion: [silu(x), B0..B6], uniform cubic B-spline, knots -2.5..2.5 step 0.5
__device__ __forceinline__ void expand8(float x, float* e) {
    e[0] = x / (1.0f + __expf(-x));
    float u  = (x + 2.5f) * 2.0f;
    float fj = floorf(u);
    int   ji = (int)fj;
    float t  = u - fj;
    float t2 = t * t, t3 = t2 * t;
    float v3 = t3 * (1.0f / 6.0f);
    float v2 = (1.0f / 6.0f) * (-3.0f * t3 + 3.0f * t2 + 3.0f * t + 1.0f);
    float v1 = (1.0f / 6.0f) * (3.0f * t3 - 6.0f * t2 + 4.0f);
    float omt = 1.0f - t;
    float v0 = (1.0f / 6.0f) * omt * omt * omt;
    if (!(u >= 0.0f && u < 10.0f)) { v0 = v1 = v2 = v3 = 0.0f; }
#pragma unroll
    for (int m = 0; m < 7; ++m) {
        int d = ji - m;
        float r = 0.0f;
        r = (d == 3) ? v0 : r;
        r = (d == 2) ? v1 : r;
        r = (d == 1) ? v2 : r;
        r = (d == 0) ? v3 : r;
        e[1 + m] = r;
    }
}
__device__ __forceinline__ uint32_t pack_bf16x2(float a, float b) {
    __nv_bfloat162 t = __floats2bfloat162_rn(a, b);
    return *(uint32_t*)&t;
}

// ---------------- fused setup ----------------
__global__ void k_prep(const float* __restrict__ bw0, const float* __restrict__ sw0, const float* __restrict__ ss0,
                       const float* __restrict__ bw1, const float* __restrict__ sw1, const float* __restrict__ ss1,
                       const float* __restrict__ bw2, const float* __restrict__ sw2, const float* __restrict__ ss2,
                       const float* __restrict__ bwr, const float* __restrict__ swr, const float* __restrict__ ssr) {
    int t = blockIdx.x * 256 + threadIdx.x;
    if (t < N_NODES)   g_degi[t] = 0;
    if (t < NG * FEAT) g_pool[t] = 0.0f;
    if (t < NG)        g_cnt[t]  = 0.0f;

    const int NW = FEAT * FEAT;
    if (t < 3 * NW + CLS * FEAT) {
        int which = t / NW;
        int i = t - which * NW;
        const float *bw, *sw, *ss;
        if      (which == 0) { bw = bw0; sw = sw0; ss = ss0; }
        else if (which == 1) { bw = bw1; sw = sw1; ss = ss1; }
        else if (which == 2) { bw = bw2; sw = sw2; ss = ss2; }
        else                 { bw = bwr; sw = swr; ss = ssr; }
        float v[8];
        v[0] = bw[i];
        float s = ss[i];
#pragma unroll
        for (int k = 0; k < 7; ++k) v[1 + k] = sw[i * 7 + k] * s;
        if (which < 3) {
            __nv_bfloat16* wh = &g_Wh[which][i * 8];
            __nv_bfloat16* wl = &g_Wl[which][i * 8];
#pragma unroll
            for (int j = 0; j < 8; ++j) {
                __nv_bfloat16 hi = __float2bfloat16(v[j]);
                wh[j] = hi;
                wl[j] = __float2bfloat16(v[j] - __bfloat162float(hi));
            }
        } else {
            float* d = g_Wr + i * 8;
#pragma unroll
            for (int j = 0; j < 8; ++j) d[j] = v[j];
        }
    }
}
__global__ void k_hist(const int* __restrict__ dst) {
    int e = blockIdx.x * 256 + threadIdx.x;
    if (e < N_EDGES) atomicAdd(&g_degi[dst[e]], 1);
}
__global__ void k_scan1() {
    __shared__ int s[256];
    int i = blockIdx.x * 256 + threadIdx.x;
    int v = (i < N_NODES) ? g_degi[i] : 0;
    if (i < N_NODES) g_dinv[i] = rsqrtf((float)v + 1.0f);
    s[threadIdx.x] = v;
    __syncthreads();
    for (int o = 1; o < 256; o <<= 1) {
        int t = (threadIdx.x >= o) ? s[threadIdx.x - o] : 0;
        __syncthreads();
        s[threadIdx.x] += t;
        __syncthreads();
    }
    if (i < N_NODES) g_rowptr[i] = s[threadIdx.x] - v;
    if (threadIdx.x == 255) g_blocksum[blockIdx.x] = s[255];
}
__global__ void k_scan2(int nblocks) {
    __shared__ int s[256];
    int i = threadIdx.x;
    int v = (i < nblocks) ? g_blocksum[i] : 0;
    s[i] = v;
    __syncthreads();
    for (int o = 1; o < 256; o <<= 1) {
        int t = (i >= o) ? s[i - o] : 0;
        __syncthreads();
        s[i] += t;
        __syncthreads();
    }
    if (i < nblocks) g_blocksum[i] = s[i] - v;
}
__global__ void k_scan3() {
    int i = blockIdx.x * 256 + threadIdx.x;
    if (i < N_NODES) {
        int r = g_rowptr[i] + g_blocksum[blockIdx.x];
        g_rowptr[i] = r;
        g_wofs[i]   = r;
    }
    if (i == 0) g_rowptr[N_NODES] = N_EDGES;
}
__global__ void k_fill(const int* __restrict__ ei) {
    int e = blockIdx.x * 256 + threadIdx.x;
    if (e >= N_EDGES) return;
    int d = ei[N_EDGES + e];
    int pos = atomicAdd(&g_wofs[d], 1);
    g_srcs[pos] = ei[e];
}

// ---------------- pipelined HMMA fused KAN-linear GEMM ----------------
// K-chunk = 32 cols. A,B triple-buffered 16KB stages -> 96KB smem -> 2 CTAs/SM.
// 64B rows, 4x16B units, XOR swizzle with (row>>1)&3; one sync per chunk (mod-3 safe).
#define A_STAGE 16384
#define B_STAGE 16384
#define OFF_B   (3 * A_STAGE)
#define SMEM_NEED (OFF_B + 3 * B_STAGE)   // 98304

__global__ __launch_bounds__(256, 2) void k_gemm_mma(const float* __restrict__ x, int layer) {
    extern __shared__ __align__(16) char sm[];
    uint32_t sb = smem_u32(sm);

    const float* Hin = (layer == 0) ? x : g_H;
    const __nv_bfloat16* Wh = g_Wh[layer];
    const __nv_bfloat16* Wl = g_Wl[layer];

    const int tid = threadIdx.x, lane = tid & 31, wid = tid >> 5;
    const int row0 = blockIdx.x * 128;
    const int m0w = (wid >> 1) * 32;
    const int n0w = (wid & 1) * 64;

    // H coords: per chunk 512 items (128 rows x 4 dims); thread does q<2: id=q*256+tid
    const int hn0 = tid >> 2;            // q=0 row
    const int hn1 = 64 + (tid >> 2);     // q=1 row
    const int hdd = tid & 3;
    const bool hok0 = (row0 + hn0) < N_NODES;
    const bool hok1 = (row0 + hn1) < N_NODES;

    float hv[2][2];
    hv[0][0] = hok0 ? Hin[(row0 + hn0) * FEAT + hdd]     : 0.0f;
    hv[0][1] = hok1 ? Hin[(row0 + hn1) * FEAT + hdd]     : 0.0f;
    hv[1][0] = hok0 ? Hin[(row0 + hn0) * FEAT + 4 + hdd] : 0.0f;
    hv[1][1] = hok1 ? Hin[(row0 + hn1) * FEAT + 4 + hdd] : 0.0f;

    // prefetch B(0) into stage 0: 512 units of 16B each for hi and lo
    {
#pragma unroll
        for (int q = 0; q < 2; ++q) {
            int idx = q * 256 + tid;       // 0..511
            int o = idx >> 2, s = idx & 3;
            uint32_t off = (uint32_t)o * 64 + (uint32_t)((s ^ ((o >> 1) & 3)) * 16);
            cp_async16(sb + OFF_B + off,        Wh + o * KDIM + s * 8);
            cp_async16(sb + OFF_B + 8192 + off, Wl + o * KDIM + s * 8);
        }
        CP_COMMIT();
    }

    // produce A(0) into stage 0
    {
        char* bufA = sm;
#pragma unroll
        for (int q = 0; q < 2; ++q) {
            int n  = (q == 0) ? hn0 : hn1;
            float e[8];
            expand8(hv[0][q], e);
            uint32_t h[4], l[4];
#pragma unroll
            for (int j = 0; j < 4; ++j) {
                float a = e[2 * j], b = e[2 * j + 1];
                __nv_bfloat16 ah = __float2bfloat16(a), bh = __float2bfloat16(b);
                h[j] = pack_bf16x2(a, b);
                l[j] = pack_bf16x2(a - __bfloat162float(ah), b - __bfloat162float(bh));
            }
            uint32_t off = (uint32_t)n * 64 + (uint32_t)((hdd ^ ((n >> 1) & 3)) * 16);
            *(uint4*)(bufA + off)        = make_uint4(h[0], h[1], h[2], h[3]);
            *(uint4*)(bufA + 8192 + off) = make_uint4(l[0], l[1], l[2], l[3]);
        }
    }

    float acc[2][8][4];
#pragma unroll
    for (int i = 0; i < 2; ++i)
#pragma unroll
        for (int j = 0; j < 8; ++j)
#pragma unroll
            for (int k = 0; k < 4; ++k) acc[i][j][k] = 0.0f;

    int stage_next = 1;
    for (int c = 0; c < 32; ++c) {
        // prefetch B(c+1)
        if (c + 1 < 32) {
            uint32_t bst = sb + OFF_B + stage_next * B_STAGE;
#pragma unroll
            for (int q = 0; q < 2; ++q) {
                int idx = q * 256 + tid;
                int o = idx >> 2, s = idx & 3;
                uint32_t off = (uint32_t)o * 64 + (uint32_t)((s ^ ((o >> 1) & 3)) * 16);
                cp_async16(bst + off,        Wh + o * KDIM + (c + 1) * 32 + s * 8);
                cp_async16(bst + 8192 + off, Wl + o * KDIM + (c + 1) * 32 + s * 8);
            }
            CP_COMMIT();
        }
        // H loads for chunk c+2
        if (c + 2 < 32) {
            hv[c & 1][0] = hok0 ? Hin[(row0 + hn0) * FEAT + (c + 2) * 4 + hdd] : 0.0f;
            hv[c & 1][1] = hok1 ? Hin[(row0 + hn1) * FEAT + (c + 2) * 4 + hdd] : 0.0f;
        }
        // produce A(c+1)
        if (c + 1 < 32) {
            char* bufA = sm + stage_next * A_STAGE;
            const float* hvc = hv[(c + 1) & 1];
#pragma unroll
            for (int q = 0; q < 2; ++q) {
                int n  = (q == 0) ? hn0 : hn1;
                float e[8];
                expand8(hvc[q], e);
                uint32_t h[4], l[4];
#pragma unroll
                for (int j = 0; j < 4; ++j) {
                    float a = e[2 * j], b = e[2 * j + 1];
                    __nv_bfloat16 ah = __float2bfloat16(a), bh = __float2bfloat16(b);
                    h[j] = pack_bf16x2(a, b);
                    l[j] = pack_bf16x2(a - __bfloat162float(ah), b - __bfloat162float(bh));
                }
                uint32_t off = (uint32_t)n * 64 + (uint32_t)((hdd ^ ((n >> 1) & 3)) * 16);
                *(uint4*)(bufA + off)        = make_uint4(h[0], h[1], h[2], h[3]);
                *(uint4*)(bufA + 8192 + off) = make_uint4(l[0], l[1], l[2], l[3]);
            }
        }
        if (c == 31) { CP_WAIT0(); } else { CP_WAIT1(); }
        __syncthreads();

        // consume chunk c from stage c%3
        const int ast = (stage_next + 2) % 3;
        const uint32_t abase = sb + ast * A_STAGE;
        const uint32_t bbase = sb + OFF_B + ast * B_STAGE;
#pragma unroll
        for (int kk = 0; kk < 2; ++kk) {
            uint32_t ah[2][4], al[2][4];
#pragma unroll
            for (int mt = 0; mt < 2; ++mt) {
                int m = m0w + mt * 16 + (lane & 15);
                uint32_t u = (uint32_t)((2 * kk + (lane >> 4)) ^ ((m >> 1) & 3));
                uint32_t off = (uint32_t)m * 64 + u * 16;
                ldm_x4(ah[mt], abase + off);
                ldm_x4(al[mt], abase + 8192 + off);
            }
            uint32_t bh[4][4], bl[4][4];
#pragma unroll
            for (int ng = 0; ng < 4; ++ng) {
                int n = n0w + ng * 16 + ((lane >> 4) << 3) + (lane & 7);
                uint32_t u = (uint32_t)((2 * kk + ((lane >> 3) & 1)) ^ ((n >> 1) & 3));
                uint32_t off = (uint32_t)n * 64 + u * 16;
                ldm_x4(bh[ng], bbase + off);
                ldm_x4(bl[ng], bbase + 8192 + off);
            }
#pragma unroll
            for (int mt = 0; mt < 2; ++mt)
#pragma unroll
                for (int ng = 0; ng < 4; ++ng)
#pragma unroll
                    for (int hf = 0; hf < 2; ++hf) {
                        float* cc = acc[mt][ng * 2 + hf];
                        mma16816(cc, ah[mt], bh[ng][hf * 2], bh[ng][hf * 2 + 1]);
                        mma16816(cc, ah[mt], bl[ng][hf * 2], bl[ng][hf * 2 + 1]);
                        mma16816(cc, al[mt], bh[ng][hf * 2], bh[ng][hf * 2 + 1]);
                    }
        }
        stage_next = (stage_next + 1) % 3;
    }

    // epilogue
#pragma unroll
    for (int mt = 0; mt < 2; ++mt) {
        int r1 = row0 + m0w + mt * 16 + (lane >> 2);
        int r2 = r1 + 8;
        bool ok1 = r1 < N_NODES, ok2 = r2 < N_NODES;
        int cb = n0w + (lane & 3) * 2;
#pragma unroll
        for (int nt = 0; nt < 8; ++nt) {
            int col = cb + nt * 8;
            float* a = acc[mt][nt];
            if (ok1) *(float2*)&g_Y[r1 * FEAT + col] = make_float2(a[0], a[1]);
            if (ok2) *(float2*)&g_Y[r2 * FEAT + col] = make_float2(a[2], a[3]);
        }
    }
}

// ---------------- fused CSR aggregation + bias + silu ----------------
__global__ __launch_bounds__(256) void k_aggr(const float* __restrict__ bias) {
    int w = (blockIdx.x * 256 + threadIdx.x) >> 5;
    int lane = threadIdx.x & 31;
    if (w >= N_NODES) return;
    float dd = g_dinv[w];
    float dd2 = dd * dd;
    float4 a = *(const float4*)&g_Y[w * FEAT + lane * 4];
    a.x *= dd2; a.y *= dd2; a.z *= dd2; a.w *= dd2;

    int e = g_rowptr[w], end = g_rowptr[w + 1];
    for (; e + 2 <= end; e += 2) {
        int s0 = g_srcs[e], s1 = g_srcs[e + 1];
        float nm0 = g_dinv[s0] * dd, nm1 = g_dinv[s1] * dd;
        float4 v0 = *(const float4*)&g_Y[s0 * FEAT + lane * 4];
        float4 v1 = *(const float4*)&g_Y[s1 * FEAT + lane * 4];
        a.x += v0.x * nm0 + v1.x * nm1;
        a.y += v0.y * nm0 + v1.y * nm1;
        a.z += v0.z * nm0 + v1.z * nm1;
        a.w += v0.w * nm0 + v1.w * nm1;
    }
    if (e < end) {
        int s0 = g_srcs[e];
        float nm0 = g_dinv[s0] * dd;
        float4 v0 = *(const float4*)&g_Y[s0 * FEAT + lane * 4];
        a.x += v0.x * nm0; a.y += v0.y * nm0; a.z += v0.z * nm0; a.w += v0.w * nm0;
    }
    float4 bv = *(const float4*)&bias[lane * 4];
    a.x += bv.x; a.y += bv.y; a.z += bv.z; a.w += bv.w;
    a.x = a.x / (1.0f + __expf(-a.x));
    a.y = a.y / (1.0f + __expf(-a.y));
    a.z = a.z / (1.0f + __expf(-a.z));
    a.w = a.w / (1.0f + __expf(-a.w));
    *(float4*)&g_H[w * FEAT + lane * 4] = a;
}

// ---------------- pooling + readout ----------------
__global__ void k_pool(const int* __restrict__ batch) {
    int w = (blockIdx.x * 256 + threadIdx.x) >> 5;
    int lane = threadIdx.x & 31;
    if (w >= N_NODES) return;
    int g = batch[w];
    float4 v = *(const float4*)&g_H[w * FEAT + lane * 4];
    red_add_v4(&g_pool[g * FEAT + lane * 4], v);
    if (lane == 0) atomicAdd(&g_cnt[g], 1.0f);
}

__global__ void k_readout(float* __restrict__ out) {
    int g = blockIdx.x;
    int t = threadIdx.x;   // 128
    __shared__ float red[CLS][4];
    __shared__ float logits[CLS];

    float inv = 1.0f / fmaxf(g_cnt[g], 1.0f);
    float p = g_pool[g * FEAT + t] * inv;
    float e[8];
    expand8(p, e);

    float part[CLS];
#pragma unroll
    for (int c = 0; c < CLS; ++c) {
        const float* w = &g_Wr[c * KDIM + t * 8];
        float s = 0.0f;
#pragma unroll
        for (int j = 0; j < 8; ++j) s = fmaf(e[j], w[j], s);
        part[c] = s;
    }
    int lane = t & 31, wid = t >> 5;
#pragma unroll
    for (int c = 0; c < CLS; ++c) {
        float v = part[c];
#pragma unroll
        for (int o = 16; o > 0; o >>= 1) v += __shfl_down_sync(0xffffffffu, v, o);
        if (lane == 0) red[c][wid] = v;
    }
    __syncthreads();
    if (t < CLS) logits[t] = red[t][0] + red[t][1] + red[t][2] + red[t][3];
    __syncthreads();
    if (t == 0) {
        float m = -1e30f;
        for (int c = 0; c < CLS; ++c) m = fmaxf(m, logits[c]);
        float s = 0.0f;
        for (int c = 0; c < CLS; ++c) s += expf(logits[c] - m);
        float lse = m + logf(s);
        for (int c = 0; c < CLS; ++c) out[g * CLS + c] = logits[c] - lse;
    }
}

// ---------------- launch ----------------
extern "C" void kernel_launch(void* const* d_in, const int* in_sizes, int n_in,
                              void* d_out, int out_size) {
    const float* x     = (const float*)d_in[0];
    const int*   ei    = (const int*)d_in[1];
    const int*   batch = (const int*)d_in[2];
    float* out = (float*)d_out;

    cudaFuncSetAttribute(k_gemm_mma, cudaFuncAttributeMaxDynamicSharedMemorySize, SMEM_NEED);

    const int nscan = (N_NODES + 255) / 256;   // 196
    const int nprep = (3 * FEAT * FEAT + CLS * FEAT + 255) / 256;  // 198
    k_prep<<<(nprep > nscan ? nprep : nscan), 256>>>(
        (const float*)d_in[3],  (const float*)d_in[4],  (const float*)d_in[5],
        (const float*)d_in[7],  (const float*)d_in[8],  (const float*)d_in[9],
        (const float*)d_in[11], (const float*)d_in[12], (const float*)d_in[13],
        (const float*)d_in[15], (const float*)d_in[16], (const float*)d_in[17]);
    k_hist<<<(N_EDGES + 255) / 256, 256>>>(ei + N_EDGES);
    k_scan1<<<nscan, 256>>>();
    k_scan2<<<1, 256>>>(nscan);
    k_scan3<<<nscan, 256>>>();
    k_fill<<<(N_EDGES + 255) / 256, 256>>>(ei);

    const float* bb[3] = {(const float*)d_in[6], (const float*)d_in[10], (const float*)d_in[14]};
    int gemm_blocks = (N_NODES + 127) / 128;   // 391
    int aggr_blocks = (N_NODES * 32 + 255) / 256;
    for (int l = 0; l < 3; ++l) {
        k_gemm_mma<<<gemm_blocks, 256, SMEM_NEED>>>(x, l);
        k_aggr<<<aggr_blocks, 256>>>(bb[l]);
    }

    k_pool<<<(N_NODES * 32 + 255) / 256, 256>>>(batch);
    k_readout<<<NG, 128>>>(out);
}

// round 9
// speedup vs baseline: 3.0893x; 1.2634x over previous
#include <cuda_runtime.h>
#include <cuda_fp16.h>
#include <math.h>
#include <stdint.h>

#define N_NODES 50000
#define N_EDGES 800000
#define FEAT    128
#define CLS     10
#define NG      64
#define KDIM    1024

// ---------------- scratch ----------------
__device__ __align__(16) __half g_Wh[3][FEAT * KDIM];   // combined weights fp16 hi
__device__ __align__(16) __half g_Wl[3][FEAT * KDIM];   // combined weights fp16 lo
__device__ __align__(16) float g_Wr[CLS * KDIM];
__device__ int   g_degi[N_NODES];
__device__ float g_dinv[N_NODES];
__device__ int   g_rowptr[N_NODES + 1];
__device__ int   g_wofs[N_NODES];
__device__ int   g_srcs[N_EDGES];
__device__ int   g_blocksum[256];
__device__ __align__(16) float g_Y[N_NODES * FEAT];
__device__ __align__(16) float g_H[N_NODES * FEAT];
__device__ float g_pool[NG * FEAT];
__device__ float g_cnt[NG];

// ---------------- helpers ----------------
__device__ __forceinline__ uint32_t smem_u32(const void* p) {
    uint32_t a;
    asm("{ .reg .u64 t; cvta.to.shared.u64 t, %1; cvt.u32.u64 %0, t; }" : "=r"(a) : "l"(p));
    return a;
}
__device__ __forceinline__ void red_add_v4(float* addr, float4 v) {
    asm volatile("red.global.add.v4.f32 [%0], {%1, %2, %3, %4};"
                 :: "l"(addr), "f"(v.x), "f"(v.y), "f"(v.z), "f"(v.w) : "memory");
}
__device__ __forceinline__ void ldm_x4(uint32_t* r, uint32_t addr) {
    asm volatile("ldmatrix.sync.aligned.m8n8.x4.shared.b16 {%0,%1,%2,%3}, [%4];"
                 : "=r"(r[0]), "=r"(r[1]), "=r"(r[2]), "=r"(r[3]) : "r"(addr));
}
__device__ __forceinline__ void mma16816(float* c, const uint32_t* a, uint32_t b0, uint32_t b1) {
    asm volatile("mma.sync.aligned.m16n8k16.row.col.f32.f16.f16.f32 "
                 "{%0,%1,%2,%3}, {%4,%5,%6,%7}, {%8,%9}, {%0,%1,%2,%3};"
                 : "+f"(c[0]), "+f"(c[1]), "+f"(c[2]), "+f"(c[3])
                 : "r"(a[0]), "r"(a[1]), "r"(a[2]), "r"(a[3]), "r"(b0), "r"(b1));
}
__device__ __forceinline__ void cp_async16(uint32_t smem_dst, const void* gsrc) {
    asm volatile("cp.async.cg.shared.global [%0], [%1], 16;" :: "r"(smem_dst), "l"(gsrc) : "memory");
}
#define CP_COMMIT() asm volatile("cp.async.commit_group;" ::: "memory")
#define CP_WAIT1()  asm volatile("cp.async.wait_group 1;" ::: "memory")
#define CP_WAIT0()  asm volatile("cp.async.wait_group 0;" ::: "memory")

// closed-form expansion: [silu(x), B0..B6], uniform cubic B-spline, knots -2.5..2.5 step 0.5
__device__ __forceinline__ void expand8(float x, float* e) {
    e[0] = x / (1.0f + __expf(-x));
    float u  = (x + 2.5f) * 2.0f;
    float fj = floorf(u);
    int   ji = (int)fj;
    float t  = u - fj;
    float t2 = t * t, t3 = t2 * t;
    float v3 = t3 * (1.0f / 6.0f);
    float v2 = (1.0f / 6.0f) * (-3.0f * t3 + 3.0f * t2 + 3.0f * t + 1.0f);
    float v1 = (1.0f / 6.0f) * (3.0f * t3 - 6.0f * t2 + 4.0f);
    float omt = 1.0f - t;
    float v0 = (1.0f / 6.0f) * omt * omt * omt;
    if (!(u >= 0.0f && u < 10.0f)) { v0 = v1 = v2 = v3 = 0.0f; }
#pragma unroll
    for (int m = 0; m < 7; ++m) {
        int d = ji - m;
        float r = 0.0f;
        r = (d == 3) ? v0 : r;
        r = (d == 2) ? v1 : r;
        r = (d == 1) ? v2 : r;
        r = (d == 0) ? v3 : r;
        e[1 + m] = r;
    }
}
__device__ __forceinline__ uint32_t pack_h16x2(float a, float b) {
    __half2 t = __floats2half2_rn(a, b);
    return *(uint32_t*)&t;
}

// ---------------- fused setup ----------------
__global__ void k_prep(const float* __restrict__ bw0, const float* __restrict__ sw0, const float* __restrict__ ss0,
                       const float* __restrict__ bw1, const float* __restrict__ sw1, const float* __restrict__ ss1,
                       const float* __restrict__ bw2, const float* __restrict__ sw2, const float* __restrict__ ss2,
                       const float* __restrict__ bwr, const float* __restrict__ swr, const float* __restrict__ ssr) {
    int t = blockIdx.x * 256 + threadIdx.x;
    if (t < N_NODES)   g_degi[t] = 0;
    if (t < NG * FEAT) g_pool[t] = 0.0f;
    if (t < NG)        g_cnt[t]  = 0.0f;

    const int NW = FEAT * FEAT;
    if (t < 3 * NW + CLS * FEAT) {
        int which = t / NW;
        int i = t - which * NW;
        const float *bw, *sw, *ss;
        if      (which == 0) { bw = bw0; sw = sw0; ss = ss0; }
        else if (which == 1) { bw = bw1; sw = sw1; ss = ss1; }
        else if (which == 2) { bw = bw2; sw = sw2; ss = ss2; }
        else                 { bw = bwr; sw = swr; ss = ssr; }
        float v[8];
        v[0] = bw[i];
        float s = ss[i];
#pragma unroll
        for (int k = 0; k < 7; ++k) v[1 + k] = sw[i * 7 + k] * s;
        if (which < 3) {
            __half* wh = &g_Wh[which][i * 8];
            __half* wl = &g_Wl[which][i * 8];
#pragma unroll
            for (int j = 0; j < 8; ++j) {
                __half hi = __float2half_rn(v[j]);
                wh[j] = hi;
                wl[j] = __float2half_rn(v[j] - __half2float(hi));
            }
        } else {
            float* d = g_Wr + i * 8;
#pragma unroll
            for (int j = 0; j < 8; ++j) d[j] = v[j];
        }
    }
}
__global__ void k_hist(const int* __restrict__ dst) {
    int e = blockIdx.x * 256 + threadIdx.x;
    if (e < N_EDGES) atomicAdd(&g_degi[dst[e]], 1);
}
__global__ void k_scan1() {
    __shared__ int s[256];
    int i = blockIdx.x * 256 + threadIdx.x;
    int v = (i < N_NODES) ? g_degi[i] : 0;
    if (i < N_NODES) g_dinv[i] = rsqrtf((float)v + 1.0f);
    s[threadIdx.x] = v;
    __syncthreads();
    for (int o = 1; o < 256; o <<= 1) {
        int t = (threadIdx.x >= o) ? s[threadIdx.x - o] : 0;
        __syncthreads();
        s[threadIdx.x] += t;
        __syncthreads();
    }
    if (i < N_NODES) g_rowptr[i] = s[threadIdx.x] - v;
    if (threadIdx.x == 255) g_blocksum[blockIdx.x] = s[255];
}
__global__ void k_scan2(int nblocks) {
    __shared__ int s[256];
    int i = threadIdx.x;
    int v = (i < nblocks) ? g_blocksum[i] : 0;
    s[i] = v;
    __syncthreads();
    for (int o = 1; o < 256; o <<= 1) {
        int t = (i >= o) ? s[i - o] : 0;
        __syncthreads();
        s[i] += t;
        __syncthreads();
    }
    if (i < nblocks) g_blocksum[i] = s[i] - v;
}
__global__ void k_scan3() {
    int i = blockIdx.x * 256 + threadIdx.x;
    if (i < N_NODES) {
        int r = g_rowptr[i] + g_blocksum[blockIdx.x];
        g_rowptr[i] = r;
        g_wofs[i]   = r;
    }
    if (i == 0) g_rowptr[N_NODES] = N_EDGES;
}
__global__ void k_fill(const int* __restrict__ ei) {
    int e = blockIdx.x * 256 + threadIdx.x;
    if (e >= N_EDGES) return;
    int d = ei[N_EDGES + e];
    int pos = atomicAdd(&g_wofs[d], 1);
    g_srcs[pos] = ei[e];
}

// ---------------- pipelined HMMA fused KAN-linear GEMM (2-term fp16) ----------------
// A single fp16 (8KB/stage), B fp16 hi+lo (16KB/stage); 3 stages each -> 72KB, 2 CTAs/SM.
// D = Ah*Bh + Ah*Bl. 64B rows, XOR swizzle (row>>1)&3; one sync/chunk (mod-3 safe).
#define A_STAGE 8192
#define B_STAGE 16384
#define OFF_B   (3 * A_STAGE)
#define SMEM_NEED (OFF_B + 3 * B_STAGE)   // 73728

__global__ __launch_bounds__(256, 2) void k_gemm_mma(const float* __restrict__ x, int layer) {
    extern __shared__ __align__(16) char sm[];
    uint32_t sb = smem_u32(sm);

    const float* Hin = (layer == 0) ? x : g_H;
    const __half* Wh = g_Wh[layer];
    const __half* Wl = g_Wl[layer];

    const int tid = threadIdx.x, lane = tid & 31, wid = tid >> 5;
    const int row0 = blockIdx.x * 128;
    const int m0w = (wid >> 1) * 32;
    const int n0w = (wid & 1) * 64;

    const int hn0 = tid >> 2;
    const int hn1 = 64 + (tid >> 2);
    const int hdd = tid & 3;
    const bool hok0 = (row0 + hn0) < N_NODES;
    const bool hok1 = (row0 + hn1) < N_NODES;

    float hv[2][2];
    hv[0][0] = hok0 ? Hin[(row0 + hn0) * FEAT + hdd]     : 0.0f;
    hv[0][1] = hok1 ? Hin[(row0 + hn1) * FEAT + hdd]     : 0.0f;
    hv[1][0] = hok0 ? Hin[(row0 + hn0) * FEAT + 4 + hdd] : 0.0f;
    hv[1][1] = hok1 ? Hin[(row0 + hn1) * FEAT + 4 + hdd] : 0.0f;

    // prefetch B(0) into stage 0
    {
#pragma unroll
        for (int q = 0; q < 2; ++q) {
            int idx = q * 256 + tid;
            int o = idx >> 2, s = idx & 3;
            uint32_t off = (uint32_t)o * 64 + (uint32_t)((s ^ ((o >> 1) & 3)) * 16);
            cp_async16(sb + OFF_B + off,        Wh + o * KDIM + s * 8);
            cp_async16(sb + OFF_B + 8192 + off, Wl + o * KDIM + s * 8);
        }
        CP_COMMIT();
    }

    // produce A(0) into stage 0
    {
        char* bufA = sm;
#pragma unroll
        for (int q = 0; q < 2; ++q) {
            int n  = (q == 0) ? hn0 : hn1;
            float e[8];
            expand8(hv[0][q], e);
            uint32_t h[4];
#pragma unroll
            for (int j = 0; j < 4; ++j) h[j] = pack_h16x2(e[2 * j], e[2 * j + 1]);
            uint32_t off = (uint32_t)n * 64 + (uint32_t)((hdd ^ ((n >> 1) & 3)) * 16);
            *(uint4*)(bufA + off) = make_uint4(h[0], h[1], h[2], h[3]);
        }
    }

    float acc[2][8][4];
#pragma unroll
    for (int i = 0; i < 2; ++i)
#pragma unroll
        for (int j = 0; j < 8; ++j)
#pragma unroll
            for (int k = 0; k < 4; ++k) acc[i][j][k] = 0.0f;

    int stage_next = 1;
    for (int c = 0; c < 32; ++c) {
        if (c + 1 < 32) {
            uint32_t bst = sb + OFF_B + stage_next * B_STAGE;
#pragma unroll
            for (int q = 0; q < 2; ++q) {
                int idx = q * 256 + tid;
                int o = idx >> 2, s = idx & 3;
                uint32_t off = (uint32_t)o * 64 + (uint32_t)((s ^ ((o >> 1) & 3)) * 16);
                cp_async16(bst + off,        Wh + o * KDIM + (c + 1) * 32 + s * 8);
                cp_async16(bst + 8192 + off, Wl + o * KDIM + (c + 1) * 32 + s * 8);
            }
            CP_COMMIT();
        }
        if (c + 2 < 32) {
            hv[c & 1][0] = hok0 ? Hin[(row0 + hn0) * FEAT + (c + 2) * 4 + hdd] : 0.0f;
            hv[c & 1][1] = hok1 ? Hin[(row0 + hn1) * FEAT + (c + 2) * 4 + hdd] : 0.0f;
        }
        if (c + 1 < 32) {
            char* bufA = sm + stage_next * A_STAGE;
            const float* hvc = hv[(c + 1) & 1];
#pragma unroll
            for (int q = 0; q < 2; ++q) {
                int n  = (q == 0) ? hn0 : hn1;
                float e[8];
                expand8(hvc[q], e);
                uint32_t h[4];
#pragma unroll
                for (int j = 0; j < 4; ++j) h[j] = pack_h16x2(e[2 * j], e[2 * j + 1]);
                uint32_t off = (uint32_t)n * 64 + (uint32_t)((hdd ^ ((n >> 1) & 3)) * 16);
                *(uint4*)(bufA + off) = make_uint4(h[0], h[1], h[2], h[3]);
            }
        }
        if (c == 31) { CP_WAIT0(); } else { CP_WAIT1(); }
        __syncthreads();

        const int ast = (stage_next + 2) % 3;
        const uint32_t abase = sb + ast * A_STAGE;
        const uint32_t bbase = sb + OFF_B + ast * B_STAGE;
#pragma unroll
        for (int kk = 0; kk < 2; ++kk) {
            uint32_t ah[2][4];
#pragma unroll
            for (int mt = 0; mt < 2; ++mt) {
                int m = m0w + mt * 16 + (lane & 15);
                uint32_t u = (uint32_t)((2 * kk + (lane >> 4)) ^ ((m >> 1) & 3));
                ldm_x4(ah[mt], abase + (uint32_t)m * 64 + u * 16);
            }
            uint32_t bh[4][4], bl[4][4];
#pragma unroll
            for (int ng = 0; ng < 4; ++ng) {
                int n = n0w + ng * 16 + ((lane >> 4) << 3) + (lane & 7);
                uint32_t u = (uint32_t)((2 * kk + ((lane >> 3) & 1)) ^ ((n >> 1) & 3));
                uint32_t off = (uint32_t)n * 64 + u * 16;
                ldm_x4(bh[ng], bbase + off);
                ldm_x4(bl[ng], bbase + 8192 + off);
            }
#pragma unroll
            for (int mt = 0; mt < 2; ++mt)
#pragma unroll
                for (int ng = 0; ng < 4; ++ng)
#pragma unroll
                    for (int hf = 0; hf < 2; ++hf) {
                        float* cc = acc[mt][ng * 2 + hf];
                        mma16816(cc, ah[mt], bh[ng][hf * 2], bh[ng][hf * 2 + 1]);
                        mma16816(cc, ah[mt], bl[ng][hf * 2], bl[ng][hf * 2 + 1]);
                    }
        }
        stage_next = (stage_next + 1) % 3;
    }

    // epilogue
#pragma unroll
    for (int mt = 0; mt < 2; ++mt) {
        int r1 = row0 + m0w + mt * 16 + (lane >> 2);
        int r2 = r1 + 8;
        bool ok1 = r1 < N_NODES, ok2 = r2 < N_NODES;
        int cb = n0w + (lane & 3) * 2;
#pragma unroll
        for (int nt = 0; nt < 8; ++nt) {
            int col = cb + nt * 8;
            float* a = acc[mt][nt];
            if (ok1) *(float2*)&g_Y[r1 * FEAT + col] = make_float2(a[0], a[1]);
            if (ok2) *(float2*)&g_Y[r2 * FEAT + col] = make_float2(a[2], a[3]);
        }
    }
}

// ---------------- fused CSR aggregation + bias + silu (+ optional pooling) ----------------
__global__ __launch_bounds__(256) void k_aggr(const float* __restrict__ bias,
                                              const int* __restrict__ batch) {
    int w = (blockIdx.x * 256 + threadIdx.x) >> 5;
    int lane = threadIdx.x & 31;
    if (w >= N_NODES) return;
    float dd = g_dinv[w];
    float dd2 = dd * dd;
    float4 a = *(const float4*)&g_Y[w * FEAT + lane * 4];
    a.x *= dd2; a.y *= dd2; a.z *= dd2; a.w *= dd2;

    int e = g_rowptr[w], end = g_rowptr[w + 1];
    for (; e + 2 <= end; e += 2) {
        int s0 = g_srcs[e], s1 = g_srcs[e + 1];
        float nm0 = g_dinv[s0] * dd, nm1 = g_dinv[s1] * dd;
        float4 v0 = *(const float4*)&g_Y[s0 * FEAT + lane * 4];
        float4 v1 = *(const float4*)&g_Y[s1 * FEAT + lane * 4];
        a.x += v0.x * nm0 + v1.x * nm1;
        a.y += v0.y * nm0 + v1.y * nm1;
        a.z += v0.z * nm0 + v1.z * nm1;
        a.w += v0.w * nm0 + v1.w * nm1;
    }
    if (e < end) {
        int s0 = g_srcs[e];
        float nm0 = g_dinv[s0] * dd;
        float4 v0 = *(const float4*)&g_Y[s0 * FEAT + lane * 4];
        a.x += v0.x * nm0; a.y += v0.y * nm0; a.z += v0.z * nm0; a.w += v0.w * nm0;
    }
    float4 bv = *(const float4*)&bias[lane * 4];
    a.x += bv.x; a.y += bv.y; a.z += bv.z; a.w += bv.w;
    a.x = a.x / (1.0f + __expf(-a.x));
    a.y = a.y / (1.0f + __expf(-a.y));
    a.z = a.z / (1.0f + __expf(-a.z));
    a.w = a.w / (1.0f + __expf(-a.w));
    if (batch == nullptr) {
        *(float4*)&g_H[w * FEAT + lane * 4] = a;
    } else {
        int g = batch[w];
        red_add_v4(&g_pool[g * FEAT + lane * 4], a);
        if (lane == 0) atomicAdd(&g_cnt[g], 1.0f);
    }
}

// ---------------- readout ----------------
__global__ void k_readout(float* __restrict__ out) {
    int g = blockIdx.x;
    int t = threadIdx.x;   // 128
    __shared__ float red[CLS][4];
    __shared__ float logits[CLS];

    float inv = 1.0f / fmaxf(g_cnt[g], 1.0f);
    float p = g_pool[g * FEAT + t] * inv;
    float e[8];
    expand8(p, e);

    float part[CLS];
#pragma unroll
    for (int c = 0; c < CLS; ++c) {
        const float* w = &g_Wr[c * KDIM + t * 8];
        float s = 0.0f;
#pragma unroll
        for (int j = 0; j < 8; ++j) s = fmaf(e[j], w[j], s);
        part[c] = s;
    }
    int lane = t & 31, wid = t >> 5;
#pragma unroll
    for (int c = 0; c < CLS; ++c) {
        float v = part[c];
#pragma unroll
        for (int o = 16; o > 0; o >>= 1) v += __shfl_down_sync(0xffffffffu, v, o);
        if (lane == 0) red[c][wid] = v;
    }
    __syncthreads();
    if (t < CLS) logits[t] = red[t][0] + red[t][1] + red[t][2] + red[t][3];
    __syncthreads();
    if (t == 0) {
        float m = -1e30f;
        for (int c = 0; c < CLS; ++c) m = fmaxf(m, logits[c]);
        float s = 0.0f;
        for (int c = 0; c < CLS; ++c) s += expf(logits[c] - m);
        float lse = m + logf(s);
        for (int c = 0; c < CLS; ++c) out[g * CLS + c] = logits[c] - lse;
    }
}

// ---------------- launch ----------------
extern "C" void kernel_launch(void* const* d_in, const int* in_sizes, int n_in,
                              void* d_out, int out_size) {
    const float* x     = (const float*)d_in[0];
    const int*   ei    = (const int*)d_in[1];
    const int*   batch = (const int*)d_in[2];
    float* out = (float*)d_out;

    cudaFuncSetAttribute(k_gemm_mma, cudaFuncAttributeMaxDynamicSharedMemorySize, SMEM_NEED);

    const int nscan = (N_NODES + 255) / 256;   // 196
    const int nprep = (3 * FEAT * FEAT + CLS * FEAT + 255) / 256;  // 198
    k_prep<<<(nprep > nscan ? nprep : nscan), 256>>>(
        (const float*)d_in[3],  (const float*)d_in[4],  (const float*)d_in[5],
        (const float*)d_in[7],  (const float*)d_in[8],  (const float*)d_in[9],
        (const float*)d_in[11], (const float*)d_in[12], (const float*)d_in[13],
        (const float*)d_in[15], (const float*)d_in[16], (const float*)d_in[17]);
    k_hist<<<(N_EDGES + 255) / 256, 256>>>(ei + N_EDGES);
    k_scan1<<<nscan, 256>>>();
    k_scan2<<<1, 256>>>(nscan);
    k_scan3<<<nscan, 256>>>();
    k_fill<<<(N_EDGES + 255) / 256, 256>>>(ei);

    const float* bb[3] = {(const float*)d_in[6], (const float*)d_in[10], (const float*)d_in[14]};
    int gemm_blocks = (N_NODES + 127) / 128;   // 391
    int aggr_blocks = (N_NODES * 32 + 255) / 256;
    for (int l = 0; l < 3; ++l) {
        k_gemm_mma<<<gemm_blocks, 256, SMEM_NEED>>>(x, l);
        k_aggr<<<aggr_blocks, 256>>>(bb[l], (l == 2) ? batch : nullptr);
    }

    k_readout<<<NG, 128>>>(out);
}

// round 10
// speedup vs baseline: 3.7286x; 1.2069x over previous
#include <cuda_runtime.h>
#include <cuda_fp16.h>
#include <math.h>
#include <stdint.h>

#define N_NODES 50000
#define N_EDGES 800000
#define FEAT    128
#define CLS     10
#define NG      64
#define KDIM    1024

// ---------------- scratch ----------------
__device__ __align__(16) __half g_Wh[3][FEAT * KDIM];   // combined weights fp16
__device__ __align__(16) float g_Wr[CLS * KDIM];
__device__ int   g_degi[N_NODES];
__device__ float g_dinv[N_NODES];
__device__ int   g_rowptr[N_NODES + 1];
__device__ int   g_wofs[N_NODES];
__device__ int   g_srcs[N_EDGES];
__device__ int   g_blocksum[256];
__device__ __align__(16) __half g_Yh[N_NODES * FEAT];   // KAN linear output (fp16)
__device__ __align__(16) float g_H[N_NODES * FEAT];
__device__ float g_pool[NG * FEAT];
__device__ float g_cnt[NG];

// ---------------- helpers ----------------
__device__ __forceinline__ uint32_t smem_u32(const void* p) {
    uint32_t a;
    asm("{ .reg .u64 t; cvta.to.shared.u64 t, %1; cvt.u32.u64 %0, t; }" : "=r"(a) : "l"(p));
    return a;
}
__device__ __forceinline__ void red_add_v4(float* addr, float4 v) {
    asm volatile("red.global.add.v4.f32 [%0], {%1, %2, %3, %4};"
                 :: "l"(addr), "f"(v.x), "f"(v.y), "f"(v.z), "f"(v.w) : "memory");
}
__device__ __forceinline__ void ldm_x4(uint32_t* r, uint32_t addr) {
    asm volatile("ldmatrix.sync.aligned.m8n8.x4.shared.b16 {%0,%1,%2,%3}, [%4];"
                 : "=r"(r[0]), "=r"(r[1]), "=r"(r[2]), "=r"(r[3]) : "r"(addr));
}
__device__ __forceinline__ void mma16816(float* c, const uint32_t* a, uint32_t b0, uint32_t b1) {
    asm volatile("mma.sync.aligned.m16n8k16.row.col.f32.f16.f16.f32 "
                 "{%0,%1,%2,%3}, {%4,%5,%6,%7}, {%8,%9}, {%0,%1,%2,%3};"
                 : "+f"(c[0]), "+f"(c[1]), "+f"(c[2]), "+f"(c[3])
                 : "r"(a[0]), "r"(a[1]), "r"(a[2]), "r"(a[3]), "r"(b0), "r"(b1));
}
__device__ __forceinline__ void cp_async16(uint32_t smem_dst, const void* gsrc) {
    asm volatile("cp.async.cg.shared.global [%0], [%1], 16;" :: "r"(smem_dst), "l"(gsrc) : "memory");
}
#define CP_COMMIT() asm volatile("cp.async.commit_group;" ::: "memory")
#define CP_WAIT1()  asm volatile("cp.async.wait_group 1;" ::: "memory")
#define CP_WAIT0()  asm volatile("cp.async.wait_group 0;" ::: "memory")

// closed-form expansion: [silu(x), B0..B6], uniform cubic B-spline, knots -2.5..2.5 step 0.5
__device__ __forceinline__ void expand8(float x, float* e) {
    e[0] = x / (1.0f + __expf(-x));
    float u  = (x + 2.5f) * 2.0f;
    float fj = floorf(u);
    int   ji = (int)fj;
    float t  = u - fj;
    float t2 = t * t, t3 = t2 * t;
    float v3 = t3 * (1.0f / 6.0f);
    float v2 = (1.0f / 6.0f) * (-3.0f * t3 + 3.0f * t2 + 3.0f * t + 1.0f);
    float v1 = (1.0f / 6.0f) * (3.0f * t3 - 6.0f * t2 + 4.0f);
    float omt = 1.0f - t;
    float v0 = (1.0f / 6.0f) * omt * omt * omt;
    if (!(u >= 0.0f && u < 10.0f)) { v0 = v1 = v2 = v3 = 0.0f; }
#pragma unroll
    for (int m = 0; m < 7; ++m) {
        int d = ji - m;
        float r = 0.0f;
        r = (d == 3) ? v0 : r;
        r = (d == 2) ? v1 : r;
        r = (d == 1) ? v2 : r;
        r = (d == 0) ? v3 : r;
        e[1 + m] = r;
    }
}
__device__ __forceinline__ uint32_t pack_h16x2(float a, float b) {
    __half2 t = __floats2half2_rn(a, b);
    return *(uint32_t*)&t;
}

// ---------------- fused setup ----------------
__global__ void k_prep(const float* __restrict__ bw0, const float* __restrict__ sw0, const float* __restrict__ ss0,
                       const float* __restrict__ bw1, const float* __restrict__ sw1, const float* __restrict__ ss1,
                       const float* __restrict__ bw2, const float* __restrict__ sw2, const float* __restrict__ ss2,
                       const float* __restrict__ bwr, const float* __restrict__ swr, const float* __restrict__ ssr) {
    int t = blockIdx.x * 256 + threadIdx.x;
    if (t < N_NODES)   g_degi[t] = 0;
    if (t < NG * FEAT) g_pool[t] = 0.0f;
    if (t < NG)        g_cnt[t]  = 0.0f;

    const int NW = FEAT * FEAT;
    if (t < 3 * NW + CLS * FEAT) {
        int which = t / NW;
        int i = t - which * NW;
        const float *bw, *sw, *ss;
        if      (which == 0) { bw = bw0; sw = sw0; ss = ss0; }
        else if (which == 1) { bw = bw1; sw = sw1; ss = ss1; }
        else if (which == 2) { bw = bw2; sw = sw2; ss = ss2; }
        else                 { bw = bwr; sw = swr; ss = ssr; }
        float v[8];
        v[0] = bw[i];
        float s = ss[i];
#pragma unroll
        for (int k = 0; k < 7; ++k) v[1 + k] = sw[i * 7 + k] * s;
        if (which < 3) {
            __half* wh = &g_Wh[which][i * 8];
#pragma unroll
            for (int j = 0; j < 8; ++j) wh[j] = __float2half_rn(v[j]);
        } else {
            float* d = g_Wr + i * 8;
#pragma unroll
            for (int j = 0; j < 8; ++j) d[j] = v[j];
        }
    }
}
__global__ void k_hist(const int* __restrict__ dst) {
    int e = blockIdx.x * 256 + threadIdx.x;
    if (e < N_EDGES) atomicAdd(&g_degi[dst[e]], 1);
}
__global__ void k_scan1() {
    __shared__ int s[256];
    int i = blockIdx.x * 256 + threadIdx.x;
    int v = (i < N_NODES) ? g_degi[i] : 0;
    if (i < N_NODES) g_dinv[i] = rsqrtf((float)v + 1.0f);
    s[threadIdx.x] = v;
    __syncthreads();
    for (int o = 1; o < 256; o <<= 1) {
        int t = (threadIdx.x >= o) ? s[threadIdx.x - o] : 0;
        __syncthreads();
        s[threadIdx.x] += t;
        __syncthreads();
    }
    if (i < N_NODES) g_rowptr[i] = s[threadIdx.x] - v;
    if (threadIdx.x == 255) g_blocksum[blockIdx.x] = s[255];
}
__global__ void k_scan2(int nblocks) {
    __shared__ int s[256];
    int i = threadIdx.x;
    int v = (i < nblocks) ? g_blocksum[i] : 0;
    s[i] = v;
    __syncthreads();
    for (int o = 1; o < 256; o <<= 1) {
        int t = (i >= o) ? s[i - o] : 0;
        __syncthreads();
        s[i] += t;
        __syncthreads();
    }
    if (i < nblocks) g_blocksum[i] = s[i] - v;
}
__global__ void k_scan3() {
    int i = blockIdx.x * 256 + threadIdx.x;
    if (i < N_NODES) {
        int r = g_rowptr[i] + g_blocksum[blockIdx.x];
        g_rowptr[i] = r;
        g_wofs[i]   = r;
    }
    if (i == 0) g_rowptr[N_NODES] = N_EDGES;
}
__global__ void k_fill(const int* __restrict__ ei) {
    int e = blockIdx.x * 256 + threadIdx.x;
    if (e >= N_EDGES) return;
    int d = ei[N_EDGES + e];
    int pos = atomicAdd(&g_wofs[d], 1);
    g_srcs[pos] = ei[e];
}

// ---------------- pipelined HMMA fused KAN-linear GEMM (single fp16) ----------------
// A fp16 (8KB/stage), B fp16 (8KB/stage); 3 stages each -> 48KB, 2 CTAs/SM.
// 64B rows, XOR swizzle (row>>1)&3; one sync/chunk (mod-3 safe).
#define A_STAGE 8192
#define B_STAGE 8192
#define OFF_B   (3 * A_STAGE)
#define SMEM_NEED (OFF_B + 3 * B_STAGE)   // 49152

__global__ __launch_bounds__(256, 2) void k_gemm_mma(const float* __restrict__ x, int layer) {
    extern __shared__ __align__(16) char sm[];
    uint32_t sb = smem_u32(sm);

    const float* Hin = (layer == 0) ? x : g_H;
    const __half* Wh = g_Wh[layer];

    const int tid = threadIdx.x, lane = tid & 31, wid = tid >> 5;
    const int row0 = blockIdx.x * 128;
    const int m0w = (wid >> 1) * 32;
    const int n0w = (wid & 1) * 64;

    const int hn0 = tid >> 2;
    const int hn1 = 64 + (tid >> 2);
    const int hdd = tid & 3;
    const bool hok0 = (row0 + hn0) < N_NODES;
    const bool hok1 = (row0 + hn1) < N_NODES;

    float hv[2][2];
    hv[0][0] = hok0 ? Hin[(row0 + hn0) * FEAT + hdd]     : 0.0f;
    hv[0][1] = hok1 ? Hin[(row0 + hn1) * FEAT + hdd]     : 0.0f;
    hv[1][0] = hok0 ? Hin[(row0 + hn0) * FEAT + 4 + hdd] : 0.0f;
    hv[1][1] = hok1 ? Hin[(row0 + hn1) * FEAT + 4 + hdd] : 0.0f;

    // prefetch B(0) into stage 0
    {
#pragma unroll
        for (int q = 0; q < 2; ++q) {
            int idx = q * 256 + tid;
            int o = idx >> 2, s = idx & 3;
            uint32_t off = (uint32_t)o * 64 + (uint32_t)((s ^ ((o >> 1) & 3)) * 16);
            cp_async16(sb + OFF_B + off, Wh + o * KDIM + s * 8);
        }
        CP_COMMIT();
    }

    // produce A(0) into stage 0
    {
        char* bufA = sm;
#pragma unroll
        for (int q = 0; q < 2; ++q) {
            int n  = (q == 0) ? hn0 : hn1;
            float e[8];
            expand8(hv[0][q], e);
            uint32_t h[4];
#pragma unroll
            for (int j = 0; j < 4; ++j) h[j] = pack_h16x2(e[2 * j], e[2 * j + 1]);
            uint32_t off = (uint32_t)n * 64 + (uint32_t)((hdd ^ ((n >> 1) & 3)) * 16);
            *(uint4*)(bufA + off) = make_uint4(h[0], h[1], h[2], h[3]);
        }
    }

    float acc[2][8][4];
#pragma unroll
    for (int i = 0; i < 2; ++i)
#pragma unroll
        for (int j = 0; j < 8; ++j)
#pragma unroll
            for (int k = 0; k < 4; ++k) acc[i][j][k] = 0.0f;

    int stage_next = 1;
    for (int c = 0; c < 32; ++c) {
        if (c + 1 < 32) {
            uint32_t bst = sb + OFF_B + stage_next * B_STAGE;
#pragma unroll
            for (int q = 0; q < 2; ++q) {
                int idx = q * 256 + tid;
                int o = idx >> 2, s = idx & 3;
                uint32_t off = (uint32_t)o * 64 + (uint32_t)((s ^ ((o >> 1) & 3)) * 16);
                cp_async16(bst + off, Wh + o * KDIM + (c + 1) * 32 + s * 8);
            }
            CP_COMMIT();
        }
        if (c + 2 < 32) {
            hv[c & 1][0] = hok0 ? Hin[(row0 + hn0) * FEAT + (c + 2) * 4 + hdd] : 0.0f;
            hv[c & 1][1] = hok1 ? Hin[(row0 + hn1) * FEAT + (c + 2) * 4 + hdd] : 0.0f;
        }
        if (c + 1 < 32) {
            char* bufA = sm + stage_next * A_STAGE;
            const float* hvc = hv[(c + 1) & 1];
#pragma unroll
            for (int q = 0; q < 2; ++q) {
                int n  = (q == 0) ? hn0 : hn1;
                float e[8];
                expand8(hvc[q], e);
                uint32_t h[4];
#pragma unroll
                for (int j = 0; j < 4; ++j) h[j] = pack_h16x2(e[2 * j], e[2 * j + 1]);
                uint32_t off = (uint32_t)n * 64 + (uint32_t)((hdd ^ ((n >> 1) & 3)) * 16);
                *(uint4*)(bufA + off) = make_uint4(h[0], h[1], h[2], h[3]);
            }
        }
        if (c == 31) { CP_WAIT0(); } else { CP_WAIT1(); }
        __syncthreads();

        const int ast = (stage_next + 2) % 3;
        const uint32_t abase = sb + ast * A_STAGE;
        const uint32_t bbase = sb + OFF_B + ast * B_STAGE;
#pragma unroll
        for (int kk = 0; kk < 2; ++kk) {
            uint32_t ah[2][4];
#pragma unroll
            for (int mt = 0; mt < 2; ++mt) {
                int m = m0w + mt * 16 + (lane & 15);
                uint32_t u = (uint32_t)((2 * kk + (lane >> 4)) ^ ((m >> 1) & 3));
                ldm_x4(ah[mt], abase + (uint32_t)m * 64 + u * 16);
            }
            uint32_t bh[4][4];
#pragma unroll
            for (int ng = 0; ng < 4; ++ng) {
                int n = n0w + ng * 16 + ((lane >> 4) << 3) + (lane & 7);
                uint32_t u = (uint32_t)((2 * kk + ((lane >> 3) & 1)) ^ ((n >> 1) & 3));
                ldm_x4(bh[ng], bbase + (uint32_t)n * 64 + u * 16);
            }
#pragma unroll
            for (int mt = 0; mt < 2; ++mt)
#pragma unroll
                for (int ng = 0; ng < 4; ++ng)
#pragma unroll
                    for (int hf = 0; hf < 2; ++hf)
                        mma16816(acc[mt][ng * 2 + hf], ah[mt], bh[ng][hf * 2], bh[ng][hf * 2 + 1]);
        }
        stage_next = (stage_next + 1) % 3;
    }

    // epilogue: write Y as fp16
#pragma unroll
    for (int mt = 0; mt < 2; ++mt) {
        int r1 = row0 + m0w + mt * 16 + (lane >> 2);
        int r2 = r1 + 8;
        bool ok1 = r1 < N_NODES, ok2 = r2 < N_NODES;
        int cb = n0w + (lane & 3) * 2;
#pragma unroll
        for (int nt = 0; nt < 8; ++nt) {
            int col = cb + nt * 8;
            float* a = acc[mt][nt];
            if (ok1) *(__half2*)&g_Yh[r1 * FEAT + col] = __floats2half2_rn(a[0], a[1]);
            if (ok2) *(__half2*)&g_Yh[r2 * FEAT + col] = __floats2half2_rn(a[2], a[3]);
        }
    }
}

// ---------------- fused CSR aggregation + bias + silu (+ optional pooling) ----------------
__device__ __forceinline__ float4 ld_y4(int node, int lane) {
    uint2 u = *(const uint2*)&g_Yh[node * FEAT + lane * 4];
    float2 p0 = __half22float2(*(__half2*)&u.x);
    float2 p1 = __half22float2(*(__half2*)&u.y);
    return make_float4(p0.x, p0.y, p1.x, p1.y);
}

__global__ __launch_bounds__(256) void k_aggr(const float* __restrict__ bias,
                                              const int* __restrict__ batch) {
    int w = (blockIdx.x * 256 + threadIdx.x) >> 5;
    int lane = threadIdx.x & 31;
    if (w >= N_NODES) return;
    float dd = g_dinv[w];
    float dd2 = dd * dd;
    float4 a = ld_y4(w, lane);
    a.x *= dd2; a.y *= dd2; a.z *= dd2; a.w *= dd2;

    int e = g_rowptr[w], end = g_rowptr[w + 1];
    for (; e + 2 <= end; e += 2) {
        int s0 = g_srcs[e], s1 = g_srcs[e + 1];
        float nm0 = g_dinv[s0] * dd, nm1 = g_dinv[s1] * dd;
        float4 v0 = ld_y4(s0, lane);
        float4 v1 = ld_y4(s1, lane);
        a.x += v0.x * nm0 + v1.x * nm1;
        a.y += v0.y * nm0 + v1.y * nm1;
        a.z += v0.z * nm0 + v1.z * nm1;
        a.w += v0.w * nm0 + v1.w * nm1;
    }
    if (e < end) {
        int s0 = g_srcs[e];
        float nm0 = g_dinv[s0] * dd;
        float4 v0 = ld_y4(s0, lane);
        a.x += v0.x * nm0; a.y += v0.y * nm0; a.z += v0.z * nm0; a.w += v0.w * nm0;
    }
    float4 bv = *(const float4*)&bias[lane * 4];
    a.x += bv.x; a.y += bv.y; a.z += bv.z; a.w += bv.w;
    a.x = a.x / (1.0f + __expf(-a.x));
    a.y = a.y / (1.0f + __expf(-a.y));
    a.z = a.z / (1.0f + __expf(-a.z));
    a.w = a.w / (1.0f + __expf(-a.w));
    if (batch == nullptr) {
        *(float4*)&g_H[w * FEAT + lane * 4] = a;
    } else {
        int g = batch[w];
        red_add_v4(&g_pool[g * FEAT + lane * 4], a);
        if (lane == 0) atomicAdd(&g_cnt[g], 1.0f);
    }
}

// ---------------- readout ----------------
__global__ void k_readout(float* __restrict__ out) {
    int g = blockIdx.x;
    int t = threadIdx.x;   // 128
    __shared__ float red[CLS][4];
    __shared__ float logits[CLS];

    float inv = 1.0f / fmaxf(g_cnt[g], 1.0f);
    float p = g_pool[g * FEAT + t] * inv;
    float e[8];
    expand8(p, e);

    float part[CLS];
#pragma unroll
    for (int c = 0; c < CLS; ++c) {
        const float* w = &g_Wr[c * KDIM + t * 8];
        float s = 0.0f;
#pragma unroll
        for (int j = 0; j < 8; ++j) s = fmaf(e[j], w[j], s);
        part[c] = s;
    }
    int lane = t & 31, wid = t >> 5;
#pragma unroll
    for (int c = 0; c < CLS; ++c) {
        float v = part[c];
#pragma unroll
        for (int o = 16; o > 0; o >>= 1) v += __shfl_down_sync(0xffffffffu, v, o);
        if (lane == 0) red[c][wid] = v;
    }
    __syncthreads();
    if (t < CLS) logits[t] = red[t][0] + red[t][1] + red[t][2] + red[t][3];
    __syncthreads();
    if (t == 0) {
        float m = -1e30f;
        for (int c = 0; c < CLS; ++c) m = fmaxf(m, logits[c]);
        float s = 0.0f;
        for (int c = 0; c < CLS; ++c) s += expf(logits[c] - m);
        float lse = m + logf(s);
        for (int c = 0; c < CLS; ++c) out[g * CLS + c] = logits[c] - lse;
    }
}

// ---------------- launch ----------------
extern "C" void kernel_launch(void* const* d_in, const int* in_sizes, int n_in,
                              void* d_out, int out_size) {
    const float* x     = (const float*)d_in[0];
    const int*   ei    = (const int*)d_in[1];
    const int*   batch = (const int*)d_in[2];
    float* out = (float*)d_out;

    cudaFuncSetAttribute(k_gemm_mma, cudaFuncAttributeMaxDynamicSharedMemorySize, SMEM_NEED);

    const int nscan = (N_NODES + 255) / 256;   // 196
    const int nprep = (3 * FEAT * FEAT + CLS * FEAT + 255) / 256;  // 198
    k_prep<<<(nprep > nscan ? nprep : nscan), 256>>>(
        (const float*)d_in[3],  (const float*)d_in[4],  (const float*)d_in[5],
        (const float*)d_in[7],  (const float*)d_in[8],  (const float*)d_in[9],
        (const float*)d_in[11], (const float*)d_in[12], (const float*)d_in[13],
        (const float*)d_in[15], (const float*)d_in[16], (const float*)d_in[17]);
    k_hist<<<(N_EDGES + 255) / 256, 256>>>(ei + N_EDGES);
    k_scan1<<<nscan, 256>>>();
    k_scan2<<<1, 256>>>(nscan);
    k_scan3<<<nscan, 256>>>();
    k_fill<<<(N_EDGES + 255) / 256, 256>>>(ei);

    const float* bb[3] = {(const float*)d_in[6], (const float*)d_in[10], (const float*)d_in[14]};
    int gemm_blocks = (N_NODES + 127) / 128;   // 391
    int aggr_blocks = (N_NODES * 32 + 255) / 256;
    for (int l = 0; l < 3; ++l) {
        k_gemm_mma<<<gemm_blocks, 256, SMEM_NEED>>>(x, l);
        k_aggr<<<aggr_blocks, 256>>>(bb[l], (l == 2) ? batch : nullptr);
    }

    k_readout<<<NG, 128>>>(out);
}

// round 12
// speedup vs baseline: 3.8665x; 1.0370x over previous
#include <cuda_runtime.h>
#include <cuda_fp16.h>
#include <math.h>
#include <stdint.h>

#define N_NODES 50000
#define N_EDGES 800000
#define FEAT    128
#define CLS     10
#define NG      64
#define KDIM    1024

// ---------------- scratch ----------------
__device__ __align__(16) __half g_Wh[3][FEAT * KDIM];   // combined weights fp16
__device__ __align__(16) float g_Wr[CLS * KDIM];
__device__ int   g_degi[N_NODES];
__device__ float g_dinv[N_NODES];
__device__ int   g_rowptr[N_NODES + 1];
__device__ int   g_wofs[N_NODES];
__device__ int   g_srcs[N_EDGES];
__device__ int   g_blocksum[256];
__device__ __align__(16) __half g_Yh[N_NODES * FEAT];   // KAN linear output (fp16)
__device__ __align__(16) float g_H[N_NODES * FEAT];
__device__ float g_pool[NG * FEAT];
__device__ float g_cnt[NG];

// ---------------- helpers ----------------
__device__ __forceinline__ uint32_t smem_u32(const void* p) {
    uint32_t a;
    asm("{ .reg .u64 t; cvta.to.shared.u64 t, %1; cvt.u32.u64 %0, t; }" : "=r"(a) : "l"(p));
    return a;
}
__device__ __forceinline__ void red_add_v4(float* addr, float4 v) {
    asm volatile("red.global.add.v4.f32 [%0], {%1, %2, %3, %4};"
                 :: "l"(addr), "f"(v.x), "f"(v.y), "f"(v.z), "f"(v.w) : "memory");
}
__device__ __forceinline__ void ldm_x4(uint32_t* r, uint32_t addr) {
    asm volatile("ldmatrix.sync.aligned.m8n8.x4.shared.b16 {%0,%1,%2,%3}, [%4];"
                 : "=r"(r[0]), "=r"(r[1]), "=r"(r[2]), "=r"(r[3]) : "r"(addr));
}
__device__ __forceinline__ void mma16816(float* c, const uint32_t* a, uint32_t b0, uint32_t b1) {
    asm volatile("mma.sync.aligned.m16n8k16.row.col.f32.f16.f16.f32 "
                 "{%0,%1,%2,%3}, {%4,%5,%6,%7}, {%8,%9}, {%0,%1,%2,%3};"
                 : "+f"(c[0]), "+f"(c[1]), "+f"(c[2]), "+f"(c[3])
                 : "r"(a[0]), "r"(a[1]), "r"(a[2]), "r"(a[3]), "r"(b0), "r"(b1));
}
__device__ __forceinline__ void cp_async16(uint32_t smem_dst, const void* gsrc) {
    asm volatile("cp.async.cg.shared.global [%0], [%1], 16;" :: "r"(smem_dst), "l"(gsrc) : "memory");
}
#define CP_COMMIT() asm volatile("cp.async.commit_group;" ::: "memory")
#define CP_WAIT1()  asm volatile("cp.async.wait_group 1;" ::: "memory")
#define CP_WAIT0()  asm volatile("cp.async.wait_group 0;" ::: "memory")

// closed-form expansion: [silu(x), B0..B6], uniform cubic B-spline, knots -2.5..2.5 step 0.5
__device__ __forceinline__ void expand8(float x, float* e) {
    e[0] = x / (1.0f + __expf(-x));
    float u  = (x + 2.5f) * 2.0f;
    float fj = floorf(u);
    int   ji = (int)fj;
    float t  = u - fj;
    float t2 = t * t, t3 = t2 * t;
    float v3 = t3 * (1.0f / 6.0f);
    float v2 = (1.0f / 6.0f) * (-3.0f * t3 + 3.0f * t2 + 3.0f * t + 1.0f);
    float v1 = (1.0f / 6.0f) * (3.0f * t3 - 6.0f * t2 + 4.0f);
    float omt = 1.0f - t;
    float v0 = (1.0f / 6.0f) * omt * omt * omt;
    if (!(u >= 0.0f && u < 10.0f)) { v0 = v1 = v2 = v3 = 0.0f; }
#pragma unroll
    for (int m = 0; m < 7; ++m) {
        int d = ji - m;
        float r = 0.0f;
        r = (d == 3) ? v0 : r;
        r = (d == 2) ? v1 : r;
        r = (d == 1) ? v2 : r;
        r = (d == 0) ? v3 : r;
        e[1 + m] = r;
    }
}
__device__ __forceinline__ uint32_t pack_h16x2(float a, float b) {
    __half2 t = __floats2half2_rn(a, b);
    return *(uint32_t*)&t;
}

// ---------------- fused setup ----------------
__global__ void k_prep(const float* __restrict__ bw0, const float* __restrict__ sw0, const float* __restrict__ ss0,
                       const float* __restrict__ bw1, const float* __restrict__ sw1, const float* __restrict__ ss1,
                       const float* __restrict__ bw2, const float* __restrict__ sw2, const float* __restrict__ ss2,
                       const float* __restrict__ bwr, const float* __restrict__ swr, const float* __restrict__ ssr) {
    int t = blockIdx.x * 256 + threadIdx.x;
    if (t < N_NODES)   g_degi[t] = 0;
    if (t < NG * FEAT) g_pool[t] = 0.0f;
    if (t < NG)        g_cnt[t]  = 0.0f;

    const int NW = FEAT * FEAT;
    if (t < 3 * NW + CLS * FEAT) {
        int which = t / NW;
        int i = t - which * NW;
        const float *bw, *sw, *ss;
        if      (which == 0) { bw = bw0; sw = sw0; ss = ss0; }
        else if (which == 1) { bw = bw1; sw = sw1; ss = ss1; }
        else if (which == 2) { bw = bw2; sw = sw2; ss = ss2; }
        else                 { bw = bwr; sw = swr; ss = ssr; }
        float v[8];
        v[0] = bw[i];
        float s = ss[i];
#pragma unroll
        for (int k = 0; k < 7; ++k) v[1 + k] = sw[i * 7 + k] * s;
        if (which < 3) {
            __half* wh = &g_Wh[which][i * 8];
#pragma unroll
            for (int j = 0; j < 8; ++j) wh[j] = __float2half_rn(v[j]);
        } else {
            float* d = g_Wr + i * 8;
#pragma unroll
            for (int j = 0; j < 8; ++j) d[j] = v[j];
        }
    }
}
__global__ void k_hist(const int* __restrict__ dst) {
    int e = blockIdx.x * 256 + threadIdx.x;
    if (e < N_EDGES) atomicAdd(&g_degi[dst[e]], 1);
}
__global__ void k_scan1() {
    __shared__ int s[256];
    int i = blockIdx.x * 256 + threadIdx.x;
    int v = (i < N_NODES) ? g_degi[i] : 0;
    if (i < N_NODES) g_dinv[i] = rsqrtf((float)v + 1.0f);
    s[threadIdx.x] = v;
    __syncthreads();
    for (int o = 1; o < 256; o <<= 1) {
        int t = (threadIdx.x >= o) ? s[threadIdx.x - o] : 0;
        __syncthreads();
        s[threadIdx.x] += t;
        __syncthreads();
    }
    if (i < N_NODES) g_rowptr[i] = s[threadIdx.x] - v;   // exclusive within block
    if (threadIdx.x == 255) g_blocksum[blockIdx.x] = s[255];   // block total
}
// scan3 with inlined cross-block prefix: each block reduces blocksum[0..bid-1]
__global__ void k_scan3() {
    __shared__ int sred[256];
    int partial = 0;
    for (int j = threadIdx.x; j < (int)blockIdx.x; j += 256) partial += g_blocksum[j];
    sred[threadIdx.x] = partial;
    __syncthreads();
    for (int o = 128; o > 0; o >>= 1) {
        if (threadIdx.x < o) sred[threadIdx.x] += sred[threadIdx.x + o];
        __syncthreads();
    }
    int base = sred[0];
    int i = blockIdx.x * 256 + threadIdx.x;
    if (i < N_NODES) {
        int r = g_rowptr[i] + base;
        g_rowptr[i] = r;
        g_wofs[i]   = r;
    }
    if (i == 0) g_rowptr[N_NODES] = N_EDGES;
}
__global__ void k_fill(const int* __restrict__ ei) {
    int e = blockIdx.x * 256 + threadIdx.x;
    if (e >= N_EDGES) return;
    int d = ei[N_EDGES + e];
    int pos = atomicAdd(&g_wofs[d], 1);
    g_srcs[pos] = ei[e];
}

// ---------------- pipelined HMMA fused KAN-linear GEMM (single fp16, K-chunk 64) ----------------
// A fp16 16KB/stage, B fp16 16KB/stage; 3 stages each -> 96KB, 2 CTAs/SM.
// 128B rows, 8x16B units, XOR swizzle (row&7); one sync/chunk (mod-3 safe), 16 chunks.
#define A_STAGE 16384
#define B_STAGE 16384
#define OFF_B   (3 * A_STAGE)
#define SMEM_NEED (OFF_B + 3 * B_STAGE)   // 98304

__global__ __launch_bounds__(256, 2) void k_gemm_mma(const float* __restrict__ x, int layer) {
    extern __shared__ __align__(16) char sm[];
    uint32_t sb = smem_u32(sm);

    const float* Hin = (layer == 0) ? x : g_H;
    const __half* Wh = g_Wh[layer];

    const int tid = threadIdx.x, lane = tid & 31, wid = tid >> 5;
    const int row0 = blockIdx.x * 128;
    const int m0w = (wid >> 1) * 32;
    const int n0w = (wid & 1) * 64;

    // H coords: per chunk 1024 items (128 rows x 8 dims); thread does q<4: id=q*256+tid
    int hrow[4];
    const int hdd = tid & 7;
#pragma unroll
    for (int q = 0; q < 4; ++q) hrow[q] = q * 32 + (tid >> 3);
    bool hok[4];
#pragma unroll
    for (int q = 0; q < 4; ++q) hok[q] = (row0 + hrow[q]) < N_NODES;

    float hv[2][4];
#pragma unroll
    for (int q = 0; q < 4; ++q)
        hv[0][q] = hok[q] ? Hin[(row0 + hrow[q]) * FEAT + hdd] : 0.0f;
#pragma unroll
    for (int q = 0; q < 4; ++q)
        hv[1][q] = hok[q] ? Hin[(row0 + hrow[q]) * FEAT + 8 + hdd] : 0.0f;

    // prefetch B(0) into stage 0: 1024 units of 16B
    {
#pragma unroll
        for (int q = 0; q < 4; ++q) {
            int idx = q * 256 + tid;
            int o = idx >> 3, s = idx & 7;
            uint32_t off = (uint32_t)o * 128 + (uint32_t)((s ^ (o & 7)) * 16);
            cp_async16(sb + OFF_B + off, Wh + o * KDIM + s * 8);
        }
        CP_COMMIT();
    }

    // produce A(0) into stage 0
    {
        char* bufA = sm;
#pragma unroll
        for (int q = 0; q < 4; ++q) {
            int id = q * 256 + tid;
            int n = id >> 3, dd = id & 7;
            float e[8];
            expand8(hv[0][q], e);
            uint32_t h[4];
#pragma unroll
            for (int j = 0; j < 4; ++j) h[j] = pack_h16x2(e[2 * j], e[2 * j + 1]);
            uint32_t off = (uint32_t)n * 128 + (uint32_t)((dd ^ (n & 7)) * 16);
            *(uint4*)(bufA + off) = make_uint4(h[0], h[1], h[2], h[3]);
        }
    }

    float acc[2][8][4];
#pragma unroll
    for (int i = 0; i < 2; ++i)
#pragma unroll
        for (int j = 0; j < 8; ++j)
#pragma unroll
            for (int k = 0; k < 4; ++k) acc[i][j][k] = 0.0f;

    int stage_next = 1;
    for (int c = 0; c < 16; ++c) {
        // prefetch B(c+1)
        if (c + 1 < 16) {
            uint32_t bst = sb + OFF_B + stage_next * B_STAGE;
#pragma unroll
            for (int q = 0; q < 4; ++q) {
                int idx = q * 256 + tid;
                int o = idx >> 3, s = idx & 7;
                uint32_t off = (uint32_t)o * 128 + (uint32_t)((s ^ (o & 7)) * 16);
                cp_async16(bst + off, Wh + o * KDIM + (c + 1) * 64 + s * 8);
            }
            CP_COMMIT();
        }
        // H loads for chunk c+2
        if (c + 2 < 16) {
#pragma unroll
            for (int q = 0; q < 4; ++q)
                hv[c & 1][q] = hok[q] ? Hin[(row0 + hrow[q]) * FEAT + (c + 2) * 8 + hdd] : 0.0f;
        }
        // produce A(c+1)
        if (c + 1 < 16) {
            char* bufA = sm + stage_next * A_STAGE;
            const float* hvc = hv[(c + 1) & 1];
#pragma unroll
            for (int q = 0; q < 4; ++q) {
                int id = q * 256 + tid;
                int n = id >> 3, dd = id & 7;
                float e[8];
                expand8(hvc[q], e);
                uint32_t h[4];
#pragma unroll
                for (int j = 0; j < 4; ++j) h[j] = pack_h16x2(e[2 * j], e[2 * j + 1]);
                uint32_t off = (uint32_t)n * 128 + (uint32_t)((dd ^ (n & 7)) * 16);
                *(uint4*)(bufA + off) = make_uint4(h[0], h[1], h[2], h[3]);
            }
        }
        if (c == 15) { CP_WAIT0(); } else { CP_WAIT1(); }
        __syncthreads();

        // consume chunk c from stage c%3
        const int ast = (stage_next + 2) % 3;
        const uint32_t abase = sb + ast * A_STAGE;
        const uint32_t bbase = sb + OFF_B + ast * B_STAGE;
#pragma unroll
        for (int kk = 0; kk < 4; ++kk) {
            uint32_t ah[2][4];
#pragma unroll
            for (int mt = 0; mt < 2; ++mt) {
                int m = m0w + mt * 16 + (lane & 15);
                uint32_t u = (uint32_t)((kk * 2 + (lane >> 4)) ^ (m & 7));
                ldm_x4(ah[mt], abase + (uint32_t)m * 128 + u * 16);
            }
            uint32_t bh[4][4];
#pragma unroll
            for (int ng = 0; ng < 4; ++ng) {
                int n = n0w + ng * 16 + ((lane >> 4) << 3) + (lane & 7);
                uint32_t u = (uint32_t)((kk * 2 + ((lane >> 3) & 1)) ^ (n & 7));
                ldm_x4(bh[ng], bbase + (uint32_t)n * 128 + u * 16);
            }
#pragma unroll
            for (int mt = 0; mt < 2; ++mt)
#pragma unroll
                for (int ng = 0; ng < 4; ++ng)
#pragma unroll
                    for (int hf = 0; hf < 2; ++hf)
                        mma16816(acc[mt][ng * 2 + hf], ah[mt], bh[ng][hf * 2], bh[ng][hf * 2 + 1]);
        }
        stage_next = (stage_next + 1) % 3;
    }

    // epilogue: write Y as fp16
#pragma unroll
    for (int mt = 0; mt < 2; ++mt) {
        int r1 = row0 + m0w + mt * 16 + (lane >> 2);
        int r2 = r1 + 8;
        bool ok1 = r1 < N_NODES, ok2 = r2 < N_NODES;
        int cb = n0w + (lane & 3) * 2;
#pragma unroll
        for (int nt = 0; nt < 8; ++nt) {
            int col = cb + nt * 8;
            float* a = acc[mt][nt];
            if (ok1) *(__half2*)&g_Yh[r1 * FEAT + col] = __floats2half2_rn(a[0], a[1]);
            if (ok2) *(__half2*)&g_Yh[r2 * FEAT + col] = __floats2half2_rn(a[2], a[3]);
        }
    }
}

// ---------------- fused CSR aggregation + bias + silu (+ optional pooling) ----------------
__device__ __forceinline__ float4 ld_y4(int node, int lane) {
    uint2 u = *(const uint2*)&g_Yh[node * FEAT + lane * 4];
    float2 p0 = __half22float2(*(__half2*)&u.x);
    float2 p1 = __half22float2(*(__half2*)&u.y);
    return make_float4(p0.x, p0.y, p1.x, p1.y);
}

__global__ __launch_bounds__(256) void k_aggr(const float* __restrict__ bias,
                                              const int* __restrict__ batch) {
    int w = (blockIdx.x * 256 + threadIdx.x) >> 5;
    int lane = threadIdx.x & 31;
    if (w >= N_NODES) return;
    float dd = g_dinv[w];
    float dd2 = dd * dd;
    float4 a = ld_y4(w, lane);
    a.x *= dd2; a.y *= dd2; a.z *= dd2; a.w *= dd2;

    int e = g_rowptr[w], end = g_rowptr[w + 1];
    for (; e + 4 <= end; e += 4) {
        int s0 = g_srcs[e],     s1 = g_srcs[e + 1];
        int s2 = g_srcs[e + 2], s3 = g_srcs[e + 3];
        float nm0 = g_dinv[s0] * dd, nm1 = g_dinv[s1] * dd;
        float nm2 = g_dinv[s2] * dd, nm3 = g_dinv[s3] * dd;
        float4 v0 = ld_y4(s0, lane);
        float4 v1 = ld_y4(s1, lane);
        float4 v2 = ld_y4(s2, lane);
        float4 v3 = ld_y4(s3, lane);
        a.x += v0.x * nm0 + v1.x * nm1 + v2.x * nm2 + v3.x * nm3;
        a.y += v0.y * nm0 + v1.y * nm1 + v2.y * nm2 + v3.y * nm3;
        a.z += v0.z * nm0 + v1.z * nm1 + v2.z * nm2 + v3.z * nm3;
        a.w += v0.w * nm0 + v1.w * nm1 + v2.w * nm2 + v3.w * nm3;
    }
    for (; e < end; ++e) {
        int s0 = g_srcs[e];
        float nm0 = g_dinv[s0] * dd;
        float4 v0 = ld_y4(s0, lane);
        a.x += v0.x * nm0; a.y += v0.y * nm0; a.z += v0.z * nm0; a.w += v0.w * nm0;
    }
    float4 bv = *(const float4*)&bias[lane * 4];
    a.x += bv.x; a.y += bv.y; a.z += bv.z; a.w += bv.w;
    a.x = a.x / (1.0f + __expf(-a.x));
    a.y = a.y / (1.0f + __expf(-a.y));
    a.z = a.z / (1.0f + __expf(-a.z));
    a.w = a.w / (1.0f + __expf(-a.w));
    if (batch == nullptr) {
        *(float4*)&g_H[w * FEAT + lane * 4] = a;
    } else {
        int g = batch[w];
        red_add_v4(&g_pool[g * FEAT + lane * 4], a);
        if (lane == 0) atomicAdd(&g_cnt[g], 1.0f);
    }
}

// ---------------- readout ----------------
__global__ void k_readout(float* __restrict__ out) {
    int g = blockIdx.x;
    int t = threadIdx.x;   // 128
    __shared__ float red[CLS][4];
    __shared__ float logits[CLS];

    float inv = 1.0f / fmaxf(g_cnt[g], 1.0f);
    float p = g_pool[g * FEAT + t] * inv;
    float e[8];
    expand8(p, e);

    float part[CLS];
#pragma unroll
    for (int c = 0; c < CLS; ++c) {
        const float* w = &g_Wr[c * KDIM + t * 8];
        float s = 0.0f;
#pragma unroll
        for (int j = 0; j < 8; ++j) s = fmaf(e[j], w[j], s);
        part[c] = s;
    }
    int lane = t & 31, wid = t >> 5;
#pragma unroll
    for (int c = 0; c < CLS; ++c) {
        float v = part[c];
#pragma unroll
        for (int o = 16; o > 0; o >>= 1) v += __shfl_down_sync(0xffffffffu, v, o);
        if (lane == 0) red[c][wid] = v;
    }
    __syncthreads();
    if (t < CLS) logits[t] = red[t][0] + red[t][1] + red[t][2] + red[t][3];
    __syncthreads();
    if (t == 0) {
        float m = -1e30f;
        for (int c = 0; c < CLS; ++c) m = fmaxf(m, logits[c]);
        float s = 0.0f;
        for (int c = 0; c < CLS; ++c) s += expf(logits[c] - m);
        float lse = m + logf(s);
        for (int c = 0; c < CLS; ++c) out[g * CLS + c] = logits[c] - lse;
    }
}

// ---------------- launch ----------------
extern "C" void kernel_launch(void* const* d_in, const int* in_sizes, int n_in,
                              void* d_out, int out_size) {
    const float* x     = (const float*)d_in[0];
    const int*   ei    = (const int*)d_in[1];
    const int*   batch = (const int*)d_in[2];
    float* out = (float*)d_out;

    cudaFuncSetAttribute(k_gemm_mma, cudaFuncAttributeMaxDynamicSharedMemorySize, SMEM_NEED);

    const int nscan = (N_NODES + 255) / 256;   // 196
    const int nprep = (3 * FEAT * FEAT + CLS * FEAT + 255) / 256;  // 198
    k_prep<<<(nprep > nscan ? nprep : nscan), 256>>>(
        (const float*)d_in[3],  (const float*)d_in[4],  (const float*)d_in[5],
        (const float*)d_in[7],  (const float*)d_in[8],  (const float*)d_in[9],
        (const float*)d_in[11], (const float*)d_in[12], (const float*)d_in[13],
        (const float*)d_in[15], (const float*)d_in[16], (const float*)d_in[17]);
    k_hist<<<(N_EDGES + 255) / 256, 256>>>(ei + N_EDGES);
    k_scan1<<<nscan, 256>>>();
    k_scan3<<<nscan, 256>>>();
    k_fill<<<(N_EDGES + 255) / 256, 256>>>(ei);

    const float* bb[3] = {(const float*)d_in[6], (const float*)d_in[10], (const float*)d_in[14]};
    int gemm_blocks = (N_NODES + 127) / 128;   // 391
    int aggr_blocks = (N_NODES * 32 + 255) / 256;
    for (int l = 0; l < 3; ++l) {
        k_gemm_mma<<<gemm_blocks, 256, SMEM_NEED>>>(x, l);
        k_aggr<<<aggr_blocks, 256>>>(bb[l], (l == 2) ? batch : nullptr);
    }

    k_readout<<<NG, 128>>>(out);
}

// round 14
// speedup vs baseline: 3.9071x; 1.0105x over previous
#include <cuda_runtime.h>
#include <cuda_fp16.h>
#include <math.h>
#include <stdint.h>

#define N_NODES 50000
#define N_EDGES 800000
#define FEAT    128
#define CLS     10
#define NG      64
#define KDIM    1024

// ---------------- scratch ----------------
__device__ __align__(16) __half g_Wh[3][FEAT * KDIM];   // combined weights fp16
__device__ __align__(16) float g_Wr[CLS * KDIM];
__device__ int   g_degi[N_NODES];
__device__ float g_dinv[N_NODES];
__device__ int   g_rowptr[N_NODES + 1];
__device__ int   g_wofs[N_NODES];
__device__ int   g_srcs[N_EDGES];
__device__ int   g_blocksum[256];
__device__ __align__(16) __half g_Yh[N_NODES * FEAT];   // KAN linear output (fp16)
__device__ __align__(16) float g_H[N_NODES * FEAT];
__device__ float g_pool[NG * FEAT];
__device__ float g_cnt[NG];

// ---------------- helpers ----------------
__device__ __forceinline__ uint32_t smem_u32(const void* p) {
    uint32_t a;
    asm("{ .reg .u64 t; cvta.to.shared.u64 t, %1; cvt.u32.u64 %0, t; }" : "=r"(a) : "l"(p));
    return a;
}
__device__ __forceinline__ void red_add_v4(float* addr, float4 v) {
    asm volatile("red.global.add.v4.f32 [%0], {%1, %2, %3, %4};"
                 :: "l"(addr), "f"(v.x), "f"(v.y), "f"(v.z), "f"(v.w) : "memory");
}
__device__ __forceinline__ void ldm_x4(uint32_t* r, uint32_t addr) {
    asm volatile("ldmatrix.sync.aligned.m8n8.x4.shared.b16 {%0,%1,%2,%3}, [%4];"
                 : "=r"(r[0]), "=r"(r[1]), "=r"(r[2]), "=r"(r[3]) : "r"(addr));
}
__device__ __forceinline__ void mma16816(float* c, const uint32_t* a, uint32_t b0, uint32_t b1) {
    asm volatile("mma.sync.aligned.m16n8k16.row.col.f32.f16.f16.f32 "
                 "{%0,%1,%2,%3}, {%4,%5,%6,%7}, {%8,%9}, {%0,%1,%2,%3};"
                 : "+f"(c[0]), "+f"(c[1]), "+f"(c[2]), "+f"(c[3])
                 : "r"(a[0]), "r"(a[1]), "r"(a[2]), "r"(a[3]), "r"(b0), "r"(b1));
}
__device__ __forceinline__ void cp_async16(uint32_t smem_dst, const void* gsrc) {
    asm volatile("cp.async.cg.shared.global [%0], [%1], 16;" :: "r"(smem_dst), "l"(gsrc) : "memory");
}
#define CP_COMMIT() asm volatile("cp.async.commit_group;" ::: "memory")
#define CP_WAIT1()  asm volatile("cp.async.wait_group 1;" ::: "memory")
#define CP_WAIT0()  asm volatile("cp.async.wait_group 0;" ::: "memory")

// closed-form expansion: [silu(x), B0..B6], uniform cubic B-spline, knots -2.5..2.5 step 0.5
__device__ __forceinline__ void expand8(float x, float* e) {
    e[0] = x / (1.0f + __expf(-x));
    float u  = (x + 2.5f) * 2.0f;
    float fj = floorf(u);
    int   ji = (int)fj;
    float t  = u - fj;
    float t2 = t * t, t3 = t2 * t;
    float v3 = t3 * (1.0f / 6.0f);
    float v2 = (1.0f / 6.0f) * (-3.0f * t3 + 3.0f * t2 + 3.0f * t + 1.0f);
    float v1 = (1.0f / 6.0f) * (3.0f * t3 - 6.0f * t2 + 4.0f);
    float omt = 1.0f - t;
    float v0 = (1.0f / 6.0f) * omt * omt * omt;
    if (!(u >= 0.0f && u < 10.0f)) { v0 = v1 = v2 = v3 = 0.0f; }
#pragma unroll
    for (int m = 0; m < 7; ++m) {
        int d = ji - m;
        float r = 0.0f;
        r = (d == 3) ? v0 : r;
        r = (d == 2) ? v1 : r;
        r = (d == 1) ? v2 : r;
        r = (d == 0) ? v3 : r;
        e[1 + m] = r;
    }
}
__device__ __forceinline__ uint32_t pack_h16x2(float a, float b) {
    __half2 t = __floats2half2_rn(a, b);
    return *(uint32_t*)&t;
}

// ---------------- fused setup ----------------
__global__ void k_prep(const float* __restrict__ bw0, const float* __restrict__ sw0, const float* __restrict__ ss0,
                       const float* __restrict__ bw1, const float* __restrict__ sw1, const float* __restrict__ ss1,
                       const float* __restrict__ bw2, const float* __restrict__ sw2, const float* __restrict__ ss2,
                       const float* __restrict__ bwr, const float* __restrict__ swr, const float* __restrict__ ssr) {
    int t = blockIdx.x * 256 + threadIdx.x;
    if (t < N_NODES)   g_degi[t] = 0;
    if (t < NG * FEAT) g_pool[t] = 0.0f;
    if (t < NG)        g_cnt[t]  = 0.0f;

    const int NW = FEAT * FEAT;
    if (t < 3 * NW + CLS * FEAT) {
        int which = t / NW;
        int i = t - which * NW;
        const float *bw, *sw, *ss;
        if      (which == 0) { bw = bw0; sw = sw0; ss = ss0; }
        else if (which == 1) { bw = bw1; sw = sw1; ss = ss1; }
        else if (which == 2) { bw = bw2; sw = sw2; ss = ss2; }
        else                 { bw = bwr; sw = swr; ss = ssr; }
        float v[8];
        v[0] = bw[i];
        float s = ss[i];
#pragma unroll
        for (int k = 0; k < 7; ++k) v[1 + k] = sw[i * 7 + k] * s;
        if (which < 3) {
            __half* wh = &g_Wh[which][i * 8];
#pragma unroll
            for (int j = 0; j < 8; ++j) wh[j] = __float2half_rn(v[j]);
        } else {
            float* d = g_Wr + i * 8;
#pragma unroll
            for (int j = 0; j < 8; ++j) d[j] = v[j];
        }
    }
}
__global__ void k_hist(const int* __restrict__ dst) {
    int e = blockIdx.x * 256 + threadIdx.x;
    if (e < N_EDGES) atomicAdd(&g_degi[dst[e]], 1);
}
__global__ void k_scan1() {
    __shared__ int s[256];
    int i = blockIdx.x * 256 + threadIdx.x;
    int v = (i < N_NODES) ? g_degi[i] : 0;
    if (i < N_NODES) g_dinv[i] = rsqrtf((float)v + 1.0f);
    s[threadIdx.x] = v;
    __syncthreads();
    for (int o = 1; o < 256; o <<= 1) {
        int t = (threadIdx.x >= o) ? s[threadIdx.x - o] : 0;
        __syncthreads();
        s[threadIdx.x] += t;
        __syncthreads();
    }
    if (i < N_NODES) g_rowptr[i] = s[threadIdx.x] - v;   // exclusive within block
    if (threadIdx.x == 255) g_blocksum[blockIdx.x] = s[255];   // block total
}
// scan3 with inlined cross-block prefix: each block reduces blocksum[0..bid-1]
__global__ void k_scan3() {
    __shared__ int sred[256];
    int partial = 0;
    for (int j = threadIdx.x; j < (int)blockIdx.x; j += 256) partial += g_blocksum[j];
    sred[threadIdx.x] = partial;
    __syncthreads();
    for (int o = 128; o > 0; o >>= 1) {
        if (threadIdx.x < o) sred[threadIdx.x] += sred[threadIdx.x + o];
        __syncthreads();
    }
    int base = sred[0];
    int i = blockIdx.x * 256 + threadIdx.x;
    if (i < N_NODES) {
        int r = g_rowptr[i] + base;
        g_rowptr[i] = r;
        g_wofs[i]   = r;
    }
    if (i == 0) g_rowptr[N_NODES] = N_EDGES;
}
__global__ void k_fill(const int* __restrict__ ei) {
    int e = blockIdx.x * 256 + threadIdx.x;
    if (e >= N_EDGES) return;
    int d = ei[N_EDGES + e];
    int pos = atomicAdd(&g_wofs[d], 1);
    g_srcs[pos] = ei[e];
}

// ---------------- pipelined HMMA fused KAN-linear GEMM (fp16, M-tile 64, K-chunk 64) ----------------
// A fp16 8KB/stage, B fp16 16KB/stage; 3 stages each -> 72KB, 3 CTAs/SM.
// 128B rows, 8x16B units, XOR swizzle (row&7); one sync/chunk (mod-3 safe), 16 chunks.
// 8 warps as 2 (M) x 4 (N): warp tile M32 x N32.
#define TM 64
#define A_STAGE 8192
#define B_STAGE 16384
#define OFF_B   (3 * A_STAGE)
#define SMEM_NEED (OFF_B + 3 * B_STAGE)   // 73728

__global__ __launch_bounds__(256, 3) void k_gemm_mma(const float* __restrict__ x, int layer) {
    extern __shared__ __align__(16) char sm[];
    uint32_t sb = smem_u32(sm);

    const float* Hin = (layer == 0) ? x : g_H;
    const __half* Wh = g_Wh[layer];

    const int tid = threadIdx.x, lane = tid & 31, wid = tid >> 5;
    const int row0 = blockIdx.x * TM;
    const int m0w = (wid >> 2) * 32;     // 0 or 32
    const int n0w = (wid & 3) * 32;      // 0,32,64,96

    // H coords: per chunk 512 items (64 rows x 8 dims); thread does q<2: id=q*256+tid
    int hrow[2];
    const int hdd = tid & 7;
#pragma unroll
    for (int q = 0; q < 2; ++q) hrow[q] = q * 32 + (tid >> 3);
    bool hok[2];
#pragma unroll
    for (int q = 0; q < 2; ++q) hok[q] = (row0 + hrow[q]) < N_NODES;

    float hv[2][2];
#pragma unroll
    for (int q = 0; q < 2; ++q)
        hv[0][q] = hok[q] ? Hin[(row0 + hrow[q]) * FEAT + hdd] : 0.0f;
#pragma unroll
    for (int q = 0; q < 2; ++q)
        hv[1][q] = hok[q] ? Hin[(row0 + hrow[q]) * FEAT + 8 + hdd] : 0.0f;

    // prefetch B(0) into stage 0: 1024 units of 16B
    {
#pragma unroll
        for (int q = 0; q < 4; ++q) {
            int idx = q * 256 + tid;
            int o = idx >> 3, s = idx & 7;
            uint32_t off = (uint32_t)o * 128 + (uint32_t)((s ^ (o & 7)) * 16);
            cp_async16(sb + OFF_B + off, Wh + o * KDIM + s * 8);
        }
        CP_COMMIT();
    }

    // produce A(0) into stage 0
    {
        char* bufA = sm;
#pragma unroll
        for (int q = 0; q < 2; ++q) {
            int n = hrow[q], dd = hdd;
            float e[8];
            expand8(hv[0][q], e);
            uint32_t h[4];
#pragma unroll
            for (int j = 0; j < 4; ++j) h[j] = pack_h16x2(e[2 * j], e[2 * j + 1]);
            uint32_t off = (uint32_t)n * 128 + (uint32_t)((dd ^ (n & 7)) * 16);
            *(uint4*)(bufA + off) = make_uint4(h[0], h[1], h[2], h[3]);
        }
    }

    float acc[2][4][4];
#pragma unroll
    for (int i = 0; i < 2; ++i)
#pragma unroll
        for (int j = 0; j < 4; ++j)
#pragma unroll
            for (int k = 0; k < 4; ++k) acc[i][j][k] = 0.0f;

    int stage_next = 1;
    for (int c = 0; c < 16; ++c) {
        // prefetch B(c+1)
        if (c + 1 < 16) {
            uint32_t bst = sb + OFF_B + stage_next * B_STAGE;
#pragma unroll
            for (int q = 0; q < 4; ++q) {
                int idx = q * 256 + tid;
                int o = idx >> 3, s = idx & 7;
                uint32_t off = (uint32_t)o * 128 + (uint32_t)((s ^ (o & 7)) * 16);
                cp_async16(bst + off, Wh + o * KDIM + (c + 1) * 64 + s * 8);
            }
            CP_COMMIT();
        }
        // H loads for chunk c+2
        if (c + 2 < 16) {
#pragma unroll
            for (int q = 0; q < 2; ++q)
                hv[c & 1][q] = hok[q] ? Hin[(row0 + hrow[q]) * FEAT + (c + 2) * 8 + hdd] : 0.0f;
        }
        // produce A(c+1)
        if (c + 1 < 16) {
            char* bufA = sm + stage_next * A_STAGE;
            const float* hvc = hv[(c + 1) & 1];
#pragma unroll
            for (int q = 0; q < 2; ++q) {
                int n = hrow[q], dd = hdd;
                float e[8];
                expand8(hvc[q], e);
                uint32_t h[4];
#pragma unroll
                for (int j = 0; j < 4; ++j) h[j] = pack_h16x2(e[2 * j], e[2 * j + 1]);
                uint32_t off = (uint32_t)n * 128 + (uint32_t)((dd ^ (n & 7)) * 16);
                *(uint4*)(bufA + off) = make_uint4(h[0], h[1], h[2], h[3]);
            }
        }
        if (c == 15) { CP_WAIT0(); } else { CP_WAIT1(); }
        __syncthreads();

        // consume chunk c from stage c%3
        const int ast = (stage_next + 2) % 3;
        const uint32_t abase = sb + ast * A_STAGE;
        const uint32_t bbase = sb + OFF_B + ast * B_STAGE;
#pragma unroll
        for (int kk = 0; kk < 4; ++kk) {
            uint32_t ah[2][4];
#pragma unroll
            for (int mt = 0; mt < 2; ++mt) {
                int m = m0w + mt * 16 + (lane & 15);
                uint32_t u = (uint32_t)((kk * 2 + (lane >> 4)) ^ (m & 7));
                ldm_x4(ah[mt], abase + (uint32_t)m * 128 + u * 16);
            }
            uint32_t bh[2][4];
#pragma unroll
            for (int ng = 0; ng < 2; ++ng) {
                int n = n0w + ng * 16 + ((lane >> 4) << 3) + (lane & 7);
                uint32_t u = (uint32_t)((kk * 2 + ((lane >> 3) & 1)) ^ (n & 7));
                ldm_x4(bh[ng], bbase + (uint32_t)n * 128 + u * 16);
            }
#pragma unroll
            for (int mt = 0; mt < 2; ++mt)
#pragma unroll
                for (int ng = 0; ng < 2; ++ng)
#pragma unroll
                    for (int hf = 0; hf < 2; ++hf)
                        mma16816(acc[mt][ng * 2 + hf], ah[mt], bh[ng][hf * 2], bh[ng][hf * 2 + 1]);
        }
        stage_next = (stage_next + 1) % 3;
    }

    // epilogue: write Y as fp16
#pragma unroll
    for (int mt = 0; mt < 2; ++mt) {
        int r1 = row0 + m0w + mt * 16 + (lane >> 2);
        int r2 = r1 + 8;
        bool ok1 = r1 < N_NODES, ok2 = r2 < N_NODES;
        int cb = n0w + (lane & 3) * 2;
#pragma unroll
        for (int nt = 0; nt < 4; ++nt) {
            int col = cb + nt * 8;
            float* a = acc[mt][nt];
            if (ok1) *(__half2*)&g_Yh[r1 * FEAT + col] = __floats2half2_rn(a[0], a[1]);
            if (ok2) *(__half2*)&g_Yh[r2 * FEAT + col] = __floats2half2_rn(a[2], a[3]);
        }
    }
}

// ---------------- fused CSR aggregation + bias + silu (+ optional pooling) ----------------
__device__ __forceinline__ float4 ld_y4(int node, int lane) {
    uint2 u = *(const uint2*)&g_Yh[node * FEAT + lane * 4];
    float2 p0 = __half22float2(*(__half2*)&u.x);
    float2 p1 = __half22float2(*(__half2*)&u.y);
    return make_float4(p0.x, p0.y, p1.x, p1.y);
}

__global__ __launch_bounds__(256) void k_aggr(const float* __restrict__ bias,
                                              const int* __restrict__ batch) {
    int w = (blockIdx.x * 256 + threadIdx.x) >> 5;
    int lane = threadIdx.x & 31;
    if (w >= N_NODES) return;
    float dd = g_dinv[w];
    float dd2 = dd * dd;
    float4 a = ld_y4(w, lane);
    a.x *= dd2; a.y *= dd2; a.z *= dd2; a.w *= dd2;

    int e = g_rowptr[w], end = g_rowptr[w + 1];
    for (; e + 4 <= end; e += 4) {
        int s0 = g_srcs[e],     s1 = g_srcs[e + 1];
        int s2 = g_srcs[e + 2], s3 = g_srcs[e + 3];
        float nm0 = g_dinv[s0] * dd, nm1 = g_dinv[s1] * dd;
        float nm2 = g_dinv[s2] * dd, nm3 = g_dinv[s3] * dd;
        float4 v0 = ld_y4(s0, lane);
        float4 v1 = ld_y4(s1, lane);
        float4 v2 = ld_y4(s2, lane);
        float4 v3 = ld_y4(s3, lane);
        a.x += v0.x * nm0 + v1.x * nm1 + v2.x * nm2 + v3.x * nm3;
        a.y += v0.y * nm0 + v1.y * nm1 + v2.y * nm2 + v3.y * nm3;
        a.z += v0.z * nm0 + v1.z * nm1 + v2.z * nm2 + v3.z * nm3;
        a.w += v0.w * nm0 + v1.w * nm1 + v2.w * nm2 + v3.w * nm3;
    }
    for (; e < end; ++e) {
        int s0 = g_srcs[e];
        float nm0 = g_dinv[s0] * dd;
        float4 v0 = ld_y4(s0, lane);
        a.x += v0.x * nm0; a.y += v0.y * nm0; a.z += v0.z * nm0; a.w += v0.w * nm0;
    }
    float4 bv = *(const float4*)&bias[lane * 4];
    a.x += bv.x; a.y += bv.y; a.z += bv.z; a.w += bv.w;
    a.x = a.x / (1.0f + __expf(-a.x));
    a.y = a.y / (1.0f + __expf(-a.y));
    a.z = a.z / (1.0f + __expf(-a.z));
    a.w = a.w / (1.0f + __expf(-a.w));
    if (batch == nullptr) {
        *(float4*)&g_H[w * FEAT + lane * 4] = a;
    } else {
        int g = batch[w];
        red_add_v4(&g_pool[g * FEAT + lane * 4], a);
        if (lane == 0) atomicAdd(&g_cnt[g], 1.0f);
    }
}

// ---------------- readout ----------------
__global__ void k_readout(float* __restrict__ out) {
    int g = blockIdx.x;
    int t = threadIdx.x;   // 128
    __shared__ float red[CLS][4];
    __shared__ float logits[CLS];

    float inv = 1.0f / fmaxf(g_cnt[g], 1.0f);
    float p = g_pool[g * FEAT + t] * inv;
    float e[8];
    expand8(p, e);

    float part[CLS];
#pragma unroll
    for (int c = 0; c < CLS; ++c) {
        const float* w = &g_Wr[c * KDIM + t * 8];
        float s = 0.0f;
#pragma unroll
        for (int j = 0; j < 8; ++j) s = fmaf(e[j], w[j], s);
        part[c] = s;
    }
    int lane = t & 31, wid = t >> 5;
#pragma unroll
    for (int c = 0; c < CLS; ++c) {
        float v = part[c];
#pragma unroll
        for (int o = 16; o > 0; o >>= 1) v += __shfl_down_sync(0xffffffffu, v, o);
        if (lane == 0) red[c][wid] = v;
    }
    __syncthreads();
    if (t < CLS) logits[t] = red[t][0] + red[t][1] + red[t][2] + red[t][3];
    __syncthreads();
    if (t == 0) {
        float m = -1e30f;
        for (int c = 0; c < CLS; ++c) m = fmaxf(m, logits[c]);
        float s = 0.0f;
        for (int c = 0; c < CLS; ++c) s += expf(logits[c] - m);
        float lse = m + logf(s);
        for (int c = 0; c < CLS; ++c) out[g * CLS + c] = logits[c] - lse;
    }
}

// ---------------- launch ----------------
extern "C" void kernel_launch(void* const* d_in, const int* in_sizes, int n_in,
                              void* d_out, int out_size) {
    const float* x     = (const float*)d_in[0];
    const int*   ei    = (const int*)d_in[1];
    const int*   batch = (const int*)d_in[2];
    float* out = (float*)d_out;

    cudaFuncSetAttribute(k_gemm_mma, cudaFuncAttributeMaxDynamicSharedMemorySize, SMEM_NEED);

    const int nscan = (N_NODES + 255) / 256;   // 196
    const int nprep = (3 * FEAT * FEAT + CLS * FEAT + 255) / 256;  // 198
    k_prep<<<(nprep > nscan ? nprep : nscan), 256>>>(
        (const float*)d_in[3],  (const float*)d_in[4],  (const float*)d_in[5],
        (const float*)d_in[7],  (const float*)d_in[8],  (const float*)d_in[9],
        (const float*)d_in[11], (const float*)d_in[12], (const float*)d_in[13],
        (const float*)d_in[15], (const float*)d_in[16], (const float*)d_in[17]);
    k_hist<<<(N_EDGES + 255) / 256, 256>>>(ei + N_EDGES);
    k_scan1<<<nscan, 256>>>();
    k_scan3<<<nscan, 256>>>();
    k_fill<<<(N_EDGES + 255) / 256, 256>>>(ei);

    const float* bb[3] = {(const float*)d_in[6], (const float*)d_in[10], (const float*)d_in[14]};
    int gemm_blocks = (N_NODES + TM - 1) / TM;   // 782
    int aggr_blocks = (N_NODES * 32 + 255) / 256;
    for (int l = 0; l < 3; ++l) {
        k_gemm_mma<<<gemm_blocks, 256, SMEM_NEED>>>(x, l);
        k_aggr<<<aggr_blocks, 256>>>(bb[l], (l == 2) ? batch : nullptr);
    }

    k_readout<<<NG, 128>>>(out);
}

// round 16
// speedup vs baseline: 4.0798x; 1.0442x over previous
#include <cuda_runtime.h>
#include <cuda_fp16.h>
#include <math.h>
#include <stdint.h>

#define N_NODES 50000
#define N_EDGES 800000
#define FEAT    128
#define CLS     10
#define NG      64
#define KDIM    1024

// ---------------- scratch ----------------
__device__ __align__(16) __half g_Wh[3][FEAT * KDIM];   // combined weights fp16
__device__ __align__(16) float g_Wr[CLS * KDIM];
__device__ int   g_degi[N_NODES];
__device__ float g_dinv[N_NODES];
__device__ int   g_rowptr[N_NODES + 1];
__device__ int   g_wofs[N_NODES];
__device__ int   g_srcs[N_EDGES];
__device__ int   g_blocksum[256];
__device__ __align__(16) __half g_Yh[N_NODES * FEAT];   // pre-scaled Y' = Y*dinv (fp16)
__device__ __align__(16) float g_H[N_NODES * FEAT];
__device__ float g_pool[NG * FEAT];
__device__ float g_cnt[NG];

// ---------------- helpers ----------------
__device__ __forceinline__ uint32_t smem_u32(const void* p) {
    uint32_t a;
    asm("{ .reg .u64 t; cvta.to.shared.u64 t, %1; cvt.u32.u64 %0, t; }" : "=r"(a) : "l"(p));
    return a;
}
__device__ __forceinline__ void red_add_v4(float* addr, float4 v) {
    asm volatile("red.global.add.v4.f32 [%0], {%1, %2, %3, %4};"
                 :: "l"(addr), "f"(v.x), "f"(v.y), "f"(v.z), "f"(v.w) : "memory");
}
__device__ __forceinline__ void ldm_x4(uint32_t* r, uint32_t addr) {
    asm volatile("ldmatrix.sync.aligned.m8n8.x4.shared.b16 {%0,%1,%2,%3}, [%4];"
                 : "=r"(r[0]), "=r"(r[1]), "=r"(r[2]), "=r"(r[3]) : "r"(addr));
}
__device__ __forceinline__ void mma16816(float* c, const uint32_t* a, uint32_t b0, uint32_t b1) {
    asm volatile("mma.sync.aligned.m16n8k16.row.col.f32.f16.f16.f32 "
                 "{%0,%1,%2,%3}, {%4,%5,%6,%7}, {%8,%9}, {%0,%1,%2,%3};"
                 : "+f"(c[0]), "+f"(c[1]), "+f"(c[2]), "+f"(c[3])
                 : "r"(a[0]), "r"(a[1]), "r"(a[2]), "r"(a[3]), "r"(b0), "r"(b1));
}
__device__ __forceinline__ void cp_async16(uint32_t smem_dst, const void* gsrc) {
    asm volatile("cp.async.cg.shared.global [%0], [%1], 16;" :: "r"(smem_dst), "l"(gsrc) : "memory");
}
#define CP_COMMIT() asm volatile("cp.async.commit_group;" ::: "memory")
#define CP_WAIT1()  asm volatile("cp.async.wait_group 1;" ::: "memory")
#define CP_WAIT0()  asm volatile("cp.async.wait_group 0;" ::: "memory")

// closed-form expansion: [silu(x), B0..B6], uniform cubic B-spline, knots -2.5..2.5 step 0.5
__device__ __forceinline__ void expand8(float x, float* e) {
    e[0] = x / (1.0f + __expf(-x));
    float u  = (x + 2.5f) * 2.0f;
    float fj = floorf(u);
    int   ji = (int)fj;
    float t  = u - fj;
    float t2 = t * t, t3 = t2 * t;
    float v3 = t3 * (1.0f / 6.0f);
    float v2 = (1.0f / 6.0f) * (-3.0f * t3 + 3.0f * t2 + 3.0f * t + 1.0f);
    float v1 = (1.0f / 6.0f) * (3.0f * t3 - 6.0f * t2 + 4.0f);
    float omt = 1.0f - t;
    float v0 = (1.0f / 6.0f) * omt * omt * omt;
    if (!(u >= 0.0f && u < 10.0f)) { v0 = v1 = v2 = v3 = 0.0f; }
#pragma unroll
    for (int m = 0; m < 7; ++m) {
        int d = ji - m;
        float r = 0.0f;
        r = (d == 3) ? v0 : r;
        r = (d == 2) ? v1 : r;
        r = (d == 1) ? v2 : r;
        r = (d == 0) ? v3 : r;
        e[1 + m] = r;
    }
}
__device__ __forceinline__ uint32_t pack_h16x2(float a, float b) {
    __half2 t = __floats2half2_rn(a, b);
    return *(uint32_t*)&t;
}

// ---------------- fused setup ----------------
__global__ void k_prep(const float* __restrict__ bw0, const float* __restrict__ sw0, const float* __restrict__ ss0,
                       const float* __restrict__ bw1, const float* __restrict__ sw1, const float* __restrict__ ss1,
                       const float* __restrict__ bw2, const float* __restrict__ sw2, const float* __restrict__ ss2,
                       const float* __restrict__ bwr, const float* __restrict__ swr, const float* __restrict__ ssr) {
    int t = blockIdx.x * 256 + threadIdx.x;
    if (t < N_NODES)   g_degi[t] = 0;
    if (t < NG * FEAT) g_pool[t] = 0.0f;
    if (t < NG)        g_cnt[t]  = 0.0f;

    const int NW = FEAT * FEAT;
    if (t < 3 * NW + CLS * FEAT) {
        int which = t / NW;
        int i = t - which * NW;
        const float *bw, *sw, *ss;
        if      (which == 0) { bw = bw0; sw = sw0; ss = ss0; }
        else if (which == 1) { bw = bw1; sw = sw1; ss = ss1; }
        else if (which == 2) { bw = bw2; sw = sw2; ss = ss2; }
        else                 { bw = bwr; sw = swr; ss = ssr; }
        float v[8];
        v[0] = bw[i];
        float s = ss[i];
#pragma unroll
        for (int k = 0; k < 7; ++k) v[1 + k] = sw[i * 7 + k] * s;
        if (which < 3) {
            __half* wh = &g_Wh[which][i * 8];
#pragma unroll
            for (int j = 0; j < 8; ++j) wh[j] = __float2half_rn(v[j]);
        } else {
            float* d = g_Wr + i * 8;
#pragma unroll
            for (int j = 0; j < 8; ++j) d[j] = v[j];
        }
    }
}
__global__ void k_hist(const int* __restrict__ dst) {
    int e = blockIdx.x * 256 + threadIdx.x;
    if (e < N_EDGES) atomicAdd(&g_degi[dst[e]], 1);
}
__global__ void k_scan1() {
    __shared__ int s[256];
    int i = blockIdx.x * 256 + threadIdx.x;
    int v = (i < N_NODES) ? g_degi[i] : 0;
    if (i < N_NODES) g_dinv[i] = rsqrtf((float)v + 1.0f);
    s[threadIdx.x] = v;
    __syncthreads();
    for (int o = 1; o < 256; o <<= 1) {
        int t = (threadIdx.x >= o) ? s[threadIdx.x - o] : 0;
        __syncthreads();
        s[threadIdx.x] += t;
        __syncthreads();
    }
    if (i < N_NODES) g_rowptr[i] = s[threadIdx.x] - v;   // exclusive within block
    if (threadIdx.x == 255) g_blocksum[blockIdx.x] = s[255];   // block total
}
// scan3 with inlined cross-block prefix: each block reduces blocksum[0..bid-1]
__global__ void k_scan3() {
    __shared__ int sred[256];
    int partial = 0;
    for (int j = threadIdx.x; j < (int)blockIdx.x; j += 256) partial += g_blocksum[j];
    sred[threadIdx.x] = partial;
    __syncthreads();
    for (int o = 128; o > 0; o >>= 1) {
        if (threadIdx.x < o) sred[threadIdx.x] += sred[threadIdx.x + o];
        __syncthreads();
    }
    int base = sred[0];
    int i = blockIdx.x * 256 + threadIdx.x;
    if (i < N_NODES) {
        int r = g_rowptr[i] + base;
        g_rowptr[i] = r;
        g_wofs[i]   = r;
    }
    if (i == 0) g_rowptr[N_NODES] = N_EDGES;
}
__global__ void k_fill(const int* __restrict__ ei) {
    int e = blockIdx.x * 256 + threadIdx.x;
    if (e >= N_EDGES) return;
    int d = ei[N_EDGES + e];
    int pos = atomicAdd(&g_wofs[d], 1);
    g_srcs[pos] = ei[e];
}

// ---------------- pipelined HMMA fused KAN-linear GEMM (fp16, M-tile 64, K-chunk 64) ----------------
// A fp16 8KB/stage, B fp16 16KB/stage; 3 stages each -> 72KB, 3 CTAs/SM.
// 128B rows, 8x16B units, XOR swizzle (row&7); one sync/chunk (mod-3 safe), 16 chunks.
// 8 warps as 2 (M) x 4 (N): warp tile M32 x N32. Epilogue stores Y' = Y*dinv (fp16).
#define TM 64
#define A_STAGE 8192
#define B_STAGE 16384
#define OFF_B   (3 * A_STAGE)
#define SMEM_NEED (OFF_B + 3 * B_STAGE)   // 73728

__global__ __launch_bounds__(256, 3) void k_gemm_mma(const float* __restrict__ x, int layer) {
    extern __shared__ __align__(16) char sm[];
    uint32_t sb = smem_u32(sm);

    const float* Hin = (layer == 0) ? x : g_H;
    const __half* Wh = g_Wh[layer];

    const int tid = threadIdx.x, lane = tid & 31, wid = tid >> 5;
    const int row0 = blockIdx.x * TM;
    const int m0w = (wid >> 2) * 32;     // 0 or 32
    const int n0w = (wid & 3) * 32;      // 0,32,64,96

    // H coords: per chunk 512 items (64 rows x 8 dims); thread does q<2: id=q*256+tid
    int hrow[2];
    const int hdd = tid & 7;
#pragma unroll
    for (int q = 0; q < 2; ++q) hrow[q] = q * 32 + (tid >> 3);
    bool hok[2];
#pragma unroll
    for (int q = 0; q < 2; ++q) hok[q] = (row0 + hrow[q]) < N_NODES;

    float hv[2][2];
#pragma unroll
    for (int q = 0; q < 2; ++q)
        hv[0][q] = hok[q] ? Hin[(row0 + hrow[q]) * FEAT + hdd] : 0.0f;
#pragma unroll
    for (int q = 0; q < 2; ++q)
        hv[1][q] = hok[q] ? Hin[(row0 + hrow[q]) * FEAT + 8 + hdd] : 0.0f;

    // prefetch B(0) into stage 0: 1024 units of 16B
    {
#pragma unroll
        for (int q = 0; q < 4; ++q) {
            int idx = q * 256 + tid;
            int o = idx >> 3, s = idx & 7;
            uint32_t off = (uint32_t)o * 128 + (uint32_t)((s ^ (o & 7)) * 16);
            cp_async16(sb + OFF_B + off, Wh + o * KDIM + s * 8);
        }
        CP_COMMIT();
    }

    // produce A(0) into stage 0
    {
        char* bufA = sm;
#pragma unroll
        for (int q = 0; q < 2; ++q) {
            int n = hrow[q], dd = hdd;
            float e[8];
            expand8(hv[0][q], e);
            uint32_t h[4];
#pragma unroll
            for (int j = 0; j < 4; ++j) h[j] = pack_h16x2(e[2 * j], e[2 * j + 1]);
            uint32_t off = (uint32_t)n * 128 + (uint32_t)((dd ^ (n & 7)) * 16);
            *(uint4*)(bufA + off) = make_uint4(h[0], h[1], h[2], h[3]);
        }
    }

    float acc[2][4][4];
#pragma unroll
    for (int i = 0; i < 2; ++i)
#pragma unroll
        for (int j = 0; j < 4; ++j)
#pragma unroll
            for (int k = 0; k < 4; ++k) acc[i][j][k] = 0.0f;

    int stage_next = 1;
    for (int c = 0; c < 16; ++c) {
        // prefetch B(c+1)
        if (c + 1 < 16) {
            uint32_t bst = sb + OFF_B + stage_next * B_STAGE;
#pragma unroll
            for (int q = 0; q < 4; ++q) {
                int idx = q * 256 + tid;
                int o = idx >> 3, s = idx & 7;
                uint32_t off = (uint32_t)o * 128 + (uint32_t)((s ^ (o & 7)) * 16);
                cp_async16(bst + off, Wh + o * KDIM + (c + 1) * 64 + s * 8);
            }
            CP_COMMIT();
        }
        // H loads for chunk c+2
        if (c + 2 < 16) {
#pragma unroll
            for (int q = 0; q < 2; ++q)
                hv[c & 1][q] = hok[q] ? Hin[(row0 + hrow[q]) * FEAT + (c + 2) * 8 + hdd] : 0.0f;
        }
        // produce A(c+1)
        if (c + 1 < 16) {
            char* bufA = sm + stage_next * A_STAGE;
            const float* hvc = hv[(c + 1) & 1];
#pragma unroll
            for (int q = 0; q < 2; ++q) {
                int n = hrow[q], dd = hdd;
                float e[8];
                expand8(hvc[q], e);
                uint32_t h[4];
#pragma unroll
                for (int j = 0; j < 4; ++j) h[j] = pack_h16x2(e[2 * j], e[2 * j + 1]);
                uint32_t off = (uint32_t)n * 128 + (uint32_t)((dd ^ (n & 7)) * 16);
                *(uint4*)(bufA + off) = make_uint4(h[0], h[1], h[2], h[3]);
            }
        }
        if (c == 15) { CP_WAIT0(); } else { CP_WAIT1(); }
        __syncthreads();

        // consume chunk c from stage c%3
        const int ast = (stage_next + 2) % 3;
        const uint32_t abase = sb + ast * A_STAGE;
        const uint32_t bbase = sb + OFF_B + ast * B_STAGE;
#pragma unroll
        for (int kk = 0; kk < 4; ++kk) {
            uint32_t ah[2][4];
#pragma unroll
            for (int mt = 0; mt < 2; ++mt) {
                int m = m0w + mt * 16 + (lane & 15);
                uint32_t u = (uint32_t)((kk * 2 + (lane >> 4)) ^ (m & 7));
                ldm_x4(ah[mt], abase + (uint32_t)m * 128 + u * 16);
            }
            uint32_t bh[2][4];
#pragma unroll
            for (int ng = 0; ng < 2; ++ng) {
                int n = n0w + ng * 16 + ((lane >> 4) << 3) + (lane & 7);
                uint32_t u = (uint32_t)((kk * 2 + ((lane >> 3) & 1)) ^ (n & 7));
                ldm_x4(bh[ng], bbase + (uint32_t)n * 128 + u * 16);
            }
#pragma unroll
            for (int mt = 0; mt < 2; ++mt)
#pragma unroll
                for (int ng = 0; ng < 2; ++ng)
#pragma unroll
                    for (int hf = 0; hf < 2; ++hf)
                        mma16816(acc[mt][ng * 2 + hf], ah[mt], bh[ng][hf * 2], bh[ng][hf * 2 + 1]);
        }
        stage_next = (stage_next + 1) % 3;
    }

    // epilogue: write Y' = Y * dinv[row] as fp16
#pragma unroll
    for (int mt = 0; mt < 2; ++mt) {
        int r1 = row0 + m0w + mt * 16 + (lane >> 2);
        int r2 = r1 + 8;
        bool ok1 = r1 < N_NODES, ok2 = r2 < N_NODES;
        float d1 = ok1 ? g_dinv[r1] : 0.0f;
        float d2 = ok2 ? g_dinv[r2] : 0.0f;
        int cb = n0w + (lane & 3) * 2;
#pragma unroll
        for (int nt = 0; nt < 4; ++nt) {
            int col = cb + nt * 8;
            float* a = acc[mt][nt];
            if (ok1) *(__half2*)&g_Yh[r1 * FEAT + col] = __floats2half2_rn(a[0] * d1, a[1] * d1);
            if (ok2) *(__half2*)&g_Yh[r2 * FEAT + col] = __floats2half2_rn(a[2] * d2, a[3] * d2);
        }
    }
}

// ---------------- fused CSR aggregation + bias + silu (+ optional pooling) ----------------
// Y' already carries dinv[src]; z = dd * (Y'[w] + sum_s Y'[s]).
__device__ __forceinline__ float4 ld_y4(int node, int lane) {
    uint2 u = *(const uint2*)&g_Yh[node * FEAT + lane * 4];
    float2 p0 = __half22float2(*(__half2*)&u.x);
    float2 p1 = __half22float2(*(__half2*)&u.y);
    return make_float4(p0.x, p0.y, p1.x, p1.y);
}
__device__ __forceinline__ void acc4(float4& a, const float4 v) {
    a.x += v.x; a.y += v.y; a.z += v.z; a.w += v.w;
}

__global__ __launch_bounds__(256) void k_aggr(const float* __restrict__ bias,
                                              const int* __restrict__ batch) {
    int w = (blockIdx.x * 256 + threadIdx.x) >> 5;
    int lane = threadIdx.x & 31;
    if (w >= N_NODES) return;
    float dd = g_dinv[w];
    float4 a = ld_y4(w, lane);   // self term Y'[w]

    int e = g_rowptr[w], end = g_rowptr[w + 1];
    for (; e + 8 <= end; e += 8) {
        int s0 = g_srcs[e],     s1 = g_srcs[e + 1];
        int s2 = g_srcs[e + 2], s3 = g_srcs[e + 3];
        int s4 = g_srcs[e + 4], s5 = g_srcs[e + 5];
        int s6 = g_srcs[e + 6], s7 = g_srcs[e + 7];
        float4 v0 = ld_y4(s0, lane), v1 = ld_y4(s1, lane);
        float4 v2 = ld_y4(s2, lane), v3 = ld_y4(s3, lane);
        float4 v4 = ld_y4(s4, lane), v5 = ld_y4(s5, lane);
        float4 v6 = ld_y4(s6, lane), v7 = ld_y4(s7, lane);
        acc4(a, v0); acc4(a, v1); acc4(a, v2); acc4(a, v3);
        acc4(a, v4); acc4(a, v5); acc4(a, v6); acc4(a, v7);
    }
    for (; e + 2 <= end; e += 2) {
        int s0 = g_srcs[e], s1 = g_srcs[e + 1];
        float4 v0 = ld_y4(s0, lane), v1 = ld_y4(s1, lane);
        acc4(a, v0); acc4(a, v1);
    }
    if (e < end) {
        float4 v0 = ld_y4(g_srcs[e], lane);
        acc4(a, v0);
    }
    float4 bv = *(const float4*)&bias[lane * 4];
    a.x = a.x * dd + bv.x;
    a.y = a.y * dd + bv.y;
    a.z = a.z * dd + bv.z;
    a.w = a.w * dd + bv.w;
    a.x = a.x / (1.0f + __expf(-a.x));
    a.y = a.y / (1.0f + __expf(-a.y));
    a.z = a.z / (1.0f + __expf(-a.z));
    a.w = a.w / (1.0f + __expf(-a.w));
    if (batch == nullptr) {
        *(float4*)&g_H[w * FEAT + lane * 4] = a;
    } else {
        int g = batch[w];
        red_add_v4(&g_pool[g * FEAT + lane * 4], a);
        if (lane == 0) atomicAdd(&g_cnt[g], 1.0f);
    }
}

// ---------------- readout ----------------
__global__ void k_readout(float* __restrict__ out) {
    int g = blockIdx.x;
    int t = threadIdx.x;   // 128
    __shared__ float red[CLS][4];
    __shared__ float logits[CLS];

    float inv = 1.0f / fmaxf(g_cnt[g], 1.0f);
    float p = g_pool[g * FEAT + t] * inv;
    float e[8];
    expand8(p, e);

    float part[CLS];
#pragma unroll
    for (int c = 0; c < CLS; ++c) {
        const float* w = &g_Wr[c * KDIM + t * 8];
        float s = 0.0f;
#pragma unroll
        for (int j = 0; j < 8; ++j) s = fmaf(e[j], w[j], s);
        part[c] = s;
    }
    int lane = t & 31, wid = t >> 5;
#pragma unroll
    for (int c = 0; c < CLS; ++c) {
        float v = part[c];
#pragma unroll
        for (int o = 16; o > 0; o >>= 1) v += __shfl_down_sync(0xffffffffu, v, o);
        if (lane == 0) red[c][wid] = v;
    }
    __syncthreads();
    if (t < CLS) logits[t] = red[t][0] + red[t][1] + red[t][2] + red[t][3];
    __syncthreads();
    if (t == 0) {
        float m = -1e30f;
        for (int c = 0; c < CLS; ++c) m = fmaxf(m, logits[c]);
        float s = 0.0f;
        for (int c = 0; c < CLS; ++c) s += expf(logits[c] - m);
        float lse = m + logf(s);
        for (int c = 0; c < CLS; ++c) out[g * CLS + c] = logits[c] - lse;
    }
}

// ---------------- launch ----------------
extern "C" void kernel_launch(void* const* d_in, const int* in_sizes, int n_in,
                              void* d_out, int out_size) {
    const float* x     = (const float*)d_in[0];
    const int*   ei    = (const int*)d_in[1];
    const int*   batch = (const int*)d_in[2];
    float* out = (float*)d_out;

    cudaFuncSetAttribute(k_gemm_mma, cudaFuncAttributeMaxDynamicSharedMemorySize, SMEM_NEED);

    const int nscan = (N_NODES + 255) / 256;   // 196
    const int nprep = (3 * FEAT * FEAT + CLS * FEAT + 255) / 256;  // 198
    k_prep<<<(nprep > nscan ? nprep : nscan), 256>>>(
        (const float*)d_in[3],  (const float*)d_in[4],  (const float*)d_in[5],
        (const float*)d_in[7],  (const float*)d_in[8],  (const float*)d_in[9],
        (const float*)d_in[11], (const float*)d_in[12], (const float*)d_in[13],
        (const float*)d_in[15], (const float*)d_in[16], (const float*)d_in[17]);
    k_hist<<<(N_EDGES + 255) / 256, 256>>>(ei + N_EDGES);
    k_scan1<<<nscan, 256>>>();
    k_scan3<<<nscan, 256>>>();
    k_fill<<<(N_EDGES + 255) / 256, 256>>>(ei);

    const float* bb[3] = {(const float*)d_in[6], (const float*)d_in[10], (const float*)d_in[14]};
    int gemm_blocks = (N_NODES + TM - 1) / TM;   // 782
    int aggr_blocks = (N_NODES * 32 + 255) / 256;
    for (int l = 0; l < 3; ++l) {
        k_gemm_mma<<<gemm_blocks, 256, SMEM_NEED>>>(x, l);
        k_aggr<<<aggr_blocks, 256>>>(bb[l], (l == 2) ? batch : nullptr);
    }

    k_readout<<<NG, 128>>>(out);
}